// round 2
// baseline (speedup 1.0000x reference)
#include <cuda_runtime.h>
#include <math_constants.h>
#include <float.h>

// Problem constants
#define BB 1024
#define DD 8192
#define CC 345
#define FF 512
#define PROTO_W_F 0.99f

// Output layout (flattened, return-tuple order, float32):
//   logits_q   [1024,345] @ 0
//   logits_q1  [1024,345] @ 353280
//   new_proto  [345,512]  @ 706560
//   prot_scores[345,345]  @ 883200
//   labels     [1024]     @ 1002225 (as float)
//   feats_q    [1024,512] @ 1003249
//   feats_q1   [1024,512] @ 1527537
#define OFF_LOGITS_Q   0
#define OFF_LOGITS_Q1  353280
#define OFF_NEW_PROTO  706560
#define OFF_PROT       883200
#define OFF_LABELS     1002225
#define OFF_FEATS_Q    1003249
#define OFF_FEATS_Q1   1527537

__device__ int g_labels[BB];

// ---------------------------------------------------------------------------
// Generic fp32 tiled GEMM: C = A[M,K] * B[K,N] (+ bias), optional 2-batch via
// blockIdx.z selecting (A0,C0)/(A1,C1). K must be a multiple of 16.
// BM=BN=64, BK=16, 256 threads, 4x4 micro-tile. All global loads scalar
// (A/C base pointers may be 4-byte aligned only).
// ---------------------------------------------------------------------------
__global__ __launch_bounds__(256)
void gemm64(const float* __restrict__ A0, const float* __restrict__ A1,
            const float* __restrict__ Bmat, const float* __restrict__ bias,
            float* __restrict__ C0, float* __restrict__ C1,
            int M, int N, int K)
{
    const float* __restrict__ A = blockIdx.z ? A1 : A0;
    float* __restrict__ C = blockIdx.z ? C1 : C0;

    __shared__ float As[16][64 + 1];
    __shared__ float Bs[16][64];

    const int tid = threadIdx.x;
    const int tx = tid & 15;        // N direction (4 cols each)
    const int ty = tid >> 4;        // M direction (4 rows each)
    const int bm = blockIdx.y * 64;
    const int bn = blockIdx.x * 64;

    float acc[4][4] = {};

    for (int k0 = 0; k0 < K; k0 += 16) {
        // Load A tile 64x16 -> As[col][row]. Lane pattern: row=(tid>>4)+16j, col=tid&15
        {
            const int acol = tid & 15;
            const int arow0 = tid >> 4;
#pragma unroll
            for (int j = 0; j < 4; ++j) {
                const int arow = arow0 + j * 16;
                const int gr = bm + arow;
                float v = 0.0f;
                if (gr < M) v = A[(size_t)gr * K + (k0 + acol)];
                As[acol][arow] = v;
            }
        }
        // Load B tile 16x64 -> Bs[row][col]. Lane pattern: row=tid>>4, col=(tid&15)+16j
        {
            const int brow = tid >> 4;
            const int bcol0 = tid & 15;
#pragma unroll
            for (int j = 0; j < 4; ++j) {
                const int bcol = bcol0 + j * 16;
                const int gc = bn + bcol;
                float v = 0.0f;
                if (gc < N) v = Bmat[(size_t)(k0 + brow) * N + gc];
                Bs[brow][bcol] = v;
            }
        }
        __syncthreads();

#pragma unroll
        for (int kk = 0; kk < 16; ++kk) {
            float a[4], b[4];
#pragma unroll
            for (int i = 0; i < 4; ++i) a[i] = As[kk][ty * 4 + i];
#pragma unroll
            for (int j = 0; j < 4; ++j) b[j] = Bs[kk][tx * 4 + j];
#pragma unroll
            for (int i = 0; i < 4; ++i)
#pragma unroll
                for (int j = 0; j < 4; ++j)
                    acc[i][j] = fmaf(a[i], b[j], acc[i][j]);
        }
        __syncthreads();
    }

#pragma unroll
    for (int i = 0; i < 4; ++i) {
        const int r = bm + ty * 4 + i;
        if (r >= M) continue;
#pragma unroll
        for (int j = 0; j < 4; ++j) {
            const int cidx = bn + tx * 4 + j;
            if (cidx < N) {
                float v = acc[i][j];
                if (bias) v += bias[cidx];
                C[(size_t)r * N + cidx] = v;
            }
        }
    }
}

// ---------------------------------------------------------------------------
// Masked argmax: labels[i] = argmax_{c: Y[i,c]>0} logits[i,c] (first index on
// ties, matching jnp.argmax over softmax(logits)*Y since softmax is monotone
// and the per-row normalizer is positive).
// One warp per row; 8 warps per block.
// ---------------------------------------------------------------------------
__global__ void argmax_kernel(const float* __restrict__ logits,
                              const float* __restrict__ Y,
                              float* __restrict__ labels_f)
{
    const int row = blockIdx.x * 8 + threadIdx.y;
    const int lane = threadIdx.x;
    if (row >= BB) return;

    float best = -FLT_MAX;
    int bidx = 0x7fffffff;
    for (int c = lane; c < CC; c += 32) {
        if (Y[(size_t)row * CC + c] != 0.0f) {
            const float v = logits[(size_t)row * CC + c];
            if (v > best || (v == best && c < bidx)) { best = v; bidx = c; }
        }
    }
#pragma unroll
    for (int o = 16; o > 0; o >>= 1) {
        const float ov = __shfl_down_sync(0xffffffffu, best, o);
        const int   oi = __shfl_down_sync(0xffffffffu, bidx, o);
        if (ov > best || (ov == best && oi < bidx)) { best = ov; bidx = oi; }
    }
    if (lane == 0) {
        g_labels[row] = bidx;
        labels_f[row] = (float)bidx;
    }
}

// ---------------------------------------------------------------------------
// Prototype EMA closed form, one block (512 threads) per class:
//   n = #occurrences of class c in order i_0..i_{n-1}
//   v = w^n * proto[c] + sum_k (1-w) w^{n-1-k} feats[i_k]
//   new_proto[c] = v / ||v||
// ---------------------------------------------------------------------------
__global__ __launch_bounds__(512)
void proto_kernel(const float* __restrict__ feats,
                  const float* __restrict__ proto,
                  float* __restrict__ new_proto)
{
    const int c = blockIdx.x;
    __shared__ int   s_lab[BB];
    __shared__ int   s_idx[BB];
    __shared__ float s_coef[BB];
    __shared__ float s_red[512];
    __shared__ float s_scale;
    __shared__ int   s_n;
    __shared__ float s_norm;

    const int tid = threadIdx.x;
    for (int i = tid; i < BB; i += 512) s_lab[i] = g_labels[i];
    __syncthreads();

    if (tid == 0) {
        int n = 0;
        for (int i = 0; i < BB; ++i)
            if (s_lab[i] == c) s_idx[n++] = i;
        s_n = n;
        for (int k = 0; k < n; ++k)
            s_coef[k] = (1.0f - PROTO_W_F) * powf(PROTO_W_F, (float)(n - 1 - k));
        s_scale = powf(PROTO_W_F, (float)n);
    }
    __syncthreads();

    const int n = s_n;
    const int f = tid;   // 512 threads == FF
    float acc = s_scale * proto[(size_t)c * FF + f];
    for (int k = 0; k < n; ++k)
        acc = fmaf(s_coef[k], feats[(size_t)s_idx[k] * FF + f], acc);

    s_red[tid] = acc * acc;
    __syncthreads();
#pragma unroll
    for (int s = 256; s > 0; s >>= 1) {
        if (tid < s) s_red[tid] += s_red[tid + s];
        __syncthreads();
    }
    if (tid == 0) s_norm = sqrtf(s_red[0]);
    __syncthreads();

    new_proto[(size_t)c * FF + f] = acc / s_norm;
}

// ---------------------------------------------------------------------------
extern "C" void kernel_launch(void* const* d_in, const int* in_sizes, int n_in,
                              void* d_out, int out_size)
{
    const float* img_q     = (const float*)d_in[0];
    const float* img_q1    = (const float*)d_in[1];
    const float* partial_Y = (const float*)d_in[2];
    const float* W_enc     = (const float*)d_in[3];
    const float* W_fc      = (const float*)d_in[4];
    const float* b_fc      = (const float*)d_in[5];
    const float* proto     = (const float*)d_in[6];

    float* out = (float*)d_out;
    float* o_logits_q  = out + OFF_LOGITS_Q;
    float* o_logits_q1 = out + OFF_LOGITS_Q1;
    float* o_new_proto = out + OFF_NEW_PROTO;
    float* o_prot      = out + OFF_PROT;
    float* o_labels    = out + OFF_LABELS;
    float* o_feats_q   = out + OFF_FEATS_Q;
    float* o_feats_q1  = out + OFF_FEATS_Q1;

    // 1) feats_{q,q1} = img @ W_enc : M=1024, N=512, K=8192, batched in z
    {
        dim3 grid(FF / 64, BB / 64, 2);   // 8 x 16 x 2
        gemm64<<<grid, 256>>>(img_q, img_q1, W_enc, nullptr,
                              o_feats_q, o_feats_q1, BB, FF, DD);
    }
    // 2) logits_{q,q1} = feats @ W_fc + b : M=1024, N=345, K=512, batched in z
    {
        dim3 grid((CC + 63) / 64, BB / 64, 2);   // 6 x 16 x 2
        gemm64<<<grid, 256>>>(o_feats_q, o_feats_q1, W_fc, b_fc,
                              o_logits_q, o_logits_q1, BB, CC, FF);
    }
    // 3) labels = masked argmax over logits_q
    {
        dim3 blk(32, 8);
        argmax_kernel<<<BB / 8, blk>>>(o_logits_q, partial_Y, o_labels);
    }
    // 4) prototype EMA + normalize
    proto_kernel<<<CC, 512>>>(o_feats_q, proto, o_new_proto);

    // 5) prot_scores = new_proto @ W_fc + b : M=345, N=345, K=512
    {
        dim3 grid((CC + 63) / 64, (CC + 63) / 64, 1);   // 6 x 6
        gemm64<<<grid, 256>>>(o_new_proto, o_new_proto, W_fc, b_fc,
                              o_prot, o_prot, CC, CC, FF);
    }
}

// round 6
// speedup vs baseline: 2.3871x; 2.3871x over previous
#include <cuda_runtime.h>
#include <cuda_fp16.h>
#include <cstdint>
#include <float.h>

// Problem constants
#define BB 1024
#define DD 8192
#define CC 345
#define FF 512
#define PROTO_W_F 0.99f

// Output layout (flattened, return-tuple order, float32)
#define OFF_LOGITS_Q   0
#define OFF_LOGITS_Q1  353280
#define OFF_NEW_PROTO  706560
#define OFF_PROT       883200
#define OFF_LABELS     1002225
#define OFF_FEATS_Q    1003249
#define OFF_FEATS_Q1   1527537
// NOTE: OFF_FEATS_Q / OFF_FEATS_Q1 are ODD element offsets -> those output
// pointers are only 4-byte aligned. All accesses to them MUST be scalar.

// ---------------------------------------------------------------------------
// Device scratch (static: allocation-free per harness rules)
// ---------------------------------------------------------------------------
__device__ __half gAh[2][BB * DD];   // f16 hi planes of img_q / img_q1 [row][k]
__device__ __half gAl[2][BB * DD];   // f16 lo planes
__device__ __half gBh[FF * DD];      // f16 hi plane of W_enc^T  [n][k]
__device__ __half gBl[FF * DD];      // f16 lo plane

__device__ int   g_labels[BB];
__device__ int   g_idx[BB];          // sample ids grouped by class, occurrence order
__device__ float g_coefs[BB];        // matching EMA coefficients
__device__ float g_scale[CC];        // w^count per class
__device__ int   g_start[CC];
__device__ int   g_n[CC];

// ---------------------------------------------------------------------------
// PTX helpers (plain sm_103-compatible: cp.async + ldmatrix + mma.sync)
// ---------------------------------------------------------------------------
__device__ __forceinline__ uint32_t smem_to_u32(const void* p) {
    uint32_t a;
    asm("{ .reg .u64 t; cvta.to.shared.u64 t, %1; cvt.u32.u64 %0, t; }" : "=r"(a) : "l"(p));
    return a;
}
#define CP_ASYNC16(dst, src) \
    asm volatile("cp.async.cg.shared.global [%0], [%1], 16;" :: "r"(dst), "l"(src) : "memory")
#define CP_COMMIT()  asm volatile("cp.async.commit_group;" ::: "memory")
#define CP_WAIT1()   asm volatile("cp.async.wait_group 1;" ::: "memory")
#define CP_WAIT0()   asm volatile("cp.async.wait_group 0;" ::: "memory")
#define LDSM_X4(r0, r1, r2, r3, addr) \
    asm volatile("ldmatrix.sync.aligned.m8n8.x4.shared.b16 {%0,%1,%2,%3}, [%4];" \
                 : "=r"(r0), "=r"(r1), "=r"(r2), "=r"(r3) : "r"(addr))
#define MMA16816(d, a, b) \
    asm volatile("mma.sync.aligned.m16n8k16.row.col.f32.f16.f16.f32 " \
                 "{%0,%1,%2,%3}, {%4,%5,%6,%7}, {%8,%9}, {%0,%1,%2,%3};" \
                 : "+f"((d)[0]), "+f"((d)[1]), "+f"((d)[2]), "+f"((d)[3]) \
                 : "r"((a)[0]), "r"((a)[1]), "r"((a)[2]), "r"((a)[3]), \
                   "r"((b)[0]), "r"((b)[1]))

// ---------------------------------------------------------------------------
// Fused transpose+split: W_enc [DD x FF] fp32 -> gBh/gBl [FF x DD] f16 planes
// ---------------------------------------------------------------------------
__global__ void splitW(const float* __restrict__ W) {
    __shared__ float t[32][33];
    const int n0 = blockIdx.x * 32, k0 = blockIdx.y * 32;
    const int tx = threadIdx.x, ty = threadIdx.y;
#pragma unroll
    for (int j = 0; j < 4; ++j)
        t[ty + 8 * j][tx] = W[(size_t)(k0 + ty + 8 * j) * FF + n0 + tx];
    __syncthreads();
#pragma unroll
    for (int j = 0; j < 4; ++j) {
        const float v = t[tx][ty + 8 * j];     // = W[k0+tx][n0+ty+8j]
        const int n = n0 + ty + 8 * j, k = k0 + tx;
        const __half h = __float2half_rn(v);
        gBh[(size_t)n * DD + k] = h;
        gBl[(size_t)n * DD + k] = __float2half_rn(v - __half2float(h));
    }
}

// ---------------------------------------------------------------------------
// fp32 -> (f16 hi, f16 lo) planes, vectorized (src/dst are 16B-aligned bufs)
// ---------------------------------------------------------------------------
__global__ __launch_bounds__(256)
void splitA(const float4* __restrict__ src, uint2* __restrict__ hi,
            uint2* __restrict__ lo, int nF4) {
    const int i = blockIdx.x * 256 + threadIdx.x;
    if (i >= nF4) return;
    float4 v = src[i];
    __half2 h01 = __floats2half2_rn(v.x, v.y);
    __half2 h23 = __floats2half2_rn(v.z, v.w);
    float2 f01 = __half22float2(h01);
    float2 f23 = __half22float2(h23);
    __half2 l01 = __floats2half2_rn(v.x - f01.x, v.y - f01.y);
    __half2 l23 = __floats2half2_rn(v.z - f23.x, v.w - f23.y);
    uint2 hw, lw;
    hw.x = *reinterpret_cast<uint32_t*>(&h01); hw.y = *reinterpret_cast<uint32_t*>(&h23);
    lw.x = *reinterpret_cast<uint32_t*>(&l01); lw.y = *reinterpret_cast<uint32_t*>(&l23);
    hi[i] = hw; lo[i] = lw;
}

// ---------------------------------------------------------------------------
// Split-FP16 HMMA GEMM:  C[b] = img[b] @ W_enc  (M=1024, N=512, K=8192)
// BM=128, BN=64, BK=32, 256 threads (8 warps as 4m x 2n, warp tile 32x32).
// Smem rows padded to 40 halfs (80 B) -> ldmatrix conflict-free.
// grid = (512/64, 1024/128, 2) = (8, 8, 2).
// Epilogue: SCALAR stores only (C base pointers are 4-byte aligned!).
// ---------------------------------------------------------------------------
#define SA_STRIDE 40                       // halfs per smem row (32 data + 8 pad)
#define STG_A1 0                           // byte offsets within a stage
#define STG_A2 10240
#define STG_B1 20480
#define STG_B2 25600
#define STAGE_BYTES 30720
#define GEMM_SMEM (2 * STAGE_BYTES)        // 61440

__global__ __launch_bounds__(256)
void gemm_mma(float* __restrict__ C0, float* __restrict__ C1) {
    extern __shared__ __align__(16) char smem[];
    const uint32_t sbase = smem_to_u32(smem);
    const int tid = threadIdx.x;
    const int lane = tid & 31, wid = tid >> 5;
    const int warp_m = wid >> 1, warp_n = wid & 1;
    const int bz = blockIdx.z;
    const int bm = blockIdx.y * 128, bn = blockIdx.x * 64;
    float* __restrict__ C = bz ? C1 : C0;

    const uint4* __restrict__ Ah = reinterpret_cast<const uint4*>(gAh[bz]);
    const uint4* __restrict__ Al = reinterpret_cast<const uint4*>(gAl[bz]);
    const uint4* __restrict__ Bh = reinterpret_cast<const uint4*>(gBh);
    const uint4* __restrict__ Bl = reinterpret_cast<const uint4*>(gBl);

    float acc[2][4][4] = {};

    // -- stage loader (cp.async, one commit group per stage) --
    const int la_row0 = tid >> 2;          // A rows (x2 via u)
    const int la_c4 = tid & 3;
    const int lb_row = tid >> 2;           // B rows
    const int lb_c4 = tid & 3;

#define LOAD_STAGE(it_)                                                            \
    do {                                                                           \
        const int s_ = (it_) & 1;                                                  \
        const int kc8_ = (it_) * 4;                                                \
        const uint32_t sb_ = sbase + s_ * STAGE_BYTES;                             \
        _Pragma("unroll")                                                          \
        for (int u = 0; u < 2; ++u) {                                              \
            const int row = la_row0 + u * 64;                                      \
            const uint32_t doff = (uint32_t)(row * SA_STRIDE + la_c4 * 8) * 2;     \
            const size_t gi = (size_t)(bm + row) * (DD / 8) + kc8_ + la_c4;        \
            CP_ASYNC16(sb_ + STG_A1 + doff, Ah + gi);                              \
            CP_ASYNC16(sb_ + STG_A2 + doff, Al + gi);                              \
        }                                                                          \
        {                                                                          \
            const uint32_t doff = (uint32_t)(lb_row * SA_STRIDE + lb_c4 * 8) * 2;  \
            const size_t gi = (size_t)(bn + lb_row) * (DD / 8) + kc8_ + lb_c4;     \
            CP_ASYNC16(sb_ + STG_B1 + doff, Bh + gi);                              \
            CP_ASYNC16(sb_ + STG_B2 + doff, Bl + gi);                              \
        }                                                                          \
        CP_COMMIT();                                                               \
    } while (0)

    LOAD_STAGE(0);

    const int NKT = DD / 32;               // 256
#pragma unroll 1
    for (int it = 0; it < NKT; ++it) {
        if (it + 1 < NKT) { LOAD_STAGE(it + 1); CP_WAIT1(); }
        else             { CP_WAIT0(); }
        __syncthreads();

        const uint32_t sb = sbase + (it & 1) * STAGE_BYTES;
#pragma unroll
        for (int ks = 0; ks < 2; ++ks) {
            uint32_t a[2][2][4];           // [plane][mtile]
#pragma unroll
            for (int p = 0; p < 2; ++p)
#pragma unroll
                for (int mt = 0; mt < 2; ++mt) {
                    const int row = warp_m * 32 + mt * 16 + (lane & 15);
                    const int col = ks * 16 + (lane >> 4) * 8;
                    const uint32_t addr = sb + (p ? STG_A2 : STG_A1) +
                                          (uint32_t)(row * SA_STRIDE + col) * 2;
                    LDSM_X4(a[p][mt][0], a[p][mt][1], a[p][mt][2], a[p][mt][3], addr);
                }
            uint32_t b[2][4][2];           // [plane][ntile]
#pragma unroll
            for (int p = 0; p < 2; ++p)
#pragma unroll
                for (int np = 0; np < 2; ++np) {
                    const int r = lane & 7, sel = lane >> 3;
                    const int row = warp_n * 32 + np * 16 + (sel >> 1) * 8 + r;
                    const int col = ks * 16 + (sel & 1) * 8;
                    const uint32_t addr = sb + (p ? STG_B2 : STG_B1) +
                                          (uint32_t)(row * SA_STRIDE + col) * 2;
                    LDSM_X4(b[p][2 * np][0], b[p][2 * np][1],
                            b[p][2 * np + 1][0], b[p][2 * np + 1][1], addr);
                }
#pragma unroll
            for (int mt = 0; mt < 2; ++mt)
#pragma unroll
                for (int nt = 0; nt < 4; ++nt) {
                    MMA16816(acc[mt][nt], a[0][mt], b[0][nt]);   // A1*B1
                    MMA16816(acc[mt][nt], a[0][mt], b[1][nt]);   // A1*B2
                    MMA16816(acc[mt][nt], a[1][mt], b[0][nt]);   // A2*B1
                }
        }
        __syncthreads();
    }
#undef LOAD_STAGE

    // epilogue: SCALAR fp32 stores (C may be only 4-byte aligned)
#pragma unroll
    for (int mt = 0; mt < 2; ++mt) {
        const int r0 = bm + warp_m * 32 + mt * 16 + (lane >> 2);
#pragma unroll
        for (int nt = 0; nt < 4; ++nt) {
            const int gc = bn + warp_n * 32 + nt * 8 + (lane & 3) * 2;
            float* p0 = C + (size_t)r0 * FF + gc;
            float* p1 = C + (size_t)(r0 + 8) * FF + gc;
            p0[0] = acc[mt][nt][0];
            p0[1] = acc[mt][nt][1];
            p1[0] = acc[mt][nt][2];
            p1[1] = acc[mt][nt][3];
        }
    }
}

// ---------------------------------------------------------------------------
// fp32 tiled GEMM (small GEMMs: logits, prot_scores) — all scalar accesses
// ---------------------------------------------------------------------------
__global__ __launch_bounds__(256)
void gemm64(const float* __restrict__ A0, const float* __restrict__ A1,
            const float* __restrict__ Bmat, const float* __restrict__ bias,
            float* __restrict__ C0, float* __restrict__ C1,
            int M, int N, int K)
{
    const float* __restrict__ A = blockIdx.z ? A1 : A0;
    float* __restrict__ C = blockIdx.z ? C1 : C0;
    __shared__ float As[16][64 + 1];
    __shared__ float Bs[16][64];
    const int tid = threadIdx.x;
    const int tx = tid & 15, ty = tid >> 4;
    const int bm = blockIdx.y * 64, bn = blockIdx.x * 64;
    float acc[4][4] = {};
    for (int k0 = 0; k0 < K; k0 += 16) {
        {
            const int acol = tid & 15, arow0 = tid >> 4;
#pragma unroll
            for (int j = 0; j < 4; ++j) {
                const int arow = arow0 + j * 16, gr = bm + arow;
                As[acol][arow] = (gr < M) ? A[(size_t)gr * K + (k0 + acol)] : 0.0f;
            }
        }
        {
            const int brow = tid >> 4, bcol0 = tid & 15;
#pragma unroll
            for (int j = 0; j < 4; ++j) {
                const int bcol = bcol0 + j * 16, gc = bn + bcol;
                Bs[brow][bcol] = (gc < N) ? Bmat[(size_t)(k0 + brow) * N + gc] : 0.0f;
            }
        }
        __syncthreads();
#pragma unroll
        for (int kk = 0; kk < 16; ++kk) {
            float a[4], b[4];
#pragma unroll
            for (int i = 0; i < 4; ++i) a[i] = As[kk][ty * 4 + i];
#pragma unroll
            for (int j = 0; j < 4; ++j) b[j] = Bs[kk][tx * 4 + j];
#pragma unroll
            for (int i = 0; i < 4; ++i)
#pragma unroll
                for (int j = 0; j < 4; ++j) acc[i][j] = fmaf(a[i], b[j], acc[i][j]);
        }
        __syncthreads();
    }
#pragma unroll
    for (int i = 0; i < 4; ++i) {
        const int rr = bm + ty * 4 + i;
        if (rr >= M) continue;
#pragma unroll
        for (int j = 0; j < 4; ++j) {
            const int cidx = bn + tx * 4 + j;
            if (cidx < N) {
                float v = acc[i][j];
                if (bias) v += bias[cidx];
                C[(size_t)rr * N + cidx] = v;
            }
        }
    }
}

// ---------------------------------------------------------------------------
// Masked argmax -> labels (first index on ties)
// ---------------------------------------------------------------------------
__global__ void argmax_kernel(const float* __restrict__ logits,
                              const float* __restrict__ Y,
                              float* __restrict__ labels_f)
{
    const int row = blockIdx.x * 8 + threadIdx.y;
    const int lane = threadIdx.x;
    if (row >= BB) return;
    float best = -FLT_MAX; int bidx = 0x7fffffff;
    for (int c = lane; c < CC; c += 32) {
        if (Y[(size_t)row * CC + c] != 0.0f) {
            const float v = logits[(size_t)row * CC + c];
            if (v > best || (v == best && c < bidx)) { best = v; bidx = c; }
        }
    }
#pragma unroll
    for (int o = 16; o > 0; o >>= 1) {
        const float ov = __shfl_down_sync(0xffffffffu, best, o);
        const int   oi = __shfl_down_sync(0xffffffffu, bidx, o);
        if (ov > best || (ov == best && oi < bidx)) { best = ov; bidx = oi; }
    }
    if (lane == 0) { g_labels[row] = bidx; labels_f[row] = (float)bidx; }
}

// ---------------------------------------------------------------------------
// One-block prep: per-class counts, occurrence ordering, EMA coefficients
// ---------------------------------------------------------------------------
__global__ __launch_bounds__(1024)
void prep_kernel() {
    __shared__ int s_lab[BB];
    __shared__ int s_tot[CC];
    __shared__ int s_start[CC];
    const int tid = threadIdx.x;
    if (tid < CC) s_tot[tid] = 0;
    s_lab[tid] = g_labels[tid];
    __syncthreads();
    const int lab = s_lab[tid];
    int occ = 0;
    for (int j = 0; j < tid; ++j) occ += (s_lab[j] == lab);
    atomicAdd(&s_tot[lab], 1);
    __syncthreads();
    if (tid == 0) {
        int acc = 0;
        for (int c = 0; c < CC; ++c) { s_start[c] = acc; acc += s_tot[c]; }
    }
    __syncthreads();
    const int n = s_tot[lab];
    const float c_after = (float)(n - occ - 1);
    const int pos = s_start[lab] + occ;
    g_idx[pos]   = tid;
    g_coefs[pos] = (1.0f - PROTO_W_F) * __powf(PROTO_W_F, c_after);
    if (tid < CC) {
        g_scale[tid] = __powf(PROTO_W_F, (float)s_tot[tid]);
        g_start[tid] = s_start[tid];
        g_n[tid]     = s_tot[tid];
    }
}

// ---------------------------------------------------------------------------
// Prototype EMA + normalize (one block per class, 512 threads = FF)
// ---------------------------------------------------------------------------
__global__ __launch_bounds__(512)
void proto_kernel(const float* __restrict__ feats,
                  const float* __restrict__ proto,
                  float* __restrict__ new_proto)
{
    const int c = blockIdx.x;
    __shared__ float s_red[512];
    __shared__ float s_norm;
    const int tid = threadIdx.x;
    const int n = g_n[c], st = g_start[c];
    float acc = g_scale[c] * proto[(size_t)c * FF + tid];
    for (int k = 0; k < n; ++k)
        acc = fmaf(g_coefs[st + k], feats[(size_t)g_idx[st + k] * FF + tid], acc);
    s_red[tid] = acc * acc;
    __syncthreads();
#pragma unroll
    for (int s = 256; s > 0; s >>= 1) {
        if (tid < s) s_red[tid] += s_red[tid + s];
        __syncthreads();
    }
    if (tid == 0) s_norm = sqrtf(s_red[0]);
    __syncthreads();
    new_proto[(size_t)c * FF + tid] = acc / s_norm;
}

// ---------------------------------------------------------------------------
extern "C" void kernel_launch(void* const* d_in, const int* in_sizes, int n_in,
                              void* d_out, int out_size)
{
    const float* img_q     = (const float*)d_in[0];
    const float* img_q1    = (const float*)d_in[1];
    const float* partial_Y = (const float*)d_in[2];
    const float* W_enc     = (const float*)d_in[3];
    const float* W_fc      = (const float*)d_in[4];
    const float* b_fc      = (const float*)d_in[5];
    const float* proto     = (const float*)d_in[6];

    float* out = (float*)d_out;
    float* o_logits_q  = out + OFF_LOGITS_Q;
    float* o_logits_q1 = out + OFF_LOGITS_Q1;
    float* o_new_proto = out + OFF_NEW_PROTO;
    float* o_prot      = out + OFF_PROT;
    float* o_labels    = out + OFF_LABELS;
    float* o_feats_q   = out + OFF_FEATS_Q;
    float* o_feats_q1  = out + OFF_FEATS_Q1;

    cudaFuncSetAttribute(gemm_mma, cudaFuncAttributeMaxDynamicSharedMemorySize, GEMM_SMEM);

    // 0) split inputs into f16 hi/lo planes (W fused with transpose)
    {
        dim3 blk(32, 8);
        splitW<<<dim3(FF / 32, DD / 32), blk>>>(W_enc);
    }
    {
        void* pAh; void* pAl;
        cudaGetSymbolAddress(&pAh, gAh);
        cudaGetSymbolAddress(&pAl, gAl);
        const int nF4 = BB * DD / 4;
        splitA<<<(nF4 + 255) / 256, 256>>>((const float4*)img_q,
                                           (uint2*)pAh, (uint2*)pAl, nF4);
        splitA<<<(nF4 + 255) / 256, 256>>>((const float4*)img_q1,
                                           (uint2*)((__half*)pAh + (size_t)BB * DD),
                                           (uint2*)((__half*)pAl + (size_t)BB * DD), nF4);
    }

    // 1) feats = img @ W_enc via split-fp16 HMMA (both batches)
    {
        dim3 grid(FF / 64, BB / 128, 2);   // 8 x 8 x 2
        gemm_mma<<<grid, 256, GEMM_SMEM>>>(o_feats_q, o_feats_q1);
    }
    // 2) logits = feats @ W_fc + b (fp32, exact path for labels)
    {
        dim3 grid((CC + 63) / 64, BB / 64, 2);
        gemm64<<<grid, 256>>>(o_feats_q, o_feats_q1, W_fc, b_fc,
                              o_logits_q, o_logits_q1, BB, CC, FF);
    }
    // 3) masked argmax -> labels
    {
        dim3 blk(32, 8);
        argmax_kernel<<<BB / 8, blk>>>(o_logits_q, partial_Y, o_labels);
    }
    // 4) prep + prototype EMA + normalize
    prep_kernel<<<1, 1024>>>();
    proto_kernel<<<CC, 512>>>(o_feats_q, proto, o_new_proto);

    // 5) prot_scores = new_proto @ W_fc + b
    {
        dim3 grid((CC + 63) / 64, (CC + 63) / 64, 1);
        gemm64<<<grid, 256>>>(o_new_proto, o_new_proto, W_fc, b_fc,
                              o_prot, o_prot, CC, CC, FF);
    }
}

// round 10
// speedup vs baseline: 2.4766x; 1.0375x over previous
#include <cuda_runtime.h>
#include <cuda_fp16.h>
#include <cstdint>
#include <float.h>

// Problem constants
#define BB 1024
#define DD 8192
#define CC 345
#define FF 512
#define PROTO_W_F 0.99f

// Output layout (flattened, return-tuple order, float32)
#define OFF_LOGITS_Q   0
#define OFF_LOGITS_Q1  353280
#define OFF_NEW_PROTO  706560
#define OFF_PROT       883200
#define OFF_LABELS     1002225
#define OFF_FEATS_Q    1003249
#define OFF_FEATS_Q1   1527537
// NOTE: OFF_FEATS_Q / OFF_FEATS_Q1 are ODD element offsets -> those output
// pointers are only 4-byte aligned. All accesses to them MUST be scalar.

// ---------------------------------------------------------------------------
// Device scratch (static: allocation-free per harness rules)
// ---------------------------------------------------------------------------
__device__ __half gAh[2][BB * DD];   // f16 hi planes of img_q / img_q1 [row][k]
__device__ __half gAl[2][BB * DD];   // f16 lo planes
__device__ __half gBh[FF * DD];      // f16 hi plane of W_enc^T  [n][k]
__device__ __half gBl[FF * DD];      // f16 lo plane
__device__ float gPart[4][BB * FF];  // split-K partials: z = batch*2 + split

__device__ int   g_labels[BB];
__device__ int   g_idx[BB];          // sample ids grouped by class, occurrence order
__device__ float g_coefs[BB];        // matching EMA coefficients
__device__ float g_scale[CC];        // w^count per class
__device__ int   g_start[CC];
__device__ int   g_n[CC];

// ---------------------------------------------------------------------------
// PTX helpers (plain sm_103-compatible: cp.async + ldmatrix + mma.sync)
// ---------------------------------------------------------------------------
__device__ __forceinline__ uint32_t smem_to_u32(const void* p) {
    uint32_t a;
    asm("{ .reg .u64 t; cvta.to.shared.u64 t, %1; cvt.u32.u64 %0, t; }" : "=r"(a) : "l"(p));
    return a;
}
#define CP_ASYNC16(dst, src) \
    asm volatile("cp.async.cg.shared.global [%0], [%1], 16;" :: "r"(dst), "l"(src) : "memory")
#define CP_COMMIT()  asm volatile("cp.async.commit_group;" ::: "memory")
#define CP_WAIT2()   asm volatile("cp.async.wait_group 2;" ::: "memory")
#define CP_WAIT1()   asm volatile("cp.async.wait_group 1;" ::: "memory")
#define CP_WAIT0()   asm volatile("cp.async.wait_group 0;" ::: "memory")
#define LDSM_X4(r0, r1, r2, r3, addr) \
    asm volatile("ldmatrix.sync.aligned.m8n8.x4.shared.b16 {%0,%1,%2,%3}, [%4];" \
                 : "=r"(r0), "=r"(r1), "=r"(r2), "=r"(r3) : "r"(addr))
#define MMA16816(d, a, b) \
    asm volatile("mma.sync.aligned.m16n8k16.row.col.f32.f16.f16.f32 " \
                 "{%0,%1,%2,%3}, {%4,%5,%6,%7}, {%8,%9}, {%0,%1,%2,%3};" \
                 : "+f"((d)[0]), "+f"((d)[1]), "+f"((d)[2]), "+f"((d)[3]) \
                 : "r"((a)[0]), "r"((a)[1]), "r"((a)[2]), "r"((a)[3]), \
                   "r"((b)[0]), "r"((b)[1]))

// ---------------------------------------------------------------------------
// Fused transpose+split: W_enc [DD x FF] fp32 -> gBh/gBl [FF x DD] f16 planes
// ---------------------------------------------------------------------------
__global__ void splitW(const float* __restrict__ W) {
    __shared__ float t[32][33];
    const int n0 = blockIdx.x * 32, k0 = blockIdx.y * 32;
    const int tx = threadIdx.x, ty = threadIdx.y;
#pragma unroll
    for (int j = 0; j < 4; ++j)
        t[ty + 8 * j][tx] = W[(size_t)(k0 + ty + 8 * j) * FF + n0 + tx];
    __syncthreads();
#pragma unroll
    for (int j = 0; j < 4; ++j) {
        const float v = t[tx][ty + 8 * j];     // = W[k0+tx][n0+ty+8j]
        const int n = n0 + ty + 8 * j, k = k0 + tx;
        const __half h = __float2half_rn(v);
        gBh[(size_t)n * DD + k] = h;
        gBl[(size_t)n * DD + k] = __float2half_rn(v - __half2float(h));
    }
}

// ---------------------------------------------------------------------------
// fp32 -> (f16 hi, f16 lo) planes, vectorized (src/dst are 16B-aligned bufs)
// ---------------------------------------------------------------------------
__global__ __launch_bounds__(256)
void splitA(const float4* __restrict__ src, uint2* __restrict__ hi,
            uint2* __restrict__ lo, int nF4) {
    const int i = blockIdx.x * 256 + threadIdx.x;
    if (i >= nF4) return;
    float4 v = src[i];
    __half2 h01 = __floats2half2_rn(v.x, v.y);
    __half2 h23 = __floats2half2_rn(v.z, v.w);
    float2 f01 = __half22float2(h01);
    float2 f23 = __half22float2(h23);
    __half2 l01 = __floats2half2_rn(v.x - f01.x, v.y - f01.y);
    __half2 l23 = __floats2half2_rn(v.z - f23.x, v.w - f23.y);
    uint2 hw, lw;
    hw.x = *reinterpret_cast<uint32_t*>(&h01); hw.y = *reinterpret_cast<uint32_t*>(&h23);
    lw.x = *reinterpret_cast<uint32_t*>(&l01); lw.y = *reinterpret_cast<uint32_t*>(&l23);
    hi[i] = hw; lo[i] = lw;
}

// ---------------------------------------------------------------------------
// Split-FP16 HMMA GEMM with split-K:  partial[z] = img[bz][:, kspan] @ W_enc[kspan]
// BM=128, BN=64, BK=32, 256 threads (8 warps as 4m x 2n, warp tile 32x32).
// grid = (8, 8, 8): z = batch*2*? -> z encodes (batch, split): bz=z>>2? NO:
//   z in [0,8): batch = z >> 2 ... we use z = (batch << 1| split) * ... see launch:
//   gridDim.z = 4: z = batch*2 + split, each split covers K/2 = 4096.
// 3-stage cp.async pipeline. Output to aligned gPart (vector stores OK).
// ---------------------------------------------------------------------------
#define SA_STRIDE 40                       // halfs per smem row (32 data + 8 pad)
#define STG_A1 0                           // byte offsets within a stage
#define STG_A2 10240
#define STG_B1 20480
#define STG_B2 25600
#define STAGE_BYTES 30720
#define N_STAGES 3
#define GEMM_SMEM (N_STAGES * STAGE_BYTES) // 92160
#define KSPLIT 2
#define KCHUNK (DD / KSPLIT)               // 4096

__global__ __launch_bounds__(256)
void gemm_mma() {
    extern __shared__ __align__(16) char smem[];
    const uint32_t sbase = smem_to_u32(smem);
    const int tid = threadIdx.x;
    const int lane = tid & 31, wid = tid >> 5;
    const int warp_m = wid >> 1, warp_n = wid & 1;
    const int zi = blockIdx.z;             // batch*2 + split
    const int bz = zi >> 1, sp = zi & 1;
    const int bm = blockIdx.y * 128, bn = blockIdx.x * 64;
    const int kbase8 = sp * (KCHUNK / 8);  // uint4 offset of this split's K range
    float* __restrict__ P = gPart[zi];

    const uint4* __restrict__ Ah = reinterpret_cast<const uint4*>(gAh[bz]);
    const uint4* __restrict__ Al = reinterpret_cast<const uint4*>(gAl[bz]);
    const uint4* __restrict__ Bh = reinterpret_cast<const uint4*>(gBh);
    const uint4* __restrict__ Bl = reinterpret_cast<const uint4*>(gBl);

    float acc[2][4][4] = {};

    const int la_row0 = tid >> 2;          // A rows (x2 via u)
    const int la_c4 = tid & 3;
    const int lb_row = tid >> 2;           // B rows
    const int lb_c4 = tid & 3;

#define LOAD_STAGE(it_)                                                            \
    do {                                                                           \
        const int s_ = (it_) % N_STAGES;                                           \
        const int kc8_ = kbase8 + (it_) * 4;                                       \
        const uint32_t sb_ = sbase + s_ * STAGE_BYTES;                             \
        _Pragma("unroll")                                                          \
        for (int u = 0; u < 2; ++u) {                                              \
            const int row = la_row0 + u * 64;                                      \
            const uint32_t doff = (uint32_t)(row * SA_STRIDE + la_c4 * 8) * 2;     \
            const size_t gi = (size_t)(bm + row) * (DD / 8) + kc8_ + la_c4;        \
            CP_ASYNC16(sb_ + STG_A1 + doff, Ah + gi);                              \
            CP_ASYNC16(sb_ + STG_A2 + doff, Al + gi);                              \
        }                                                                          \
        {                                                                          \
            const uint32_t doff = (uint32_t)(lb_row * SA_STRIDE + lb_c4 * 8) * 2;  \
            const size_t gi = (size_t)(bn + lb_row) * (DD / 8) + kc8_ + lb_c4;     \
            CP_ASYNC16(sb_ + STG_B1 + doff, Bh + gi);                              \
            CP_ASYNC16(sb_ + STG_B2 + doff, Bl + gi);                              \
        }                                                                          \
        CP_COMMIT();                                                               \
    } while (0)

    LOAD_STAGE(0);
    LOAD_STAGE(1);

    const int NKT = KCHUNK / 32;           // 128
#pragma unroll 1
    for (int it = 0; it < NKT; ++it) {
        if (it + 2 < NKT)      { LOAD_STAGE(it + 2); CP_WAIT2(); }
        else if (it + 1 < NKT) { CP_WAIT1(); }
        else                   { CP_WAIT0(); }
        __syncthreads();

        const uint32_t sb = sbase + (it % N_STAGES) * STAGE_BYTES;
#pragma unroll
        for (int ks = 0; ks < 2; ++ks) {
            uint32_t a[2][2][4];           // [plane][mtile]
#pragma unroll
            for (int p = 0; p < 2; ++p)
#pragma unroll
                for (int mt = 0; mt < 2; ++mt) {
                    const int row = warp_m * 32 + mt * 16 + (lane & 15);
                    const int col = ks * 16 + (lane >> 4) * 8;
                    const uint32_t addr = sb + (p ? STG_A2 : STG_A1) +
                                          (uint32_t)(row * SA_STRIDE + col) * 2;
                    LDSM_X4(a[p][mt][0], a[p][mt][1], a[p][mt][2], a[p][mt][3], addr);
                }
            uint32_t b[2][4][2];           // [plane][ntile]
#pragma unroll
            for (int p = 0; p < 2; ++p)
#pragma unroll
                for (int np = 0; np < 2; ++np) {
                    const int r = lane & 7, sel = lane >> 3;
                    const int row = warp_n * 32 + np * 16 + (sel >> 1) * 8 + r;
                    const int col = ks * 16 + (sel & 1) * 8;
                    const uint32_t addr = sb + (p ? STG_B2 : STG_B1) +
                                          (uint32_t)(row * SA_STRIDE + col) * 2;
                    LDSM_X4(b[p][2 * np][0], b[p][2 * np][1],
                            b[p][2 * np + 1][0], b[p][2 * np + 1][1], addr);
                }
#pragma unroll
            for (int mt = 0; mt < 2; ++mt)
#pragma unroll
                for (int nt = 0; nt < 4; ++nt) {
                    MMA16816(acc[mt][nt], a[0][mt], b[0][nt]);   // A1*B1
                    MMA16816(acc[mt][nt], a[0][mt], b[1][nt]);   // A1*B2
                    MMA16816(acc[mt][nt], a[1][mt], b[0][nt]);   // A2*B1
                }
        }
        __syncthreads();
    }
#undef LOAD_STAGE

    // epilogue: vector stores into ALIGNED partial buffer
#pragma unroll
    for (int mt = 0; mt < 2; ++mt) {
        const int r0 = bm + warp_m * 32 + mt * 16 + (lane >> 2);
#pragma unroll
        for (int nt = 0; nt < 4; ++nt) {
            const int gc = bn + warp_n * 32 + nt * 8 + (lane & 3) * 2;
            *reinterpret_cast<float2*>(P + (size_t)r0 * FF + gc) =
                make_float2(acc[mt][nt][0], acc[mt][nt][1]);
            *reinterpret_cast<float2*>(P + (size_t)(r0 + 8) * FF + gc) =
                make_float2(acc[mt][nt][2], acc[mt][nt][3]);
        }
    }
}

// ---------------------------------------------------------------------------
// Split-K reduce: feats[b] = part[2b] + part[2b+1]  (scalar stores: odd align)
// ---------------------------------------------------------------------------
__global__ __launch_bounds__(256)
void reduceK(float* __restrict__ o0, float* __restrict__ o1) {
    const int i = blockIdx.x * 256 + threadIdx.x;   // 0 .. BB*FF-1
    const int b = blockIdx.y;
    float* __restrict__ o = b ? o1 : o0;
    o[i] = gPart[2 * b][i] + gPart[2 * b + 1][i];
}

// ---------------------------------------------------------------------------
// fp32 tiled GEMM (small GEMMs: logits, prot_scores) — all scalar accesses
// ---------------------------------------------------------------------------
__global__ __launch_bounds__(256)
void gemm64(const float* __restrict__ A0, const float* __restrict__ A1,
            const float* __restrict__ Bmat, const float* __restrict__ bias,
            float* __restrict__ C0, float* __restrict__ C1,
            int M, int N, int K)
{
    const float* __restrict__ A = blockIdx.z ? A1 : A0;
    float* __restrict__ C = blockIdx.z ? C1 : C0;
    __shared__ float As[16][64 + 1];
    __shared__ float Bs[16][64];
    const int tid = threadIdx.x;
    const int tx = tid & 15, ty = tid >> 4;
    const int bm = blockIdx.y * 64, bn = blockIdx.x * 64;
    float acc[4][4] = {};
    for (int k0 = 0; k0 < K; k0 += 16) {
        {
            const int acol = tid & 15, arow0 = tid >> 4;
#pragma unroll
            for (int j = 0; j < 4; ++j) {
                const int arow = arow0 + j * 16, gr = bm + arow;
                As[acol][arow] = (gr < M) ? A[(size_t)gr * K + (k0 + acol)] : 0.0f;
            }
        }
        {
            const int brow = tid >> 4, bcol0 = tid & 15;
#pragma unroll
            for (int j = 0; j < 4; ++j) {
                const int bcol = bcol0 + j * 16, gc = bn + bcol;
                Bs[brow][bcol] = (gc < N) ? Bmat[(size_t)(k0 + brow) * N + gc] : 0.0f;
            }
        }
        __syncthreads();
#pragma unroll
        for (int kk = 0; kk < 16; ++kk) {
            float a[4], b[4];
#pragma unroll
            for (int i = 0; i < 4; ++i) a[i] = As[kk][ty * 4 + i];
#pragma unroll
            for (int j = 0; j < 4; ++j) b[j] = Bs[kk][tx * 4 + j];
#pragma unroll
            for (int i = 0; i < 4; ++i)
#pragma unroll
                for (int j = 0; j < 4; ++j) acc[i][j] = fmaf(a[i], b[j], acc[i][j]);
        }
        __syncthreads();
    }
#pragma unroll
    for (int i = 0; i < 4; ++i) {
        const int rr = bm + ty * 4 + i;
        if (rr >= M) continue;
#pragma unroll
        for (int j = 0; j < 4; ++j) {
            const int cidx = bn + tx * 4 + j;
            if (cidx < N) {
                float v = acc[i][j];
                if (bias) v += bias[cidx];
                C[(size_t)rr * N + cidx] = v;
            }
        }
    }
}

// ---------------------------------------------------------------------------
// Masked argmax -> labels (first index on ties)
// ---------------------------------------------------------------------------
__global__ void argmax_kernel(const float* __restrict__ logits,
                              const float* __restrict__ Y,
                              float* __restrict__ labels_f)
{
    const int row = blockIdx.x * 8 + threadIdx.y;
    const int lane = threadIdx.x;
    if (row >= BB) return;
    float best = -FLT_MAX; int bidx = 0x7fffffff;
    for (int c = lane; c < CC; c += 32) {
        if (Y[(size_t)row * CC + c] != 0.0f) {
            const float v = logits[(size_t)row * CC + c];
            if (v > best || (v == best && c < bidx)) { best = v; bidx = c; }
        }
    }
#pragma unroll
    for (int o = 16; o > 0; o >>= 1) {
        const float ov = __shfl_down_sync(0xffffffffu, best, o);
        const int   oi = __shfl_down_sync(0xffffffffu, bidx, o);
        if (ov > best || (ov == best && oi < bidx)) { best = ov; bidx = oi; }
    }
    if (lane == 0) { g_labels[row] = bidx; labels_f[row] = (float)bidx; }
}

// ---------------------------------------------------------------------------
// One-block prep: class-parallel counting scan (smem broadcasts, no O(B) per
// thread serial dependence). 1024 threads.
// ---------------------------------------------------------------------------
__global__ __launch_bounds__(1024)
void prep_kernel() {
    __shared__ int s_lab[BB];
    __shared__ int s_tot[CC];
    __shared__ int s_start[CC];
    const int tid = threadIdx.x;
    s_lab[tid] = g_labels[tid];
    __syncthreads();

    // pass 1: per-class counts (threads 0..CC-1 scan; smem reads broadcast)
    if (tid < CC) {
        int cnt = 0;
        for (int j = 0; j < BB; ++j) cnt += (s_lab[j] == tid);
        s_tot[tid] = cnt;
    }
    __syncthreads();
    if (tid == 0) {
        int acc = 0;
        for (int c = 0; c < CC; ++c) { s_start[c] = acc; acc += s_tot[c]; }
    }
    __syncthreads();

    // pass 2: fill grouped indices + coefficients (class-parallel)
    if (tid < CC) {
        const int n = s_tot[tid];
        const int st = s_start[tid];
        int k = 0;
        for (int j = 0; j < BB; ++j) {
            if (s_lab[j] == tid) {
                g_idx[st + k] = j;
                g_coefs[st + k] = (1.0f - PROTO_W_F) * __powf(PROTO_W_F, (float)(n - 1 - k));
                ++k;
            }
        }
        g_scale[tid] = __powf(PROTO_W_F, (float)n);
        g_start[tid] = st;
        g_n[tid]     = n;
    }
}

// ---------------------------------------------------------------------------
// Prototype EMA + normalize (one block per class, 512 threads = FF)
// ---------------------------------------------------------------------------
__global__ __launch_bounds__(512)
void proto_kernel(const float* __restrict__ feats,
                  const float* __restrict__ proto,
                  float* __restrict__ new_proto)
{
    const int c = blockIdx.x;
    __shared__ float s_red[512];
    __shared__ float s_norm;
    const int tid = threadIdx.x;
    const int n = g_n[c], st = g_start[c];
    float acc = g_scale[c] * proto[(size_t)c * FF + tid];
    for (int k = 0; k < n; ++k)
        acc = fmaf(g_coefs[st + k], feats[(size_t)g_idx[st + k] * FF + tid], acc);
    s_red[tid] = acc * acc;
    __syncthreads();
#pragma unroll
    for (int s = 256; s > 0; s >>= 1) {
        if (tid < s) s_red[tid] += s_red[tid + s];
        __syncthreads();
    }
    if (tid == 0) s_norm = sqrtf(s_red[0]);
    __syncthreads();
    new_proto[(size_t)c * FF + tid] = acc / s_norm;
}

// ---------------------------------------------------------------------------
extern "C" void kernel_launch(void* const* d_in, const int* in_sizes, int n_in,
                              void* d_out, int out_size)
{
    const float* img_q     = (const float*)d_in[0];
    const float* img_q1    = (const float*)d_in[1];
    const float* partial_Y = (const float*)d_in[2];
    const float* W_enc     = (const float*)d_in[3];
    const float* W_fc      = (const float*)d_in[4];
    const float* b_fc      = (const float*)d_in[5];
    const float* proto     = (const float*)d_in[6];

    float* out = (float*)d_out;
    float* o_logits_q  = out + OFF_LOGITS_Q;
    float* o_logits_q1 = out + OFF_LOGITS_Q1;
    float* o_new_proto = out + OFF_NEW_PROTO;
    float* o_prot      = out + OFF_PROT;
    float* o_labels    = out + OFF_LABELS;
    float* o_feats_q   = out + OFF_FEATS_Q;
    float* o_feats_q1  = out + OFF_FEATS_Q1;

    cudaFuncSetAttribute(gemm_mma, cudaFuncAttributeMaxDynamicSharedMemorySize, GEMM_SMEM);

    // 0) split inputs into f16 hi/lo planes (W fused with transpose)
    {
        dim3 blk(32, 8);
        splitW<<<dim3(FF / 32, DD / 32), blk>>>(W_enc);
    }
    {
        void* pAh; void* pAl;
        cudaGetSymbolAddress(&pAh, gAh);
        cudaGetSymbolAddress(&pAl, gAl);
        const int nF4 = BB * DD / 4;
        splitA<<<(nF4 + 255) / 256, 256>>>((const float4*)img_q,
                                           (uint2*)pAh, (uint2*)pAl, nF4);
        splitA<<<(nF4 + 255) / 256, 256>>>((const float4*)img_q1,
                                           (uint2*)((__half*)pAh + (size_t)BB * DD),
                                           (uint2*)((__half*)pAl + (size_t)BB * DD), nF4);
    }

    // 1) feats = img @ W_enc via split-fp16 HMMA, split-K=2 -> partials -> reduce
    {
        dim3 grid(FF / 64, BB / 128, 2 * KSPLIT);   // 8 x 8 x 4 = 256 CTAs
        gemm_mma<<<grid, 256, GEMM_SMEM>>>();
        dim3 rgrid(BB * FF / 256, 2);
        reduceK<<<rgrid, 256>>>(o_feats_q, o_feats_q1);
    }
    // 2) logits = feats @ W_fc + b (fp32, exact path for labels)
    {
        dim3 grid((CC + 63) / 64, BB / 64, 2);
        gemm64<<<grid, 256>>>(o_feats_q, o_feats_q1, W_fc, b_fc,
                              o_logits_q, o_logits_q1, BB, CC, FF);
    }
    // 3) masked argmax -> labels
    {
        dim3 blk(32, 8);
        argmax_kernel<<<BB / 8, blk>>>(o_logits_q, partial_Y, o_labels);
    }
    // 4) prep + prototype EMA + normalize
    prep_kernel<<<1, 1024>>>();
    proto_kernel<<<CC, 512>>>(o_feats_q, proto, o_new_proto);

    // 5) prot_scores = new_proto @ W_fc + b
    {
        dim3 grid((CC + 63) / 64, (CC + 63) / 64, 1);
        gemm64<<<grid, 256>>>(o_new_proto, o_new_proto, W_fc, b_fc,
                              o_prot, o_prot, CC, CC, FF);
    }
}

// round 11
// speedup vs baseline: 2.6948x; 1.0881x over previous
#include <cuda_runtime.h>
#include <cuda_fp16.h>
#include <cstdint>
#include <float.h>

// Problem constants
#define BB 1024
#define DD 8192
#define CC 345
#define FF 512
#define NPAD 384                      // padded class dim for HMMA logits
#define PROTO_W_F 0.99f

// Output layout (flattened, return-tuple order, float32)
#define OFF_LOGITS_Q   0
#define OFF_LOGITS_Q1  353280
#define OFF_NEW_PROTO  706560
#define OFF_PROT       883200
#define OFF_LABELS     1002225
#define OFF_FEATS_Q    1003249
#define OFF_FEATS_Q1   1527537
// NOTE: OFF_FEATS_Q / OFF_FEATS_Q1 are ODD element offsets -> those output
// pointers are only 4-byte aligned. All accesses to them MUST be scalar.

// ---------------------------------------------------------------------------
// Device scratch (static: allocation-free per harness rules)
// ---------------------------------------------------------------------------
__device__ __half gAh[2][BB * DD];   // f16 hi planes of img_q / img_q1 [row][k]
__device__ __half gAl[2][BB * DD];   // f16 lo planes
__device__ __half gBh[FF * DD];      // f16 hi plane of W_enc^T  [n][k]
__device__ __half gBl[FF * DD];      // f16 lo plane
__device__ float gPart[4][BB * FF];  // split-K partials: z = batch*2 + split
__device__ __half gFh[2][BB * FF];   // f16 hi planes of feats (for logits HMMA)
__device__ __half gFl[2][BB * FF];   // f16 lo planes
__device__ __half gWfh[NPAD * FF];   // f16 hi plane of W_fc^T [n][k], zero-padded
__device__ __half gWfl[NPAD * FF];   // f16 lo plane

__device__ int   g_labels[BB];
__device__ int   g_idx[BB];          // sample ids grouped by class, occurrence order
__device__ float g_coefs[BB];        // matching EMA coefficients
__device__ float g_scale[CC];        // w^count per class
__device__ int   g_start[CC];
__device__ int   g_n[CC];

// ---------------------------------------------------------------------------
// PTX helpers (plain sm_103-compatible: cp.async + ldmatrix + mma.sync)
// ---------------------------------------------------------------------------
__device__ __forceinline__ uint32_t smem_to_u32(const void* p) {
    uint32_t a;
    asm("{ .reg .u64 t; cvta.to.shared.u64 t, %1; cvt.u32.u64 %0, t; }" : "=r"(a) : "l"(p));
    return a;
}
#define CP_ASYNC16(dst, src) \
    asm volatile("cp.async.cg.shared.global [%0], [%1], 16;" :: "r"(dst), "l"(src) : "memory")
#define CP_COMMIT()  asm volatile("cp.async.commit_group;" ::: "memory")
#define CP_WAIT1()   asm volatile("cp.async.wait_group 1;" ::: "memory")
#define CP_WAIT0()   asm volatile("cp.async.wait_group 0;" ::: "memory")
#define LDSM_X4(r0, r1, r2, r3, addr) \
    asm volatile("ldmatrix.sync.aligned.m8n8.x4.shared.b16 {%0,%1,%2,%3}, [%4];" \
                 : "=r"(r0), "=r"(r1), "=r"(r2), "=r"(r3) : "r"(addr))
#define MMA16816(d, a, b) \
    asm volatile("mma.sync.aligned.m16n8k16.row.col.f32.f16.f16.f32 " \
                 "{%0,%1,%2,%3}, {%4,%5,%6,%7}, {%8,%9}, {%0,%1,%2,%3};" \
                 : "+f"((d)[0]), "+f"((d)[1]), "+f"((d)[2]), "+f"((d)[3]) \
                 : "r"((a)[0]), "r"((a)[1]), "r"((a)[2]), "r"((a)[3]), \
                   "r"((b)[0]), "r"((b)[1]))

// ---------------------------------------------------------------------------
// Fused transpose+split: W_enc [DD x FF] fp32 -> gBh/gBl [FF x DD] f16 planes
// ---------------------------------------------------------------------------
__global__ void splitW(const float* __restrict__ W) {
    __shared__ float t[32][33];
    const int n0 = blockIdx.x * 32, k0 = blockIdx.y * 32;
    const int tx = threadIdx.x, ty = threadIdx.y;
#pragma unroll
    for (int j = 0; j < 4; ++j)
        t[ty + 8 * j][tx] = W[(size_t)(k0 + ty + 8 * j) * FF + n0 + tx];
    __syncthreads();
#pragma unroll
    for (int j = 0; j < 4; ++j) {
        const float v = t[tx][ty + 8 * j];     // = W[k0+tx][n0+ty+8j]
        const int n = n0 + ty + 8 * j, k = k0 + tx;
        const __half h = __float2half_rn(v);
        gBh[(size_t)n * DD + k] = h;
        gBl[(size_t)n * DD + k] = __float2half_rn(v - __half2float(h));
    }
}

// ---------------------------------------------------------------------------
// Transpose+split W_fc [FF x CC] fp32 -> gWfh/gWfl [NPAD x FF], zero padding
// ---------------------------------------------------------------------------
__global__ void splitWfc(const float* __restrict__ W) {
    __shared__ float t[32][33];
    const int n0 = blockIdx.x * 32, k0 = blockIdx.y * 32;   // n over NPAD, k over FF
    const int tx = threadIdx.x, ty = threadIdx.y;
#pragma unroll
    for (int j = 0; j < 4; ++j) {
        const int nn = n0 + tx, kk = k0 + ty + 8 * j;
        t[ty + 8 * j][tx] = (nn < CC) ? W[(size_t)kk * CC + nn] : 0.0f;
    }
    __syncthreads();
#pragma unroll
    for (int j = 0; j < 4; ++j) {
        const float v = t[tx][ty + 8 * j];
        const int n = n0 + ty + 8 * j, k = k0 + tx;
        const __half h = __float2half_rn(v);
        gWfh[(size_t)n * FF + k] = h;
        gWfl[(size_t)n * FF + k] = __float2half_rn(v - __half2float(h));
    }
}

// ---------------------------------------------------------------------------
// fp32 -> (f16 hi, f16 lo) planes, vectorized (src/dst are 16B-aligned bufs)
// ---------------------------------------------------------------------------
__global__ __launch_bounds__(256)
void splitA(const float4* __restrict__ src, uint2* __restrict__ hi,
            uint2* __restrict__ lo, int nF4) {
    const int i = blockIdx.x * 256 + threadIdx.x;
    if (i >= nF4) return;
    float4 v = src[i];
    __half2 h01 = __floats2half2_rn(v.x, v.y);
    __half2 h23 = __floats2half2_rn(v.z, v.w);
    float2 f01 = __half22float2(h01);
    float2 f23 = __half22float2(h23);
    __half2 l01 = __floats2half2_rn(v.x - f01.x, v.y - f01.y);
    __half2 l23 = __floats2half2_rn(v.z - f23.x, v.w - f23.y);
    uint2 hw, lw;
    hw.x = *reinterpret_cast<uint32_t*>(&h01); hw.y = *reinterpret_cast<uint32_t*>(&h23);
    lw.x = *reinterpret_cast<uint32_t*>(&l01); lw.y = *reinterpret_cast<uint32_t*>(&l23);
    hi[i] = hw; lo[i] = lw;
}

// ---------------------------------------------------------------------------
// Split-FP16 HMMA GEMM with split-K (feats = img @ W_enc).
// BM=128, BN=64, BK=32, 256 threads (8 warps as 4m x 2n, warp tile 32x32).
// 3-stage cp.async pipeline, ONE barrier per k-iter, product-major MMAs.
// grid = (8, 8, 4): z = batch*2 + split, split covers K/2 = 4096.
// ---------------------------------------------------------------------------
#define SA_STRIDE 40                       // halfs per smem row (32 data + 8 pad)
#define STG_A1 0                           // byte offsets within a stage
#define STG_A2 10240
#define STG_B1 20480
#define STG_B2 25600
#define STAGE_BYTES 30720
#define N_STAGES 3
#define GEMM_SMEM (N_STAGES * STAGE_BYTES) // 92160
#define KSPLIT 2
#define KCHUNK (DD / KSPLIT)               // 4096

// Consume one 32-K stage: ldmatrix both planes, product-major MMA schedule.
#define CONSUME_STAGE(sb)                                                          \
    do {                                                                           \
        _Pragma("unroll")                                                          \
        for (int ks = 0; ks < 2; ++ks) {                                           \
            uint32_t a[2][2][4];                                                   \
            _Pragma("unroll")                                                      \
            for (int p = 0; p < 2; ++p)                                            \
                _Pragma("unroll")                                                  \
                for (int mt = 0; mt < 2; ++mt) {                                   \
                    const int row = warp_m * 32 + mt * 16 + (lane & 15);           \
                    const int col = ks * 16 + (lane >> 4) * 8;                     \
                    const uint32_t addr = (sb) + (p ? STG_A2 : STG_A1) +           \
                                          (uint32_t)(row * SA_STRIDE + col) * 2;   \
                    LDSM_X4(a[p][mt][0], a[p][mt][1], a[p][mt][2], a[p][mt][3], addr); \
                }                                                                  \
            uint32_t b[2][4][2];                                                   \
            _Pragma("unroll")                                                      \
            for (int p = 0; p < 2; ++p)                                            \
                _Pragma("unroll")                                                  \
                for (int np = 0; np < 2; ++np) {                                   \
                    const int r = lane & 7, sel = lane >> 3;                       \
                    const int row = warp_n * 32 + np * 16 + (sel >> 1) * 8 + r;    \
                    const int col = ks * 16 + (sel & 1) * 8;                       \
                    const uint32_t addr = (sb) + (p ? STG_B2 : STG_B1) +           \
                                          (uint32_t)(row * SA_STRIDE + col) * 2;   \
                    LDSM_X4(b[p][2 * np][0], b[p][2 * np][1],                      \
                            b[p][2 * np + 1][0], b[p][2 * np + 1][1], addr);       \
                }                                                                  \
            /* product-major: 8 independent accs between dependent reuses */       \
            _Pragma("unroll")                                                      \
            for (int mt = 0; mt < 2; ++mt)                                         \
                _Pragma("unroll")                                                  \
                for (int nt = 0; nt < 4; ++nt)                                     \
                    MMA16816(acc[mt][nt], a[0][mt], b[0][nt]);                     \
            _Pragma("unroll")                                                      \
            for (int mt = 0; mt < 2; ++mt)                                         \
                _Pragma("unroll")                                                  \
                for (int nt = 0; nt < 4; ++nt)                                     \
                    MMA16816(acc[mt][nt], a[0][mt], b[1][nt]);                     \
            _Pragma("unroll")                                                      \
            for (int mt = 0; mt < 2; ++mt)                                         \
                _Pragma("unroll")                                                  \
                for (int nt = 0; nt < 4; ++nt)                                     \
                    MMA16816(acc[mt][nt], a[1][mt], b[0][nt]);                     \
        }                                                                          \
    } while (0)

__global__ __launch_bounds__(256)
void gemm_mma() {
    extern __shared__ __align__(16) char smem[];
    const uint32_t sbase = smem_to_u32(smem);
    const int tid = threadIdx.x;
    const int lane = tid & 31, wid = tid >> 5;
    const int warp_m = wid >> 1, warp_n = wid & 1;
    const int zi = blockIdx.z;             // batch*2 + split
    const int bz = zi >> 1, sp = zi & 1;
    const int bm = blockIdx.y * 128, bn = blockIdx.x * 64;
    const int kbase8 = sp * (KCHUNK / 8);
    float* __restrict__ P = gPart[zi];

    const uint4* __restrict__ Ah = reinterpret_cast<const uint4*>(gAh[bz]);
    const uint4* __restrict__ Al = reinterpret_cast<const uint4*>(gAl[bz]);
    const uint4* __restrict__ Bh = reinterpret_cast<const uint4*>(gBh);
    const uint4* __restrict__ Bl = reinterpret_cast<const uint4*>(gBl);

    float acc[2][4][4] = {};

    const int la_row0 = tid >> 2;
    const int la_c4 = tid & 3;

#define LOAD_STAGE(it_)                                                            \
    do {                                                                           \
        const int s_ = (it_) % N_STAGES;                                           \
        const int kc8_ = kbase8 + (it_) * 4;                                       \
        const uint32_t sb_ = sbase + s_ * STAGE_BYTES;                             \
        _Pragma("unroll")                                                          \
        for (int u = 0; u < 2; ++u) {                                              \
            const int row = la_row0 + u * 64;                                      \
            const uint32_t doff = (uint32_t)(row * SA_STRIDE + la_c4 * 8) * 2;     \
            const size_t gi = (size_t)(bm + row) * (DD / 8) + kc8_ + la_c4;        \
            CP_ASYNC16(sb_ + STG_A1 + doff, Ah + gi);                              \
            CP_ASYNC16(sb_ + STG_A2 + doff, Al + gi);                              \
        }                                                                          \
        {                                                                          \
            const uint32_t doff = (uint32_t)(la_row0 * SA_STRIDE + la_c4 * 8) * 2; \
            const size_t gi = (size_t)(bn + la_row0) * (DD / 8) + kc8_ + la_c4;    \
            CP_ASYNC16(sb_ + STG_B1 + doff, Bh + gi);                              \
            CP_ASYNC16(sb_ + STG_B2 + doff, Bl + gi);                              \
        }                                                                          \
        CP_COMMIT();                                                               \
    } while (0)

    LOAD_STAGE(0);
    LOAD_STAGE(1);

    const int NKT = KCHUNK / 32;           // 128
#pragma unroll 1
    for (int it = 0; it < NKT; ++it) {
        if (it + 1 < NKT) CP_WAIT1(); else CP_WAIT0();
        __syncthreads();                   // single barrier per iter
        if (it + 2 < NKT) LOAD_STAGE(it + 2);   // writes slot (it-1)%3: safe
        const uint32_t sb = sbase + (it % N_STAGES) * STAGE_BYTES;
        CONSUME_STAGE(sb);
    }
#undef LOAD_STAGE

    // epilogue: vector stores into ALIGNED partial buffer
#pragma unroll
    for (int mt = 0; mt < 2; ++mt) {
        const int r0 = bm + warp_m * 32 + mt * 16 + (lane >> 2);
#pragma unroll
        for (int nt = 0; nt < 4; ++nt) {
            const int gc = bn + warp_n * 32 + nt * 8 + (lane & 3) * 2;
            *reinterpret_cast<float2*>(P + (size_t)r0 * FF + gc) =
                make_float2(acc[mt][nt][0], acc[mt][nt][1]);
            *reinterpret_cast<float2*>(P + (size_t)(r0 + 8) * FF + gc) =
                make_float2(acc[mt][nt][2], acc[mt][nt][3]);
        }
    }
}

// ---------------------------------------------------------------------------
// Split-K reduce: feats = part0 + part1; also emit f16 hi/lo planes of feats.
// 2 elements per thread (half2 plane stores). Scalar fp32 stores (odd align).
// ---------------------------------------------------------------------------
__global__ __launch_bounds__(256)
void reduceK(float* __restrict__ o0, float* __restrict__ o1) {
    const int i2 = blockIdx.x * 256 + threadIdx.x;   // pair index
    const int b = blockIdx.y;
    const int i = i2 * 2;
    float* __restrict__ o = b ? o1 : o0;
    const float s0 = gPart[2 * b][i]     + gPart[2 * b + 1][i];
    const float s1 = gPart[2 * b][i + 1] + gPart[2 * b + 1][i + 1];
    o[i] = s0; o[i + 1] = s1;
    __half2 h = __floats2half2_rn(s0, s1);
    float2 hf = __half22float2(h);
    __half2 l = __floats2half2_rn(s0 - hf.x, s1 - hf.y);
    *reinterpret_cast<__half2*>(&gFh[b][i]) = h;
    *reinterpret_cast<__half2*>(&gFl[b][i]) = l;
}

// ---------------------------------------------------------------------------
// Split-FP16 HMMA logits GEMM: logits[b] = feats[b] @ W_fc + b_fc
// M=1024, N=NPAD(384, mask to 345), K=512. Same tile scheme, NKT=16.
// grid = (6, 8, 2). Output: scalar stores, row stride 345.
// ---------------------------------------------------------------------------
__global__ __launch_bounds__(256)
void gemm_logits(float* __restrict__ C0, float* __restrict__ C1,
                 const float* __restrict__ bias) {
    extern __shared__ __align__(16) char smem[];
    const uint32_t sbase = smem_to_u32(smem);
    const int tid = threadIdx.x;
    const int lane = tid & 31, wid = tid >> 5;
    const int warp_m = wid >> 1, warp_n = wid & 1;
    const int bz = blockIdx.z;
    const int bm = blockIdx.y * 128, bn = blockIdx.x * 64;
    float* __restrict__ C = bz ? C1 : C0;

    const uint4* __restrict__ Ah = reinterpret_cast<const uint4*>(gFh[bz]);
    const uint4* __restrict__ Al = reinterpret_cast<const uint4*>(gFl[bz]);
    const uint4* __restrict__ Bh = reinterpret_cast<const uint4*>(gWfh);
    const uint4* __restrict__ Bl = reinterpret_cast<const uint4*>(gWfl);

    float acc[2][4][4] = {};

    const int la_row0 = tid >> 2;
    const int la_c4 = tid & 3;

#define LOAD_STAGE_L(it_)                                                          \
    do {                                                                           \
        const int s_ = (it_) % N_STAGES;                                           \
        const int kc8_ = (it_) * 4;                                                \
        const uint32_t sb_ = sbase + s_ * STAGE_BYTES;                             \
        _Pragma("unroll")                                                          \
        for (int u = 0; u < 2; ++u) {                                              \
            const int row = la_row0 + u * 64;                                      \
            const uint32_t doff = (uint32_t)(row * SA_STRIDE + la_c4 * 8) * 2;     \
            const size_t gi = (size_t)(bm + row) * (FF / 8) + kc8_ + la_c4;        \
            CP_ASYNC16(sb_ + STG_A1 + doff, Ah + gi);                              \
            CP_ASYNC16(sb_ + STG_A2 + doff, Al + gi);                              \
        }                                                                          \
        {                                                                          \
            const uint32_t doff = (uint32_t)(la_row0 * SA_STRIDE + la_c4 * 8) * 2; \
            const size_t gi = (size_t)(bn + la_row0) * (FF / 8) + kc8_ + la_c4;    \
            CP_ASYNC16(sb_ + STG_B1 + doff, Bh + gi);                              \
            CP_ASYNC16(sb_ + STG_B2 + doff, Bl + gi);                              \
        }                                                                          \
        CP_COMMIT();                                                               \
    } while (0)

    LOAD_STAGE_L(0);
    LOAD_STAGE_L(1);

    const int NKT = FF / 32;               // 16
#pragma unroll 1
    for (int it = 0; it < NKT; ++it) {
        if (it + 1 < NKT) CP_WAIT1(); else CP_WAIT0();
        __syncthreads();
        if (it + 2 < NKT) LOAD_STAGE_L(it + 2);
        const uint32_t sb = sbase + (it % N_STAGES) * STAGE_BYTES;
        CONSUME_STAGE(sb);
    }
#undef LOAD_STAGE_L

    // epilogue: scalar stores into [1024 x 345] with bias, mask n >= CC
#pragma unroll
    for (int mt = 0; mt < 2; ++mt) {
        const int r0 = bm + warp_m * 32 + mt * 16 + (lane >> 2);
#pragma unroll
        for (int nt = 0; nt < 4; ++nt) {
            const int gc = bn + warp_n * 32 + nt * 8 + (lane & 3) * 2;
            if (gc < CC) {
                C[(size_t)r0 * CC + gc] = acc[mt][nt][0] + bias[gc];
                C[(size_t)(r0 + 8) * CC + gc] = acc[mt][nt][2] + bias[gc];
            }
            if (gc + 1 < CC) {
                C[(size_t)r0 * CC + gc + 1] = acc[mt][nt][1] + bias[gc + 1];
                C[(size_t)(r0 + 8) * CC + gc + 1] = acc[mt][nt][3] + bias[gc + 1];
            }
        }
    }
}

// ---------------------------------------------------------------------------
// fp32 tiled GEMM (prot_scores only) — all scalar accesses
// ---------------------------------------------------------------------------
__global__ __launch_bounds__(256)
void gemm64(const float* __restrict__ A0,
            const float* __restrict__ Bmat, const float* __restrict__ bias,
            float* __restrict__ C0, int M, int N, int K)
{
    const float* __restrict__ A = A0;
    float* __restrict__ C = C0;
    __shared__ float As[16][64 + 1];
    __shared__ float Bs[16][64];
    const int tid = threadIdx.x;
    const int tx = tid & 15, ty = tid >> 4;
    const int bm = blockIdx.y * 64, bn = blockIdx.x * 64;
    float acc[4][4] = {};
    for (int k0 = 0; k0 < K; k0 += 16) {
        {
            const int acol = tid & 15, arow0 = tid >> 4;
#pragma unroll
            for (int j = 0; j < 4; ++j) {
                const int arow = arow0 + j * 16, gr = bm + arow;
                As[acol][arow] = (gr < M) ? A[(size_t)gr * K + (k0 + acol)] : 0.0f;
            }
        }
        {
            const int brow = tid >> 4, bcol0 = tid & 15;
#pragma unroll
            for (int j = 0; j < 4; ++j) {
                const int bcol = bcol0 + j * 16, gc = bn + bcol;
                Bs[brow][bcol] = (gc < N) ? Bmat[(size_t)(k0 + brow) * N + gc] : 0.0f;
            }
        }
        __syncthreads();
#pragma unroll
        for (int kk = 0; kk < 16; ++kk) {
            float a[4], b[4];
#pragma unroll
            for (int i = 0; i < 4; ++i) a[i] = As[kk][ty * 4 + i];
#pragma unroll
            for (int j = 0; j < 4; ++j) b[j] = Bs[kk][tx * 4 + j];
#pragma unroll
            for (int i = 0; i < 4; ++i)
#pragma unroll
                for (int j = 0; j < 4; ++j) acc[i][j] = fmaf(a[i], b[j], acc[i][j]);
        }
        __syncthreads();
    }
#pragma unroll
    for (int i = 0; i < 4; ++i) {
        const int rr = bm + ty * 4 + i;
        if (rr >= M) continue;
#pragma unroll
        for (int j = 0; j < 4; ++j) {
            const int cidx = bn + tx * 4 + j;
            if (cidx < N) {
                float v = acc[i][j];
                if (bias) v += bias[cidx];
                C[(size_t)rr * N + cidx] = v;
            }
        }
    }
}

// ---------------------------------------------------------------------------
// Masked argmax -> labels (first index on ties)
// ---------------------------------------------------------------------------
__global__ void argmax_kernel(const float* __restrict__ logits,
                              const float* __restrict__ Y,
                              float* __restrict__ labels_f)
{
    const int row = blockIdx.x * 8 + threadIdx.y;
    const int lane = threadIdx.x;
    if (row >= BB) return;
    float best = -FLT_MAX; int bidx = 0x7fffffff;
    for (int c = lane; c < CC; c += 32) {
        if (Y[(size_t)row * CC + c] != 0.0f) {
            const float v = logits[(size_t)row * CC + c];
            if (v > best || (v == best && c < bidx)) { best = v; bidx = c; }
        }
    }
#pragma unroll
    for (int o = 16; o > 0; o >>= 1) {
        const float ov = __shfl_down_sync(0xffffffffu, best, o);
        const int   oi = __shfl_down_sync(0xffffffffu, bidx, o);
        if (ov > best || (ov == best && oi < bidx)) { best = ov; bidx = oi; }
    }
    if (lane == 0) { g_labels[row] = bidx; labels_f[row] = (float)bidx; }
}

// ---------------------------------------------------------------------------
// One-block prep: class-parallel counting scan. 1024 threads.
// ---------------------------------------------------------------------------
__global__ __launch_bounds__(1024)
void prep_kernel() {
    __shared__ int s_lab[BB];
    __shared__ int s_tot[CC];
    __shared__ int s_start[CC];
    const int tid = threadIdx.x;
    s_lab[tid] = g_labels[tid];
    __syncthreads();

    if (tid < CC) {
        int cnt = 0;
        for (int j = 0; j < BB; ++j) cnt += (s_lab[j] == tid);
        s_tot[tid] = cnt;
    }
    __syncthreads();
    if (tid == 0) {
        int acc = 0;
        for (int c = 0; c < CC; ++c) { s_start[c] = acc; acc += s_tot[c]; }
    }
    __syncthreads();

    if (tid < CC) {
        const int n = s_tot[tid];
        const int st = s_start[tid];
        int k = 0;
        for (int j = 0; j < BB; ++j) {
            if (s_lab[j] == tid) {
                g_idx[st + k] = j;
                g_coefs[st + k] = (1.0f - PROTO_W_F) * __powf(PROTO_W_F, (float)(n - 1 - k));
                ++k;
            }
        }
        g_scale[tid] = __powf(PROTO_W_F, (float)n);
        g_start[tid] = st;
        g_n[tid]     = n;
    }
}

// ---------------------------------------------------------------------------
// Prototype EMA + normalize (one block per class, 512 threads = FF)
// ---------------------------------------------------------------------------
__global__ __launch_bounds__(512)
void proto_kernel(const float* __restrict__ feats,
                  const float* __restrict__ proto,
                  float* __restrict__ new_proto)
{
    const int c = blockIdx.x;
    __shared__ float s_red[512];
    __shared__ float s_norm;
    const int tid = threadIdx.x;
    const int n = g_n[c], st = g_start[c];
    float acc = g_scale[c] * proto[(size_t)c * FF + tid];
    for (int k = 0; k < n; ++k)
        acc = fmaf(g_coefs[st + k], feats[(size_t)g_idx[st + k] * FF + tid], acc);
    s_red[tid] = acc * acc;
    __syncthreads();
#pragma unroll
    for (int s = 256; s > 0; s >>= 1) {
        if (tid < s) s_red[tid] += s_red[tid + s];
        __syncthreads();
    }
    if (tid == 0) s_norm = sqrtf(s_red[0]);
    __syncthreads();
    new_proto[(size_t)c * FF + tid] = acc / s_norm;
}

// ---------------------------------------------------------------------------
extern "C" void kernel_launch(void* const* d_in, const int* in_sizes, int n_in,
                              void* d_out, int out_size)
{
    const float* img_q     = (const float*)d_in[0];
    const float* img_q1    = (const float*)d_in[1];
    const float* partial_Y = (const float*)d_in[2];
    const float* W_enc     = (const float*)d_in[3];
    const float* W_fc      = (const float*)d_in[4];
    const float* b_fc      = (const float*)d_in[5];
    const float* proto     = (const float*)d_in[6];

    float* out = (float*)d_out;
    float* o_logits_q  = out + OFF_LOGITS_Q;
    float* o_logits_q1 = out + OFF_LOGITS_Q1;
    float* o_new_proto = out + OFF_NEW_PROTO;
    float* o_prot      = out + OFF_PROT;
    float* o_labels    = out + OFF_LABELS;
    float* o_feats_q   = out + OFF_FEATS_Q;
    float* o_feats_q1  = out + OFF_FEATS_Q1;

    cudaFuncSetAttribute(gemm_mma, cudaFuncAttributeMaxDynamicSharedMemorySize, GEMM_SMEM);
    cudaFuncSetAttribute(gemm_logits, cudaFuncAttributeMaxDynamicSharedMemorySize, GEMM_SMEM);

    // 0) split inputs into f16 hi/lo planes (W fused with transpose)
    {
        dim3 blk(32, 8);
        splitW<<<dim3(FF / 32, DD / 32), blk>>>(W_enc);
        splitWfc<<<dim3(NPAD / 32, FF / 32), blk>>>(W_fc);
    }
    {
        void* pAh; void* pAl;
        cudaGetSymbolAddress(&pAh, gAh);
        cudaGetSymbolAddress(&pAl, gAl);
        const int nF4 = BB * DD / 4;
        splitA<<<(nF4 + 255) / 256, 256>>>((const float4*)img_q,
                                           (uint2*)pAh, (uint2*)pAl, nF4);
        splitA<<<(nF4 + 255) / 256, 256>>>((const float4*)img_q1,
                                           (uint2*)((__half*)pAh + (size_t)BB * DD),
                                           (uint2*)((__half*)pAl + (size_t)BB * DD), nF4);
    }

    // 1) feats = img @ W_enc via split-fp16 HMMA, split-K=2 -> partials -> reduce
    {
        dim3 grid(FF / 64, BB / 128, 2 * KSPLIT);   // 8 x 8 x 4 = 256 CTAs
        gemm_mma<<<grid, 256, GEMM_SMEM>>>();
        dim3 rgrid(BB * FF / 512, 2);
        reduceK<<<rgrid, 256>>>(o_feats_q, o_feats_q1);
    }
    // 2) logits = feats @ W_fc + b via split-fp16 HMMA
    {
        dim3 grid(NPAD / 64, BB / 128, 2);          // 6 x 8 x 2 = 96 CTAs
        gemm_logits<<<grid, 256, GEMM_SMEM>>>(o_logits_q, o_logits_q1, b_fc);
    }
    // 3) masked argmax -> labels
    {
        dim3 blk(32, 8);
        argmax_kernel<<<BB / 8, blk>>>(o_logits_q, partial_Y, o_labels);
    }
    // 4) prep + prototype EMA + normalize
    prep_kernel<<<1, 1024>>>();
    proto_kernel<<<CC, 512>>>(o_feats_q, proto, o_new_proto);

    // 5) prot_scores = new_proto @ W_fc + b (fp32, small)
    {
        dim3 grid((CC + 63) / 64, (CC + 63) / 64, 1);
        gemm64<<<grid, 256>>>(o_new_proto, W_fc, b_fc, o_prot, CC, CC, FF);
    }
}

// round 12
// speedup vs baseline: 2.7672x; 1.0268x over previous
#include <cuda_runtime.h>
#include <cuda_fp16.h>
#include <cstdint>
#include <float.h>

// Problem constants
#define BB 1024
#define DD 8192
#define CC 345
#define FF 512
#define NPAD 384                      // padded class dim for HMMA logits
#define PROTO_W_F 0.99f

// Output layout (flattened, return-tuple order, float32)
#define OFF_LOGITS_Q   0
#define OFF_LOGITS_Q1  353280
#define OFF_NEW_PROTO  706560
#define OFF_PROT       883200
#define OFF_LABELS     1002225
#define OFF_FEATS_Q    1003249
#define OFF_FEATS_Q1   1527537
// NOTE: OFF_FEATS_Q / OFF_FEATS_Q1 are ODD element offsets -> those output
// pointers are only 4-byte aligned. All accesses to them MUST be scalar.

#define KSPLIT 4
#define KCHUNK (DD / KSPLIT)               // 2048

// ---------------------------------------------------------------------------
// Device scratch (static: allocation-free per harness rules)
// ---------------------------------------------------------------------------
__device__ __half gAh[2][BB * DD];   // f16 hi planes of img_q / img_q1 [row][k]
__device__ __half gAl[2][BB * DD];   // f16 lo planes
__device__ __half gBh[FF * DD];      // f16 hi plane of W_enc^T  [n][k]
__device__ __half gBl[FF * DD];      // f16 lo plane
__device__ float gPart[2 * KSPLIT][BB * FF];  // split-K partials: z = batch*KSPLIT + split
__device__ __half gFh[2][BB * FF];   // f16 hi planes of feats (for logits HMMA)
__device__ __half gFl[2][BB * FF];   // f16 lo planes
__device__ __half gWfh[NPAD * FF];   // f16 hi plane of W_fc^T [n][k], zero-padded
__device__ __half gWfl[NPAD * FF];   // f16 lo plane

__device__ int   g_labels[BB];
__device__ int   g_idx[BB];          // sample ids grouped by class, occurrence order
__device__ float g_coefs[BB];        // matching EMA coefficients
__device__ float g_scale[CC];        // w^count per class
__device__ int   g_start[CC];
__device__ int   g_n[CC];

// ---------------------------------------------------------------------------
// PTX helpers (plain sm_103-compatible: cp.async + ldmatrix + mma.sync)
// ---------------------------------------------------------------------------
__device__ __forceinline__ uint32_t smem_to_u32(const void* p) {
    uint32_t a;
    asm("{ .reg .u64 t; cvta.to.shared.u64 t, %1; cvt.u32.u64 %0, t; }" : "=r"(a) : "l"(p));
    return a;
}
#define CP_ASYNC16(dst, src) \
    asm volatile("cp.async.cg.shared.global [%0], [%1], 16;" :: "r"(dst), "l"(src) : "memory")
#define CP_COMMIT()  asm volatile("cp.async.commit_group;" ::: "memory")
#define CP_WAIT1()   asm volatile("cp.async.wait_group 1;" ::: "memory")
#define CP_WAIT0()   asm volatile("cp.async.wait_group 0;" ::: "memory")
#define LDSM_X4(r0, r1, r2, r3, addr) \
    asm volatile("ldmatrix.sync.aligned.m8n8.x4.shared.b16 {%0,%1,%2,%3}, [%4];" \
                 : "=r"(r0), "=r"(r1), "=r"(r2), "=r"(r3) : "r"(addr))
#define MMA16816(d, a, b) \
    asm volatile("mma.sync.aligned.m16n8k16.row.col.f32.f16.f16.f32 " \
                 "{%0,%1,%2,%3}, {%4,%5,%6,%7}, {%8,%9}, {%0,%1,%2,%3};" \
                 : "+f"((d)[0]), "+f"((d)[1]), "+f"((d)[2]), "+f"((d)[3]) \
                 : "r"((a)[0]), "r"((a)[1]), "r"((a)[2]), "r"((a)[3]), \
                   "r"((b)[0]), "r"((b)[1]))

// ---------------------------------------------------------------------------
// Fused transpose+split: W_enc [DD x FF] fp32 -> gBh/gBl [FF x DD] f16 planes
// ---------------------------------------------------------------------------
__global__ void splitW(const float* __restrict__ W) {
    __shared__ float t[32][33];
    const int n0 = blockIdx.x * 32, k0 = blockIdx.y * 32;
    const int tx = threadIdx.x, ty = threadIdx.y;
#pragma unroll
    for (int j = 0; j < 4; ++j)
        t[ty + 8 * j][tx] = W[(size_t)(k0 + ty + 8 * j) * FF + n0 + tx];
    __syncthreads();
#pragma unroll
    for (int j = 0; j < 4; ++j) {
        const float v = t[tx][ty + 8 * j];     // = W[k0+tx][n0+ty+8j]
        const int n = n0 + ty + 8 * j, k = k0 + tx;
        const __half h = __float2half_rn(v);
        gBh[(size_t)n * DD + k] = h;
        gBl[(size_t)n * DD + k] = __float2half_rn(v - __half2float(h));
    }
}

// ---------------------------------------------------------------------------
// Transpose+split W_fc [FF x CC] fp32 -> gWfh/gWfl [NPAD x FF], zero padding
// ---------------------------------------------------------------------------
__global__ void splitWfc(const float* __restrict__ W) {
    __shared__ float t[32][33];
    const int n0 = blockIdx.x * 32, k0 = blockIdx.y * 32;   // n over NPAD, k over FF
    const int tx = threadIdx.x, ty = threadIdx.y;
#pragma unroll
    for (int j = 0; j < 4; ++j) {
        const int nn = n0 + tx, kk = k0 + ty + 8 * j;
        t[ty + 8 * j][tx] = (nn < CC) ? W[(size_t)kk * CC + nn] : 0.0f;
    }
    __syncthreads();
#pragma unroll
    for (int j = 0; j < 4; ++j) {
        const float v = t[tx][ty + 8 * j];
        const int n = n0 + ty + 8 * j, k = k0 + tx;
        const __half h = __float2half_rn(v);
        gWfh[(size_t)n * FF + k] = h;
        gWfl[(size_t)n * FF + k] = __float2half_rn(v - __half2float(h));
    }
}

// ---------------------------------------------------------------------------
// fp32 -> (f16 hi, f16 lo) planes, vectorized (src/dst are 16B-aligned bufs)
// ---------------------------------------------------------------------------
__global__ __launch_bounds__(256)
void splitA(const float4* __restrict__ src, uint2* __restrict__ hi,
            uint2* __restrict__ lo, int nF4) {
    const int i = blockIdx.x * 256 + threadIdx.x;
    if (i >= nF4) return;
    float4 v = src[i];
    __half2 h01 = __floats2half2_rn(v.x, v.y);
    __half2 h23 = __floats2half2_rn(v.z, v.w);
    float2 f01 = __half22float2(h01);
    float2 f23 = __half22float2(h23);
    __half2 l01 = __floats2half2_rn(v.x - f01.x, v.y - f01.y);
    __half2 l23 = __floats2half2_rn(v.z - f23.x, v.w - f23.y);
    uint2 hw, lw;
    hw.x = *reinterpret_cast<uint32_t*>(&h01); hw.y = *reinterpret_cast<uint32_t*>(&h23);
    lw.x = *reinterpret_cast<uint32_t*>(&l01); lw.y = *reinterpret_cast<uint32_t*>(&l23);
    hi[i] = hw; lo[i] = lw;
}

// ---------------------------------------------------------------------------
// Split-FP16 HMMA GEMM with split-K (feats = img @ W_enc).
// BM=128, BN=64, BK=32, 256 threads (8 warps as 4m x 2n, warp tile 32x32).
// 3-stage cp.async pipeline, ONE barrier per k-iter.
// All 16 LDSM of the iter hoisted before the 96 MMAs (product-major).
// grid = (8, 8, 2*KSPLIT).
// ---------------------------------------------------------------------------
#define SA_STRIDE 40                       // halfs per smem row (32 data + 8 pad)
#define STG_A1 0                           // byte offsets within a stage
#define STG_A2 10240
#define STG_B1 20480
#define STG_B2 25600
#define STAGE_BYTES 30720
#define N_STAGES 3
#define GEMM_SMEM (N_STAGES * STAGE_BYTES) // 92160

// Consume one 32-K stage: hoist ALL ldmatrix, then product-major MMA schedule.
#define CONSUME_STAGE(sb)                                                          \
    do {                                                                           \
        uint32_t a[2][2][2][4];   /* [ks][plane][mtile] */                         \
        uint32_t b[2][2][4][2];   /* [ks][plane][ntile] */                         \
        _Pragma("unroll")                                                          \
        for (int ks = 0; ks < 2; ++ks) {                                           \
            _Pragma("unroll")                                                      \
            for (int p = 0; p < 2; ++p)                                            \
                _Pragma("unroll")                                                  \
                for (int mt = 0; mt < 2; ++mt) {                                   \
                    const int row = warp_m * 32 + mt * 16 + (lane & 15);           \
                    const int col = ks * 16 + (lane >> 4) * 8;                     \
                    const uint32_t addr = (sb) + (p ? STG_A2 : STG_A1) +           \
                                          (uint32_t)(row * SA_STRIDE + col) * 2;   \
                    LDSM_X4(a[ks][p][mt][0], a[ks][p][mt][1],                      \
                            a[ks][p][mt][2], a[ks][p][mt][3], addr);               \
                }                                                                  \
            _Pragma("unroll")                                                      \
            for (int p = 0; p < 2; ++p)                                            \
                _Pragma("unroll")                                                  \
                for (int np = 0; np < 2; ++np) {                                   \
                    const int r = lane & 7, sel = lane >> 3;                       \
                    const int row = warp_n * 32 + np * 16 + (sel >> 1) * 8 + r;    \
                    const int col = ks * 16 + (sel & 1) * 8;                       \
                    const uint32_t addr = (sb) + (p ? STG_B2 : STG_B1) +           \
                                          (uint32_t)(row * SA_STRIDE + col) * 2;   \
                    LDSM_X4(b[ks][p][2 * np][0], b[ks][p][2 * np][1],              \
                            b[ks][p][2 * np + 1][0], b[ks][p][2 * np + 1][1], addr); \
                }                                                                  \
        }                                                                          \
        _Pragma("unroll")                                                          \
        for (int ks = 0; ks < 2; ++ks)                                             \
            _Pragma("unroll")                                                      \
            for (int mt = 0; mt < 2; ++mt)                                         \
                _Pragma("unroll")                                                  \
                for (int nt = 0; nt < 4; ++nt)                                     \
                    MMA16816(acc[mt][nt], a[ks][0][mt], b[ks][0][nt]);             \
        _Pragma("unroll")                                                          \
        for (int ks = 0; ks < 2; ++ks)                                             \
            _Pragma("unroll")                                                      \
            for (int mt = 0; mt < 2; ++mt)                                         \
                _Pragma("unroll")                                                  \
                for (int nt = 0; nt < 4; ++nt)                                     \
                    MMA16816(acc[mt][nt], a[ks][0][mt], b[ks][1][nt]);             \
        _Pragma("unroll")                                                          \
        for (int ks = 0; ks < 2; ++ks)                                             \
            _Pragma("unroll")                                                      \
            for (int mt = 0; mt < 2; ++mt)                                         \
                _Pragma("unroll")                                                  \
                for (int nt = 0; nt < 4; ++nt)                                     \
                    MMA16816(acc[mt][nt], a[ks][1][mt], b[ks][0][nt]);             \
    } while (0)

__global__ __launch_bounds__(256, 2)
void gemm_mma() {
    extern __shared__ __align__(16) char smem[];
    const uint32_t sbase = smem_to_u32(smem);
    const int tid = threadIdx.x;
    const int lane = tid & 31, wid = tid >> 5;
    const int warp_m = wid >> 1, warp_n = wid & 1;
    const int zi = blockIdx.z;             // batch*KSPLIT + split
    const int bz = zi >> 2, sp = zi & 3;
    const int bm = blockIdx.y * 128, bn = blockIdx.x * 64;
    const int kbase8 = sp * (KCHUNK / 8);
    float* __restrict__ P = gPart[zi];

    const uint4* __restrict__ Ah = reinterpret_cast<const uint4*>(gAh[bz]);
    const uint4* __restrict__ Al = reinterpret_cast<const uint4*>(gAl[bz]);
    const uint4* __restrict__ Bh = reinterpret_cast<const uint4*>(gBh);
    const uint4* __restrict__ Bl = reinterpret_cast<const uint4*>(gBl);

    float acc[2][4][4] = {};

    const int la_row0 = tid >> 2;
    const int la_c4 = tid & 3;

#define LOAD_STAGE(it_)                                                            \
    do {                                                                           \
        const int s_ = (it_) % N_STAGES;                                           \
        const int kc8_ = kbase8 + (it_) * 4;                                       \
        const uint32_t sb_ = sbase + s_ * STAGE_BYTES;                             \
        _Pragma("unroll")                                                          \
        for (int u = 0; u < 2; ++u) {                                              \
            const int row = la_row0 + u * 64;                                      \
            const uint32_t doff = (uint32_t)(row * SA_STRIDE + la_c4 * 8) * 2;     \
            const size_t gi = (size_t)(bm + row) * (DD / 8) + kc8_ + la_c4;        \
            CP_ASYNC16(sb_ + STG_A1 + doff, Ah + gi);                              \
            CP_ASYNC16(sb_ + STG_A2 + doff, Al + gi);                              \
        }                                                                          \
        {                                                                          \
            const uint32_t doff = (uint32_t)(la_row0 * SA_STRIDE + la_c4 * 8) * 2; \
            const size_t gi = (size_t)(bn + la_row0) * (DD / 8) + kc8_ + la_c4;    \
            CP_ASYNC16(sb_ + STG_B1 + doff, Bh + gi);                              \
            CP_ASYNC16(sb_ + STG_B2 + doff, Bl + gi);                              \
        }                                                                          \
        CP_COMMIT();                                                               \
    } while (0)

    LOAD_STAGE(0);
    LOAD_STAGE(1);

    const int NKT = KCHUNK / 32;           // 64
#pragma unroll 1
    for (int it = 0; it < NKT; ++it) {
        if (it + 1 < NKT) CP_WAIT1(); else CP_WAIT0();
        __syncthreads();                   // single barrier per iter
        if (it + 2 < NKT) LOAD_STAGE(it + 2);   // writes slot (it-1)%3: safe
        const uint32_t sb = sbase + (it % N_STAGES) * STAGE_BYTES;
        CONSUME_STAGE(sb);
    }
#undef LOAD_STAGE

    // epilogue: vector stores into ALIGNED partial buffer
#pragma unroll
    for (int mt = 0; mt < 2; ++mt) {
        const int r0 = bm + warp_m * 32 + mt * 16 + (lane >> 2);
#pragma unroll
        for (int nt = 0; nt < 4; ++nt) {
            const int gc = bn + warp_n * 32 + nt * 8 + (lane & 3) * 2;
            *reinterpret_cast<float2*>(P + (size_t)r0 * FF + gc) =
                make_float2(acc[mt][nt][0], acc[mt][nt][1]);
            *reinterpret_cast<float2*>(P + (size_t)(r0 + 8) * FF + gc) =
                make_float2(acc[mt][nt][2], acc[mt][nt][3]);
        }
    }
}

// ---------------------------------------------------------------------------
// Split-K reduce: feats = sum of KSPLIT partials; also emit f16 hi/lo planes.
// ---------------------------------------------------------------------------
__global__ __launch_bounds__(256)
void reduceK(float* __restrict__ o0, float* __restrict__ o1) {
    const int i2 = blockIdx.x * 256 + threadIdx.x;   // pair index
    const int b = blockIdx.y;
    const int i = i2 * 2;
    float* __restrict__ o = b ? o1 : o0;
    float s0 = 0.0f, s1 = 0.0f;
#pragma unroll
    for (int s = 0; s < KSPLIT; ++s) {
        s0 += gPart[KSPLIT * b + s][i];
        s1 += gPart[KSPLIT * b + s][i + 1];
    }
    o[i] = s0; o[i + 1] = s1;
    __half2 h = __floats2half2_rn(s0, s1);
    float2 hf = __half22float2(h);
    __half2 l = __floats2half2_rn(s0 - hf.x, s1 - hf.y);
    *reinterpret_cast<__half2*>(&gFh[b][i]) = h;
    *reinterpret_cast<__half2*>(&gFl[b][i]) = l;
}

// ---------------------------------------------------------------------------
// Split-FP16 HMMA logits GEMM: logits[b] = feats[b] @ W_fc + b_fc
// M=1024, N=NPAD(384, mask to 345), K=512. Same tile scheme, NKT=16.
// grid = (6, 8, 2). Output: scalar stores, row stride 345.
// ---------------------------------------------------------------------------
__global__ __launch_bounds__(256, 2)
void gemm_logits(float* __restrict__ C0, float* __restrict__ C1,
                 const float* __restrict__ bias) {
    extern __shared__ __align__(16) char smem[];
    const uint32_t sbase = smem_to_u32(smem);
    const int tid = threadIdx.x;
    const int lane = tid & 31, wid = tid >> 5;
    const int warp_m = wid >> 1, warp_n = wid & 1;
    const int bz = blockIdx.z;
    const int bm = blockIdx.y * 128, bn = blockIdx.x * 64;
    float* __restrict__ C = bz ? C1 : C0;

    const uint4* __restrict__ Ah = reinterpret_cast<const uint4*>(gFh[bz]);
    const uint4* __restrict__ Al = reinterpret_cast<const uint4*>(gFl[bz]);
    const uint4* __restrict__ Bh = reinterpret_cast<const uint4*>(gWfh);
    const uint4* __restrict__ Bl = reinterpret_cast<const uint4*>(gWfl);

    float acc[2][4][4] = {};

    const int la_row0 = tid >> 2;
    const int la_c4 = tid & 3;

#define LOAD_STAGE_L(it_)                                                          \
    do {                                                                           \
        const int s_ = (it_) % N_STAGES;                                           \
        const int kc8_ = (it_) * 4;                                                \
        const uint32_t sb_ = sbase + s_ * STAGE_BYTES;                             \
        _Pragma("unroll")                                                          \
        for (int u = 0; u < 2; ++u) {                                              \
            const int row = la_row0 + u * 64;                                      \
            const uint32_t doff = (uint32_t)(row * SA_STRIDE + la_c4 * 8) * 2;     \
            const size_t gi = (size_t)(bm + row) * (FF / 8) + kc8_ + la_c4;        \
            CP_ASYNC16(sb_ + STG_A1 + doff, Ah + gi);                              \
            CP_ASYNC16(sb_ + STG_A2 + doff, Al + gi);                              \
        }                                                                          \
        {                                                                          \
            const uint32_t doff = (uint32_t)(la_row0 * SA_STRIDE + la_c4 * 8) * 2; \
            const size_t gi = (size_t)(bn + la_row0) * (FF / 8) + kc8_ + la_c4;    \
            CP_ASYNC16(sb_ + STG_B1 + doff, Bh + gi);                              \
            CP_ASYNC16(sb_ + STG_B2 + doff, Bl + gi);                              \
        }                                                                          \
        CP_COMMIT();                                                               \
    } while (0)

    LOAD_STAGE_L(0);
    LOAD_STAGE_L(1);

    const int NKT = FF / 32;               // 16
#pragma unroll 1
    for (int it = 0; it < NKT; ++it) {
        if (it + 1 < NKT) CP_WAIT1(); else CP_WAIT0();
        __syncthreads();
        if (it + 2 < NKT) LOAD_STAGE_L(it + 2);
        const uint32_t sb = sbase + (it % N_STAGES) * STAGE_BYTES;
        CONSUME_STAGE(sb);
    }
#undef LOAD_STAGE_L

    // epilogue: scalar stores into [1024 x 345] with bias, mask n >= CC
#pragma unroll
    for (int mt = 0; mt < 2; ++mt) {
        const int r0 = bm + warp_m * 32 + mt * 16 + (lane >> 2);
#pragma unroll
        for (int nt = 0; nt < 4; ++nt) {
            const int gc = bn + warp_n * 32 + nt * 8 + (lane & 3) * 2;
            if (gc < CC) {
                C[(size_t)r0 * CC + gc] = acc[mt][nt][0] + bias[gc];
                C[(size_t)(r0 + 8) * CC + gc] = acc[mt][nt][2] + bias[gc];
            }
            if (gc + 1 < CC) {
                C[(size_t)r0 * CC + gc + 1] = acc[mt][nt][1] + bias[gc + 1];
                C[(size_t)(r0 + 8) * CC + gc + 1] = acc[mt][nt][3] + bias[gc + 1];
            }
        }
    }
}

// ---------------------------------------------------------------------------
// fp32 tiled GEMM (prot_scores only) — all scalar accesses
// ---------------------------------------------------------------------------
__global__ __launch_bounds__(256)
void gemm64(const float* __restrict__ A0,
            const float* __restrict__ Bmat, const float* __restrict__ bias,
            float* __restrict__ C0, int M, int N, int K)
{
    const float* __restrict__ A = A0;
    float* __restrict__ C = C0;
    __shared__ float As[16][64 + 1];
    __shared__ float Bs[16][64];
    const int tid = threadIdx.x;
    const int tx = tid & 15, ty = tid >> 4;
    const int bm = blockIdx.y * 64, bn = blockIdx.x * 64;
    float acc[4][4] = {};
    for (int k0 = 0; k0 < K; k0 += 16) {
        {
            const int acol = tid & 15, arow0 = tid >> 4;
#pragma unroll
            for (int j = 0; j < 4; ++j) {
                const int arow = arow0 + j * 16, gr = bm + arow;
                As[acol][arow] = (gr < M) ? A[(size_t)gr * K + (k0 + acol)] : 0.0f;
            }
        }
        {
            const int brow = tid >> 4, bcol0 = tid & 15;
#pragma unroll
            for (int j = 0; j < 4; ++j) {
                const int bcol = bcol0 + j * 16, gc = bn + bcol;
                Bs[brow][bcol] = (gc < N) ? Bmat[(size_t)(k0 + brow) * N + gc] : 0.0f;
            }
        }
        __syncthreads();
#pragma unroll
        for (int kk = 0; kk < 16; ++kk) {
            float a[4], b[4];
#pragma unroll
            for (int i = 0; i < 4; ++i) a[i] = As[kk][ty * 4 + i];
#pragma unroll
            for (int j = 0; j < 4; ++j) b[j] = Bs[kk][tx * 4 + j];
#pragma unroll
            for (int i = 0; i < 4; ++i)
#pragma unroll
                for (int j = 0; j < 4; ++j) acc[i][j] = fmaf(a[i], b[j], acc[i][j]);
        }
        __syncthreads();
    }
#pragma unroll
    for (int i = 0; i < 4; ++i) {
        const int rr = bm + ty * 4 + i;
        if (rr >= M) continue;
#pragma unroll
        for (int j = 0; j < 4; ++j) {
            const int cidx = bn + tx * 4 + j;
            if (cidx < N) {
                float v = acc[i][j];
                if (bias) v += bias[cidx];
                C[(size_t)rr * N + cidx] = v;
            }
        }
    }
}

// ---------------------------------------------------------------------------
// Masked argmax -> labels (first index on ties)
// ---------------------------------------------------------------------------
__global__ void argmax_kernel(const float* __restrict__ logits,
                              const float* __restrict__ Y,
                              float* __restrict__ labels_f)
{
    const int row = blockIdx.x * 8 + threadIdx.y;
    const int lane = threadIdx.x;
    if (row >= BB) return;
    float best = -FLT_MAX; int bidx = 0x7fffffff;
    for (int c = lane; c < CC; c += 32) {
        if (Y[(size_t)row * CC + c] != 0.0f) {
            const float v = logits[(size_t)row * CC + c];
            if (v > best || (v == best && c < bidx)) { best = v; bidx = c; }
        }
    }
#pragma unroll
    for (int o = 16; o > 0; o >>= 1) {
        const float ov = __shfl_down_sync(0xffffffffu, best, o);
        const int   oi = __shfl_down_sync(0xffffffffu, bidx, o);
        if (ov > best || (ov == best && oi < bidx)) { best = ov; bidx = oi; }
    }
    if (lane == 0) { g_labels[row] = bidx; labels_f[row] = (float)bidx; }
}

// ---------------------------------------------------------------------------
// One-block prep: class-parallel counting scan. 1024 threads.
// ---------------------------------------------------------------------------
__global__ __launch_bounds__(1024)
void prep_kernel() {
    __shared__ int s_lab[BB];
    __shared__ int s_tot[CC];
    __shared__ int s_start[CC];
    const int tid = threadIdx.x;
    s_lab[tid] = g_labels[tid];
    __syncthreads();

    if (tid < CC) {
        int cnt = 0;
        for (int j = 0; j < BB; ++j) cnt += (s_lab[j] == tid);
        s_tot[tid] = cnt;
    }
    __syncthreads();
    if (tid == 0) {
        int acc = 0;
        for (int c = 0; c < CC; ++c) { s_start[c] = acc; acc += s_tot[c]; }
    }
    __syncthreads();

    if (tid < CC) {
        const int n = s_tot[tid];
        const int st = s_start[tid];
        int k = 0;
        for (int j = 0; j < BB; ++j) {
            if (s_lab[j] == tid) {
                g_idx[st + k] = j;
                g_coefs[st + k] = (1.0f - PROTO_W_F) * __powf(PROTO_W_F, (float)(n - 1 - k));
                ++k;
            }
        }
        g_scale[tid] = __powf(PROTO_W_F, (float)n);
        g_start[tid] = st;
        g_n[tid]     = n;
    }
}

// ---------------------------------------------------------------------------
// Prototype EMA + normalize (one block per class, 512 threads = FF)
// ---------------------------------------------------------------------------
__global__ __launch_bounds__(512)
void proto_kernel(const float* __restrict__ feats,
                  const float* __restrict__ proto,
                  float* __restrict__ new_proto)
{
    const int c = blockIdx.x;
    __shared__ float s_red[512];
    __shared__ float s_norm;
    const int tid = threadIdx.x;
    const int n = g_n[c], st = g_start[c];
    float acc = g_scale[c] * proto[(size_t)c * FF + tid];
    for (int k = 0; k < n; ++k)
        acc = fmaf(g_coefs[st + k], feats[(size_t)g_idx[st + k] * FF + tid], acc);
    s_red[tid] = acc * acc;
    __syncthreads();
#pragma unroll
    for (int s = 256; s > 0; s >>= 1) {
        if (tid < s) s_red[tid] += s_red[tid + s];
        __syncthreads();
    }
    if (tid == 0) s_norm = sqrtf(s_red[0]);
    __syncthreads();
    new_proto[(size_t)c * FF + tid] = acc / s_norm;
}

// ---------------------------------------------------------------------------
extern "C" void kernel_launch(void* const* d_in, const int* in_sizes, int n_in,
                              void* d_out, int out_size)
{
    const float* img_q     = (const float*)d_in[0];
    const float* img_q1    = (const float*)d_in[1];
    const float* partial_Y = (const float*)d_in[2];
    const float* W_enc     = (const float*)d_in[3];
    const float* W_fc      = (const float*)d_in[4];
    const float* b_fc      = (const float*)d_in[5];
    const float* proto     = (const float*)d_in[6];

    float* out = (float*)d_out;
    float* o_logits_q  = out + OFF_LOGITS_Q;
    float* o_logits_q1 = out + OFF_LOGITS_Q1;
    float* o_new_proto = out + OFF_NEW_PROTO;
    float* o_prot      = out + OFF_PROT;
    float* o_labels    = out + OFF_LABELS;
    float* o_feats_q   = out + OFF_FEATS_Q;
    float* o_feats_q1  = out + OFF_FEATS_Q1;

    cudaFuncSetAttribute(gemm_mma, cudaFuncAttributeMaxDynamicSharedMemorySize, GEMM_SMEM);
    cudaFuncSetAttribute(gemm_logits, cudaFuncAttributeMaxDynamicSharedMemorySize, GEMM_SMEM);

    // 0) split inputs into f16 hi/lo planes (W fused with transpose)
    {
        dim3 blk(32, 8);
        splitW<<<dim3(FF / 32, DD / 32), blk>>>(W_enc);
        splitWfc<<<dim3(NPAD / 32, FF / 32), blk>>>(W_fc);
    }
    {
        void* pAh; void* pAl;
        cudaGetSymbolAddress(&pAh, gAh);
        cudaGetSymbolAddress(&pAl, gAl);
        const int nF4 = BB * DD / 4;
        splitA<<<(nF4 + 255) / 256, 256>>>((const float4*)img_q,
                                           (uint2*)pAh, (uint2*)pAl, nF4);
        splitA<<<(nF4 + 255) / 256, 256>>>((const float4*)img_q1,
                                           (uint2*)((__half*)pAh + (size_t)BB * DD),
                                           (uint2*)((__half*)pAl + (size_t)BB * DD), nF4);
    }

    // 1) feats = img @ W_enc via split-fp16 HMMA, split-K=4 -> partials -> reduce
    {
        dim3 grid(FF / 64, BB / 128, 2 * KSPLIT);   // 8 x 8 x 8 = 512 CTAs
        gemm_mma<<<grid, 256, GEMM_SMEM>>>();
        dim3 rgrid(BB * FF / 512, 2);
        reduceK<<<rgrid, 256>>>(o_feats_q, o_feats_q1);
    }
    // 2) logits = feats @ W_fc + b via split-fp16 HMMA
    {
        dim3 grid(NPAD / 64, BB / 128, 2);          // 6 x 8 x 2 = 96 CTAs
        gemm_logits<<<grid, 256, GEMM_SMEM>>>(o_logits_q, o_logits_q1, b_fc);
    }
    // 3) masked argmax -> labels
    {
        dim3 blk(32, 8);
        argmax_kernel<<<BB / 8, blk>>>(o_logits_q, partial_Y, o_labels);
    }
    // 4) prep + prototype EMA + normalize
    prep_kernel<<<1, 1024>>>();
    proto_kernel<<<CC, 512>>>(o_feats_q, proto, o_new_proto);

    // 5) prot_scores = new_proto @ W_fc + b (fp32, small)
    {
        dim3 grid((CC + 63) / 64, (CC + 63) / 64, 1);
        gemm64<<<grid, 256>>>(o_new_proto, W_fc, b_fc, o_prot, CC, CC, FF);
    }
}

// round 13
// speedup vs baseline: 2.8201x; 1.0191x over previous
#include <cuda_runtime.h>
#include <cuda_fp16.h>
#include <cstdint>
#include <float.h>

// Problem constants
#define BB 1024
#define DD 8192
#define CC 345
#define FF 512
#define NPAD 384                      // padded class dim for HMMA logits
#define PROTO_W_F 0.99f

// Output layout (flattened, return-tuple order, float32)
#define OFF_LOGITS_Q   0
#define OFF_LOGITS_Q1  353280
#define OFF_NEW_PROTO  706560
#define OFF_PROT       883200
#define OFF_LABELS     1002225
#define OFF_FEATS_Q    1003249
#define OFF_FEATS_Q1   1527537
// NOTE: OFF_FEATS_Q / OFF_FEATS_Q1 are ODD element offsets -> those output
// pointers are only 4-byte aligned. All accesses to them MUST be scalar.

#define KSPLIT 4
#define KCHUNK (DD / KSPLIT)               // 2048

// ---------------------------------------------------------------------------
// Device scratch (static: allocation-free per harness rules)
// ---------------------------------------------------------------------------
__device__ __half gAh[2][BB * DD];   // f16 hi planes of img_q / img_q1 [row][k]
__device__ __half gAl[2][BB * DD];   // f16 lo planes
__device__ __half gBh[FF * DD];      // f16 hi plane of W_enc^T  [n][k]
__device__ __half gBl[FF * DD];      // f16 lo plane
__device__ float gPart[2 * KSPLIT][BB * FF];  // split-K partials
__device__ __half gFh[2][BB * FF];   // f16 hi planes of feats (for logits HMMA)
__device__ __half gFl[2][BB * FF];   // f16 lo planes
__device__ __half gWfh[NPAD * FF];   // f16 hi plane of W_fc^T [n][k], zero-padded
__device__ __half gWfl[NPAD * FF];   // f16 lo plane

__device__ int   g_labels[BB];
__device__ int   g_idx[BB];
__device__ float g_coefs[BB];
__device__ float g_scale[CC];
__device__ int   g_start[CC];
__device__ int   g_n[CC];

// ---------------------------------------------------------------------------
// PTX helpers (plain sm_103-compatible: cp.async + ldmatrix + mma.sync)
// ---------------------------------------------------------------------------
__device__ __forceinline__ uint32_t smem_to_u32(const void* p) {
    uint32_t a;
    asm("{ .reg .u64 t; cvta.to.shared.u64 t, %1; cvt.u32.u64 %0, t; }" : "=r"(a) : "l"(p));
    return a;
}
#define CP_ASYNC16(dst, src) \
    asm volatile("cp.async.cg.shared.global [%0], [%1], 16;" :: "r"(dst), "l"(src) : "memory")
#define CP_COMMIT()  asm volatile("cp.async.commit_group;" ::: "memory")
#define CP_WAIT1()   asm volatile("cp.async.wait_group 1;" ::: "memory")
#define CP_WAIT0()   asm volatile("cp.async.wait_group 0;" ::: "memory")
#define LDSM_X4(r0, r1, r2, r3, addr) \
    asm volatile("ldmatrix.sync.aligned.m8n8.x4.shared.b16 {%0,%1,%2,%3}, [%4];" \
                 : "=r"(r0), "=r"(r1), "=r"(r2), "=r"(r3) : "r"(addr))
// fp32-accumulate HMMA (main product)
#define MMA16816(d, a, b) \
    asm volatile("mma.sync.aligned.m16n8k16.row.col.f32.f16.f16.f32 " \
                 "{%0,%1,%2,%3}, {%4,%5,%6,%7}, {%8,%9}, {%0,%1,%2,%3};" \
                 : "+f"((d)[0]), "+f"((d)[1]), "+f"((d)[2]), "+f"((d)[3]) \
                 : "r"((a)[0]), "r"((a)[1]), "r"((a)[2]), "r"((a)[3]), \
                   "r"((b)[0]), "r"((b)[1]))
// fp16-accumulate HMMA (correction products; potentially double-rate)
#define MMA16816H(d, a, b) \
    asm volatile("mma.sync.aligned.m16n8k16.row.col.f16.f16.f16.f16 " \
                 "{%0,%1}, {%2,%3,%4,%5}, {%6,%7}, {%0,%1};" \
                 : "+r"((d)[0]), "+r"((d)[1]) \
                 : "r"((a)[0]), "r"((a)[1]), "r"((a)[2]), "r"((a)[3]), \
                   "r"((b)[0]), "r"((b)[1]))

// ---------------------------------------------------------------------------
// Fused transpose+split: W_enc [DD x FF] fp32 -> gBh/gBl [FF x DD] f16 planes
// ---------------------------------------------------------------------------
__global__ void splitW(const float* __restrict__ W) {
    __shared__ float t[32][33];
    const int n0 = blockIdx.x * 32, k0 = blockIdx.y * 32;
    const int tx = threadIdx.x, ty = threadIdx.y;
#pragma unroll
    for (int j = 0; j < 4; ++j)
        t[ty + 8 * j][tx] = W[(size_t)(k0 + ty + 8 * j) * FF + n0 + tx];
    __syncthreads();
#pragma unroll
    for (int j = 0; j < 4; ++j) {
        const float v = t[tx][ty + 8 * j];
        const int n = n0 + ty + 8 * j, k = k0 + tx;
        const __half h = __float2half_rn(v);
        gBh[(size_t)n * DD + k] = h;
        gBl[(size_t)n * DD + k] = __float2half_rn(v - __half2float(h));
    }
}

// ---------------------------------------------------------------------------
// Transpose+split W_fc [FF x CC] fp32 -> gWfh/gWfl [NPAD x FF], zero padding
// ---------------------------------------------------------------------------
__global__ void splitWfc(const float* __restrict__ W) {
    __shared__ float t[32][33];
    const int n0 = blockIdx.x * 32, k0 = blockIdx.y * 32;
    const int tx = threadIdx.x, ty = threadIdx.y;
#pragma unroll
    for (int j = 0; j < 4; ++j) {
        const int nn = n0 + tx, kk = k0 + ty + 8 * j;
        t[ty + 8 * j][tx] = (nn < CC) ? W[(size_t)kk * CC + nn] : 0.0f;
    }
    __syncthreads();
#pragma unroll
    for (int j = 0; j < 4; ++j) {
        const float v = t[tx][ty + 8 * j];
        const int n = n0 + ty + 8 * j, k = k0 + tx;
        const __half h = __float2half_rn(v);
        gWfh[(size_t)n * FF + k] = h;
        gWfl[(size_t)n * FF + k] = __float2half_rn(v - __half2float(h));
    }
}

// ---------------------------------------------------------------------------
// fp32 -> (f16 hi, f16 lo) planes, vectorized
// ---------------------------------------------------------------------------
__global__ __launch_bounds__(256)
void splitA(const float4* __restrict__ src, uint2* __restrict__ hi,
            uint2* __restrict__ lo, int nF4) {
    const int i = blockIdx.x * 256 + threadIdx.x;
    if (i >= nF4) return;
    float4 v = src[i];
    __half2 h01 = __floats2half2_rn(v.x, v.y);
    __half2 h23 = __floats2half2_rn(v.z, v.w);
    float2 f01 = __half22float2(h01);
    float2 f23 = __half22float2(h23);
    __half2 l01 = __floats2half2_rn(v.x - f01.x, v.y - f01.y);
    __half2 l23 = __floats2half2_rn(v.z - f23.x, v.w - f23.y);
    uint2 hw, lw;
    hw.x = *reinterpret_cast<uint32_t*>(&h01); hw.y = *reinterpret_cast<uint32_t*>(&h23);
    lw.x = *reinterpret_cast<uint32_t*>(&l01); lw.y = *reinterpret_cast<uint32_t*>(&l23);
    hi[i] = hw; lo[i] = lw;
}

// ---------------------------------------------------------------------------
// Split-FP16 HMMA GEMM, split-K. BM=128, BN=64, BK=32, 256 threads.
// Main product fp32-accum; corrections fp16-accum (rate experiment).
// 3-stage cp.async pipeline, ONE barrier per k-iter.
// ---------------------------------------------------------------------------
#define SA_STRIDE 40
#define STG_A1 0
#define STG_A2 10240
#define STG_B1 20480
#define STG_B2 25600
#define STAGE_BYTES 30720
#define N_STAGES 3
#define GEMM_SMEM (N_STAGES * STAGE_BYTES)

// Consume one 32-K stage. Uses: acc (fp32[2][4][4]), ac1/ac2 (u32[2][4][2]).
#define CONSUME_STAGE(sb)                                                          \
    do {                                                                           \
        _Pragma("unroll")                                                          \
        for (int ks = 0; ks < 2; ++ks) {                                           \
            uint32_t a[2][2][4];   /* [plane][mtile] */                            \
            uint32_t b[2][4][2];   /* [plane][ntile] */                            \
            _Pragma("unroll")                                                      \
            for (int p = 0; p < 2; ++p)                                            \
                _Pragma("unroll")                                                  \
                for (int mt = 0; mt < 2; ++mt) {                                   \
                    const int row = warp_m * 32 + mt * 16 + (lane & 15);           \
                    const int col = ks * 16 + (lane >> 4) * 8;                     \
                    const uint32_t addr = (sb) + (p ? STG_A2 : STG_A1) +           \
                                          (uint32_t)(row * SA_STRIDE + col) * 2;   \
                    LDSM_X4(a[p][mt][0], a[p][mt][1], a[p][mt][2], a[p][mt][3], addr); \
                }                                                                  \
            _Pragma("unroll")                                                      \
            for (int p = 0; p < 2; ++p)                                            \
                _Pragma("unroll")                                                  \
                for (int np = 0; np < 2; ++np) {                                   \
                    const int r = lane & 7, sel = lane >> 3;                       \
                    const int row = warp_n * 32 + np * 16 + (sel >> 1) * 8 + r;    \
                    const int col = ks * 16 + (sel & 1) * 8;                       \
                    const uint32_t addr = (sb) + (p ? STG_B2 : STG_B1) +           \
                                          (uint32_t)(row * SA_STRIDE + col) * 2;   \
                    LDSM_X4(b[p][2 * np][0], b[p][2 * np][1],                      \
                            b[p][2 * np + 1][0], b[p][2 * np + 1][1], addr);       \
                }                                                                  \
            /* main: A1*B1 fp32-accum */                                           \
            _Pragma("unroll")                                                      \
            for (int mt = 0; mt < 2; ++mt)                                         \
                _Pragma("unroll")                                                  \
                for (int nt = 0; nt < 4; ++nt)                                     \
                    MMA16816(acc[mt][nt], a[0][mt], b[0][nt]);                     \
            /* corrections: A1*B2, A2*B1 fp16-accum */                             \
            _Pragma("unroll")                                                      \
            for (int mt = 0; mt < 2; ++mt)                                         \
                _Pragma("unroll")                                                  \
                for (int nt = 0; nt < 4; ++nt)                                     \
                    MMA16816H(ac1[mt][nt], a[0][mt], b[1][nt]);                    \
            _Pragma("unroll")                                                      \
            for (int mt = 0; mt < 2; ++mt)                                         \
                _Pragma("unroll")                                                  \
                for (int nt = 0; nt < 4; ++nt)                                     \
                    MMA16816H(ac2[mt][nt], a[1][mt], b[0][nt]);                    \
        }                                                                          \
    } while (0)

__global__ __launch_bounds__(256, 2)
void gemm_mma() {
    extern __shared__ __align__(16) char smem[];
    const uint32_t sbase = smem_to_u32(smem);
    const int tid = threadIdx.x;
    const int lane = tid & 31, wid = tid >> 5;
    const int warp_m = wid >> 1, warp_n = wid & 1;
    const int zi = blockIdx.z;             // batch*KSPLIT + split
    const int bz = zi >> 2, sp = zi & 3;
    const int bm = blockIdx.y * 128, bn = blockIdx.x * 64;
    const int kbase8 = sp * (KCHUNK / 8);
    float* __restrict__ P = gPart[zi];

    const uint4* __restrict__ Ah = reinterpret_cast<const uint4*>(gAh[bz]);
    const uint4* __restrict__ Al = reinterpret_cast<const uint4*>(gAl[bz]);
    const uint4* __restrict__ Bh = reinterpret_cast<const uint4*>(gBh);
    const uint4* __restrict__ Bl = reinterpret_cast<const uint4*>(gBl);

    float acc[2][4][4] = {};
    uint32_t ac1[2][4][2] = {};
    uint32_t ac2[2][4][2] = {};

    const int la_row0 = tid >> 2;
    const int la_c4 = tid & 3;

#define LOAD_STAGE(it_)                                                            \
    do {                                                                           \
        const int s_ = (it_) % N_STAGES;                                           \
        const int kc8_ = kbase8 + (it_) * 4;                                       \
        const uint32_t sb_ = sbase + s_ * STAGE_BYTES;                             \
        _Pragma("unroll")                                                          \
        for (int u = 0; u < 2; ++u) {                                              \
            const int row = la_row0 + u * 64;                                      \
            const uint32_t doff = (uint32_t)(row * SA_STRIDE + la_c4 * 8) * 2;     \
            const size_t gi = (size_t)(bm + row) * (DD / 8) + kc8_ + la_c4;        \
            CP_ASYNC16(sb_ + STG_A1 + doff, Ah + gi);                              \
            CP_ASYNC16(sb_ + STG_A2 + doff, Al + gi);                              \
        }                                                                          \
        {                                                                          \
            const uint32_t doff = (uint32_t)(la_row0 * SA_STRIDE + la_c4 * 8) * 2; \
            const size_t gi = (size_t)(bn + la_row0) * (DD / 8) + kc8_ + la_c4;    \
            CP_ASYNC16(sb_ + STG_B1 + doff, Bh + gi);                              \
            CP_ASYNC16(sb_ + STG_B2 + doff, Bl + gi);                              \
        }                                                                          \
        CP_COMMIT();                                                               \
    } while (0)

    LOAD_STAGE(0);
    LOAD_STAGE(1);

    const int NKT = KCHUNK / 32;           // 64
#pragma unroll 1
    for (int it = 0; it < NKT; ++it) {
        if (it + 1 < NKT) CP_WAIT1(); else CP_WAIT0();
        __syncthreads();
        if (it + 2 < NKT) LOAD_STAGE(it + 2);
        const uint32_t sb = sbase + (it % N_STAGES) * STAGE_BYTES;
        CONSUME_STAGE(sb);
    }
#undef LOAD_STAGE

    // epilogue: fold fp16 correction accs into fp32, vector stores (aligned buf)
#pragma unroll
    for (int mt = 0; mt < 2; ++mt) {
        const int r0 = bm + warp_m * 32 + mt * 16 + (lane >> 2);
#pragma unroll
        for (int nt = 0; nt < 4; ++nt) {
            const float2 c1lo = __half22float2(*reinterpret_cast<__half2*>(&ac1[mt][nt][0]));
            const float2 c1hi = __half22float2(*reinterpret_cast<__half2*>(&ac1[mt][nt][1]));
            const float2 c2lo = __half22float2(*reinterpret_cast<__half2*>(&ac2[mt][nt][0]));
            const float2 c2hi = __half22float2(*reinterpret_cast<__half2*>(&ac2[mt][nt][1]));
            const int gc = bn + warp_n * 32 + nt * 8 + (lane & 3) * 2;
            *reinterpret_cast<float2*>(P + (size_t)r0 * FF + gc) =
                make_float2(acc[mt][nt][0] + c1lo.x + c2lo.x,
                            acc[mt][nt][1] + c1lo.y + c2lo.y);
            *reinterpret_cast<float2*>(P + (size_t)(r0 + 8) * FF + gc) =
                make_float2(acc[mt][nt][2] + c1hi.x + c2hi.x,
                            acc[mt][nt][3] + c1hi.y + c2hi.y);
        }
    }
}

// ---------------------------------------------------------------------------
// Split-K reduce: feats = sum of KSPLIT partials; also emit f16 hi/lo planes.
// ---------------------------------------------------------------------------
__global__ __launch_bounds__(256)
void reduceK(float* __restrict__ o0, float* __restrict__ o1) {
    const int i2 = blockIdx.x * 256 + threadIdx.x;
    const int b = blockIdx.y;
    const int i = i2 * 2;
    float* __restrict__ o = b ? o1 : o0;
    float s0 = 0.0f, s1 = 0.0f;
#pragma unroll
    for (int s = 0; s < KSPLIT; ++s) {
        s0 += gPart[KSPLIT * b + s][i];
        s1 += gPart[KSPLIT * b + s][i + 1];
    }
    o[i] = s0; o[i + 1] = s1;
    __half2 h = __floats2half2_rn(s0, s1);
    float2 hf = __half22float2(h);
    __half2 l = __floats2half2_rn(s0 - hf.x, s1 - hf.y);
    *reinterpret_cast<__half2*>(&gFh[b][i]) = h;
    *reinterpret_cast<__half2*>(&gFl[b][i]) = l;
}

// ---------------------------------------------------------------------------
// Split-FP16 HMMA logits GEMM: logits[b] = feats[b] @ W_fc + b_fc
// ---------------------------------------------------------------------------
__global__ __launch_bounds__(256, 2)
void gemm_logits(float* __restrict__ C0, float* __restrict__ C1,
                 const float* __restrict__ bias) {
    extern __shared__ __align__(16) char smem[];
    const uint32_t sbase = smem_to_u32(smem);
    const int tid = threadIdx.x;
    const int lane = tid & 31, wid = tid >> 5;
    const int warp_m = wid >> 1, warp_n = wid & 1;
    const int bz = blockIdx.z;
    const int bm = blockIdx.y * 128, bn = blockIdx.x * 64;
    float* __restrict__ C = bz ? C1 : C0;

    const uint4* __restrict__ Ah = reinterpret_cast<const uint4*>(gFh[bz]);
    const uint4* __restrict__ Al = reinterpret_cast<const uint4*>(gFl[bz]);
    const uint4* __restrict__ Bh = reinterpret_cast<const uint4*>(gWfh);
    const uint4* __restrict__ Bl = reinterpret_cast<const uint4*>(gWfl);

    float acc[2][4][4] = {};
    uint32_t ac1[2][4][2] = {};
    uint32_t ac2[2][4][2] = {};

    const int la_row0 = tid >> 2;
    const int la_c4 = tid & 3;

#define LOAD_STAGE_L(it_)                                                          \
    do {                                                                           \
        const int s_ = (it_) % N_STAGES;                                           \
        const int kc8_ = (it_) * 4;                                                \
        const uint32_t sb_ = sbase + s_ * STAGE_BYTES;                             \
        _Pragma("unroll")                                                          \
        for (int u = 0; u < 2; ++u) {                                              \
            const int row = la_row0 + u * 64;                                      \
            const uint32_t doff = (uint32_t)(row * SA_STRIDE + la_c4 * 8) * 2;     \
            const size_t gi = (size_t)(bm + row) * (FF / 8) + kc8_ + la_c4;        \
            CP_ASYNC16(sb_ + STG_A1 + doff, Ah + gi);                              \
            CP_ASYNC16(sb_ + STG_A2 + doff, Al + gi);                              \
        }                                                                          \
        {                                                                          \
            const uint32_t doff = (uint32_t)(la_row0 * SA_STRIDE + la_c4 * 8) * 2; \
            const size_t gi = (size_t)(bn + la_row0) * (FF / 8) + kc8_ + la_c4;    \
            CP_ASYNC16(sb_ + STG_B1 + doff, Bh + gi);                              \
            CP_ASYNC16(sb_ + STG_B2 + doff, Bl + gi);                              \
        }                                                                          \
        CP_COMMIT();                                                               \
    } while (0)

    LOAD_STAGE_L(0);
    LOAD_STAGE_L(1);

    const int NKT = FF / 32;               // 16
#pragma unroll 1
    for (int it = 0; it < NKT; ++it) {
        if (it + 1 < NKT) CP_WAIT1(); else CP_WAIT0();
        __syncthreads();
        if (it + 2 < NKT) LOAD_STAGE_L(it + 2);
        const uint32_t sb = sbase + (it % N_STAGES) * STAGE_BYTES;
        CONSUME_STAGE(sb);
    }
#undef LOAD_STAGE_L

    // epilogue: fold corrections, scalar stores into [1024 x 345], mask n >= CC
#pragma unroll
    for (int mt = 0; mt < 2; ++mt) {
        const int r0 = bm + warp_m * 32 + mt * 16 + (lane >> 2);
#pragma unroll
        for (int nt = 0; nt < 4; ++nt) {
            const float2 c1lo = __half22float2(*reinterpret_cast<__half2*>(&ac1[mt][nt][0]));
            const float2 c1hi = __half22float2(*reinterpret_cast<__half2*>(&ac1[mt][nt][1]));
            const float2 c2lo = __half22float2(*reinterpret_cast<__half2*>(&ac2[mt][nt][0]));
            const float2 c2hi = __half22float2(*reinterpret_cast<__half2*>(&ac2[mt][nt][1]));
            const int gc = bn + warp_n * 32 + nt * 8 + (lane & 3) * 2;
            if (gc < CC) {
                C[(size_t)r0 * CC + gc] = acc[mt][nt][0] + c1lo.x + c2lo.x + bias[gc];
                C[(size_t)(r0 + 8) * CC + gc] = acc[mt][nt][2] + c1hi.x + c2hi.x + bias[gc];
            }
            if (gc + 1 < CC) {
                C[(size_t)r0 * CC + gc + 1] = acc[mt][nt][1] + c1lo.y + c2lo.y + bias[gc + 1];
                C[(size_t)(r0 + 8) * CC + gc + 1] = acc[mt][nt][3] + c1hi.y + c2hi.y + bias[gc + 1];
            }
        }
    }
}

// ---------------------------------------------------------------------------
// fp32 tiled GEMM (prot_scores only)
// ---------------------------------------------------------------------------
__global__ __launch_bounds__(256)
void gemm64(const float* __restrict__ A0,
            const float* __restrict__ Bmat, const float* __restrict__ bias,
            float* __restrict__ C0, int M, int N, int K)
{
    const float* __restrict__ A = A0;
    float* __restrict__ C = C0;
    __shared__ float As[16][64 + 1];
    __shared__ float Bs[16][64];
    const int tid = threadIdx.x;
    const int tx = tid & 15, ty = tid >> 4;
    const int bm = blockIdx.y * 64, bn = blockIdx.x * 64;
    float acc[4][4] = {};
    for (int k0 = 0; k0 < K; k0 += 16) {
        {
            const int acol = tid & 15, arow0 = tid >> 4;
#pragma unroll
            for (int j = 0; j < 4; ++j) {
                const int arow = arow0 + j * 16, gr = bm + arow;
                As[acol][arow] = (gr < M) ? A[(size_t)gr * K + (k0 + acol)] : 0.0f;
            }
        }
        {
            const int brow = tid >> 4, bcol0 = tid & 15;
#pragma unroll
            for (int j = 0; j < 4; ++j) {
                const int bcol = bcol0 + j * 16, gc = bn + bcol;
                Bs[brow][bcol] = (gc < N) ? Bmat[(size_t)(k0 + brow) * N + gc] : 0.0f;
            }
        }
        __syncthreads();
#pragma unroll
        for (int kk = 0; kk < 16; ++kk) {
            float a[4], b[4];
#pragma unroll
            for (int i = 0; i < 4; ++i) a[i] = As[kk][ty * 4 + i];
#pragma unroll
            for (int j = 0; j < 4; ++j) b[j] = Bs[kk][tx * 4 + j];
#pragma unroll
            for (int i = 0; i < 4; ++i)
#pragma unroll
                for (int j = 0; j < 4; ++j) acc[i][j] = fmaf(a[i], b[j], acc[i][j]);
        }
        __syncthreads();
    }
#pragma unroll
    for (int i = 0; i < 4; ++i) {
        const int rr = bm + ty * 4 + i;
        if (rr >= M) continue;
#pragma unroll
        for (int j = 0; j < 4; ++j) {
            const int cidx = bn + tx * 4 + j;
            if (cidx < N) {
                float v = acc[i][j];
                if (bias) v += bias[cidx];
                C[(size_t)rr * N + cidx] = v;
            }
        }
    }
}

// ---------------------------------------------------------------------------
// Masked argmax -> labels (first index on ties)
// ---------------------------------------------------------------------------
__global__ void argmax_kernel(const float* __restrict__ logits,
                              const float* __restrict__ Y,
                              float* __restrict__ labels_f)
{
    const int row = blockIdx.x * 8 + threadIdx.y;
    const int lane = threadIdx.x;
    if (row >= BB) return;
    float best = -FLT_MAX; int bidx = 0x7fffffff;
    for (int c = lane; c < CC; c += 32) {
        if (Y[(size_t)row * CC + c] != 0.0f) {
            const float v = logits[(size_t)row * CC + c];
            if (v > best || (v == best && c < bidx)) { best = v; bidx = c; }
        }
    }
#pragma unroll
    for (int o = 16; o > 0; o >>= 1) {
        const float ov = __shfl_down_sync(0xffffffffu, best, o);
        const int   oi = __shfl_down_sync(0xffffffffu, bidx, o);
        if (ov > best || (ov == best && oi < bidx)) { best = ov; bidx = oi; }
    }
    if (lane == 0) { g_labels[row] = bidx; labels_f[row] = (float)bidx; }
}

// ---------------------------------------------------------------------------
// One-block prep: class-parallel counting scan. 1024 threads.
// ---------------------------------------------------------------------------
__global__ __launch_bounds__(1024)
void prep_kernel() {
    __shared__ int s_lab[BB];
    __shared__ int s_tot[CC];
    __shared__ int s_start[CC];
    const int tid = threadIdx.x;
    s_lab[tid] = g_labels[tid];
    __syncthreads();

    if (tid < CC) {
        int cnt = 0;
        for (int j = 0; j < BB; ++j) cnt += (s_lab[j] == tid);
        s_tot[tid] = cnt;
    }
    __syncthreads();
    if (tid == 0) {
        int acc = 0;
        for (int c = 0; c < CC; ++c) { s_start[c] = acc; acc += s_tot[c]; }
    }
    __syncthreads();

    if (tid < CC) {
        const int n = s_tot[tid];
        const int st = s_start[tid];
        int k = 0;
        for (int j = 0; j < BB; ++j) {
            if (s_lab[j] == tid) {
                g_idx[st + k] = j;
                g_coefs[st + k] = (1.0f - PROTO_W_F) * __powf(PROTO_W_F, (float)(n - 1 - k));
                ++k;
            }
        }
        g_scale[tid] = __powf(PROTO_W_F, (float)n);
        g_start[tid] = st;
        g_n[tid]     = n;
    }
}

// ---------------------------------------------------------------------------
// Prototype EMA + normalize (one block per class, 512 threads = FF)
// ---------------------------------------------------------------------------
__global__ __launch_bounds__(512)
void proto_kernel(const float* __restrict__ feats,
                  const float* __restrict__ proto,
                  float* __restrict__ new_proto)
{
    const int c = blockIdx.x;
    __shared__ float s_red[512];
    __shared__ float s_norm;
    const int tid = threadIdx.x;
    const int n = g_n[c], st = g_start[c];
    float acc = g_scale[c] * proto[(size_t)c * FF + tid];
    for (int k = 0; k < n; ++k)
        acc = fmaf(g_coefs[st + k], feats[(size_t)g_idx[st + k] * FF + tid], acc);
    s_red[tid] = acc * acc;
    __syncthreads();
#pragma unroll
    for (int s = 256; s > 0; s >>= 1) {
        if (tid < s) s_red[tid] += s_red[tid + s];
        __syncthreads();
    }
    if (tid == 0) s_norm = sqrtf(s_red[0]);
    __syncthreads();
    new_proto[(size_t)c * FF + tid] = acc / s_norm;
}

// ---------------------------------------------------------------------------
extern "C" void kernel_launch(void* const* d_in, const int* in_sizes, int n_in,
                              void* d_out, int out_size)
{
    const float* img_q     = (const float*)d_in[0];
    const float* img_q1    = (const float*)d_in[1];
    const float* partial_Y = (const float*)d_in[2];
    const float* W_enc     = (const float*)d_in[3];
    const float* W_fc      = (const float*)d_in[4];
    const float* b_fc      = (const float*)d_in[5];
    const float* proto     = (const float*)d_in[6];

    float* out = (float*)d_out;
    float* o_logits_q  = out + OFF_LOGITS_Q;
    float* o_logits_q1 = out + OFF_LOGITS_Q1;
    float* o_new_proto = out + OFF_NEW_PROTO;
    float* o_prot      = out + OFF_PROT;
    float* o_labels    = out + OFF_LABELS;
    float* o_feats_q   = out + OFF_FEATS_Q;
    float* o_feats_q1  = out + OFF_FEATS_Q1;

    cudaFuncSetAttribute(gemm_mma, cudaFuncAttributeMaxDynamicSharedMemorySize, GEMM_SMEM);
    cudaFuncSetAttribute(gemm_logits, cudaFuncAttributeMaxDynamicSharedMemorySize, GEMM_SMEM);

    // 0) split inputs into f16 hi/lo planes (W fused with transpose)
    {
        dim3 blk(32, 8);
        splitW<<<dim3(FF / 32, DD / 32), blk>>>(W_enc);
        splitWfc<<<dim3(NPAD / 32, FF / 32), blk>>>(W_fc);
    }
    {
        void* pAh; void* pAl;
        cudaGetSymbolAddress(&pAh, gAh);
        cudaGetSymbolAddress(&pAl, gAl);
        const int nF4 = BB * DD / 4;
        splitA<<<(nF4 + 255) / 256, 256>>>((const float4*)img_q,
                                           (uint2*)pAh, (uint2*)pAl, nF4);
        splitA<<<(nF4 + 255) / 256, 256>>>((const float4*)img_q1,
                                           (uint2*)((__half*)pAh + (size_t)BB * DD),
                                           (uint2*)((__half*)pAl + (size_t)BB * DD), nF4);
    }

    // 1) feats = img @ W_enc via split-fp16 HMMA, split-K=4 -> partials -> reduce
    {
        dim3 grid(FF / 64, BB / 128, 2 * KSPLIT);   // 512 CTAs
        gemm_mma<<<grid, 256, GEMM_SMEM>>>();
        dim3 rgrid(BB * FF / 512, 2);
        reduceK<<<rgrid, 256>>>(o_feats_q, o_feats_q1);
    }
    // 2) logits = feats @ W_fc + b via split-fp16 HMMA
    {
        dim3 grid(NPAD / 64, BB / 128, 2);
        gemm_logits<<<grid, 256, GEMM_SMEM>>>(o_logits_q, o_logits_q1, b_fc);
    }
    // 3) masked argmax -> labels
    {
        dim3 blk(32, 8);
        argmax_kernel<<<BB / 8, blk>>>(o_logits_q, partial_Y, o_labels);
    }
    // 4) prep + prototype EMA + normalize
    prep_kernel<<<1, 1024>>>();
    proto_kernel<<<CC, 512>>>(o_feats_q, proto, o_new_proto);

    // 5) prot_scores = new_proto @ W_fc + b (fp32, small)
    {
        dim3 grid((CC + 63) / 64, (CC + 63) / 64, 1);
        gemm64<<<grid, 256>>>(o_new_proto, W_fc, b_fc, o_prot, CC, CC, FF);
    }
}

// round 14
// speedup vs baseline: 2.9100x; 1.0319x over previous
#include <cuda_runtime.h>
#include <cuda_fp16.h>
#include <cstdint>
#include <float.h>

// Problem constants
#define BB 1024
#define DD 8192
#define CC 345
#define FF 512
#define NPAD 384                      // padded class dim for HMMA logits
#define PROTO_W_F 0.99f

// Output layout (flattened, return-tuple order, float32)
#define OFF_LOGITS_Q   0
#define OFF_LOGITS_Q1  353280
#define OFF_NEW_PROTO  706560
#define OFF_PROT       883200
#define OFF_LABELS     1002225
#define OFF_FEATS_Q    1003249
#define OFF_FEATS_Q1   1527537
// NOTE: OFF_FEATS_Q / OFF_FEATS_Q1 are ODD element offsets -> those output
// pointers are only 4-byte aligned. All accesses to them MUST be scalar.

#define KSPLIT 4
#define KCHUNK (DD / KSPLIT)               // 2048

// ---------------------------------------------------------------------------
// Device scratch (static: allocation-free per harness rules)
// ---------------------------------------------------------------------------
__device__ __half gAh[2][BB * DD];   // f16 hi planes of img_q / img_q1 [row][k]
__device__ __half gAl[2][BB * DD];   // f16 lo planes
__device__ __half gBh[FF * DD];      // f16 hi plane of W_enc^T  [n][k]
__device__ __half gBl[FF * DD];      // f16 lo plane
__device__ float gPart[2 * KSPLIT][BB * FF];  // split-K partials
__device__ __half gFh[2][BB * FF];   // f16 hi planes of feats (for logits HMMA)
__device__ __half gFl[2][BB * FF];   // f16 lo planes
__device__ __half gWfh[NPAD * FF];   // f16 hi plane of W_fc^T [n][k], zero-padded
__device__ __half gWfl[NPAD * FF];   // f16 lo plane

__device__ int   g_labels[BB];
__device__ int   g_idx[BB];
__device__ float g_coefs[BB];
__device__ float g_scale[CC];
__device__ int   g_start[CC];
__device__ int   g_n[CC];

// ---------------------------------------------------------------------------
// PTX helpers (plain sm_103-compatible: cp.async + ldmatrix + mma.sync)
// ---------------------------------------------------------------------------
__device__ __forceinline__ uint32_t smem_to_u32(const void* p) {
    uint32_t a;
    asm("{ .reg .u64 t; cvta.to.shared.u64 t, %1; cvt.u32.u64 %0, t; }" : "=r"(a) : "l"(p));
    return a;
}
#define CP_ASYNC16(dst, src) \
    asm volatile("cp.async.cg.shared.global [%0], [%1], 16;" :: "r"(dst), "l"(src) : "memory")
#define CP_COMMIT()  asm volatile("cp.async.commit_group;" ::: "memory")
#define CP_WAIT1()   asm volatile("cp.async.wait_group 1;" ::: "memory")
#define CP_WAIT0()   asm volatile("cp.async.wait_group 0;" ::: "memory")
#define LDSM_X4(r0, r1, r2, r3, addr) \
    asm volatile("ldmatrix.sync.aligned.m8n8.x4.shared.b16 {%0,%1,%2,%3}, [%4];" \
                 : "=r"(r0), "=r"(r1), "=r"(r2), "=r"(r3) : "r"(addr))
// fp32-accumulate HMMA (main product)
#define MMA16816(d, a, b) \
    asm volatile("mma.sync.aligned.m16n8k16.row.col.f32.f16.f16.f32 " \
                 "{%0,%1,%2,%3}, {%4,%5,%6,%7}, {%8,%9}, {%0,%1,%2,%3};" \
                 : "+f"((d)[0]), "+f"((d)[1]), "+f"((d)[2]), "+f"((d)[3]) \
                 : "r"((a)[0]), "r"((a)[1]), "r"((a)[2]), "r"((a)[3]), \
                   "r"((b)[0]), "r"((b)[1]))
// fp16-accumulate HMMA (both correction products share one accumulator)
#define MMA16816H(d, a, b) \
    asm volatile("mma.sync.aligned.m16n8k16.row.col.f16.f16.f16.f16 " \
                 "{%0,%1}, {%2,%3,%4,%5}, {%6,%7}, {%0,%1};" \
                 : "+r"((d)[0]), "+r"((d)[1]) \
                 : "r"((a)[0]), "r"((a)[1]), "r"((a)[2]), "r"((a)[3]), \
                   "r"((b)[0]), "r"((b)[1]))

// ---------------------------------------------------------------------------
// Fused transpose+split: W_enc [DD x FF] fp32 -> gBh/gBl [FF x DD] f16 planes
// ---------------------------------------------------------------------------
__global__ void splitW(const float* __restrict__ W) {
    __shared__ float t[32][33];
    const int n0 = blockIdx.x * 32, k0 = blockIdx.y * 32;
    const int tx = threadIdx.x, ty = threadIdx.y;
#pragma unroll
    for (int j = 0; j < 4; ++j)
        t[ty + 8 * j][tx] = W[(size_t)(k0 + ty + 8 * j) * FF + n0 + tx];
    __syncthreads();
#pragma unroll
    for (int j = 0; j < 4; ++j) {
        const float v = t[tx][ty + 8 * j];
        const int n = n0 + ty + 8 * j, k = k0 + tx;
        const __half h = __float2half_rn(v);
        gBh[(size_t)n * DD + k] = h;
        gBl[(size_t)n * DD + k] = __float2half_rn(v - __half2float(h));
    }
}

// ---------------------------------------------------------------------------
// Transpose+split W_fc [FF x CC] fp32 -> gWfh/gWfl [NPAD x FF], zero padding
// ---------------------------------------------------------------------------
__global__ void splitWfc(const float* __restrict__ W) {
    __shared__ float t[32][33];
    const int n0 = blockIdx.x * 32, k0 = blockIdx.y * 32;
    const int tx = threadIdx.x, ty = threadIdx.y;
#pragma unroll
    for (int j = 0; j < 4; ++j) {
        const int nn = n0 + tx, kk = k0 + ty + 8 * j;
        t[ty + 8 * j][tx] = (nn < CC) ? W[(size_t)kk * CC + nn] : 0.0f;
    }
    __syncthreads();
#pragma unroll
    for (int j = 0; j < 4; ++j) {
        const float v = t[tx][ty + 8 * j];
        const int n = n0 + ty + 8 * j, k = k0 + tx;
        const __half h = __float2half_rn(v);
        gWfh[(size_t)n * FF + k] = h;
        gWfl[(size_t)n * FF + k] = __float2half_rn(v - __half2float(h));
    }
}

// ---------------------------------------------------------------------------
// fp32 -> (f16 hi, f16 lo) planes, vectorized
// ---------------------------------------------------------------------------
__global__ __launch_bounds__(256)
void splitA(const float4* __restrict__ src, uint2* __restrict__ hi,
            uint2* __restrict__ lo, int nF4) {
    const int i = blockIdx.x * 256 + threadIdx.x;
    if (i >= nF4) return;
    float4 v = src[i];
    __half2 h01 = __floats2half2_rn(v.x, v.y);
    __half2 h23 = __floats2half2_rn(v.z, v.w);
    float2 f01 = __half22float2(h01);
    float2 f23 = __half22float2(h23);
    __half2 l01 = __floats2half2_rn(v.x - f01.x, v.y - f01.y);
    __half2 l23 = __floats2half2_rn(v.z - f23.x, v.w - f23.y);
    uint2 hw, lw;
    hw.x = *reinterpret_cast<uint32_t*>(&h01); hw.y = *reinterpret_cast<uint32_t*>(&h23);
    lw.x = *reinterpret_cast<uint32_t*>(&l01); lw.y = *reinterpret_cast<uint32_t*>(&l23);
    hi[i] = hw; lo[i] = lw;
}

// ---------------------------------------------------------------------------
// Split-FP16 HMMA GEMM, split-K. BM=128, BN=64, BK=32, 256 threads.
// Main product fp32-accum; BOTH corrections into ONE fp16 accumulator.
// gemm_mma: 2-stage pipeline, 61.4 KB smem -> 3 CTAs/SM (24 warps).
// gemm_logits: 3-stage (small kernel).
// ---------------------------------------------------------------------------
#define SA_STRIDE 40
#define STG_A1 0
#define STG_A2 10240
#define STG_B1 20480
#define STG_B2 25600
#define STAGE_BYTES 30720
#define GM_STAGES 2
#define GM_SMEM (GM_STAGES * STAGE_BYTES)   // 61440 -> 3 CTAs/SM
#define GL_STAGES 3
#define GL_SMEM (GL_STAGES * STAGE_BYTES)   // 92160

// Consume one 32-K stage. Uses: acc (fp32[2][4][4]), ac1 (u32[2][4][2]).
#define CONSUME_STAGE(sb)                                                          \
    do {                                                                           \
        _Pragma("unroll")                                                          \
        for (int ks = 0; ks < 2; ++ks) {                                           \
            uint32_t a[2][2][4];   /* [plane][mtile] */                            \
            uint32_t b[2][4][2];   /* [plane][ntile] */                            \
            _Pragma("unroll")                                                      \
            for (int p = 0; p < 2; ++p)                                            \
                _Pragma("unroll")                                                  \
                for (int mt = 0; mt < 2; ++mt) {                                   \
                    const int row = warp_m * 32 + mt * 16 + (lane & 15);           \
                    const int col = ks * 16 + (lane >> 4) * 8;                     \
                    const uint32_t addr = (sb) + (p ? STG_A2 : STG_A1) +           \
                                          (uint32_t)(row * SA_STRIDE + col) * 2;   \
                    LDSM_X4(a[p][mt][0], a[p][mt][1], a[p][mt][2], a[p][mt][3], addr); \
                }                                                                  \
            _Pragma("unroll")                                                      \
            for (int p = 0; p < 2; ++p)                                            \
                _Pragma("unroll")                                                  \
                for (int np = 0; np < 2; ++np) {                                   \
                    const int r = lane & 7, sel = lane >> 3;                       \
                    const int row = warp_n * 32 + np * 16 + (sel >> 1) * 8 + r;    \
                    const int col = ks * 16 + (sel & 1) * 8;                       \
                    const uint32_t addr = (sb) + (p ? STG_B2 : STG_B1) +           \
                                          (uint32_t)(row * SA_STRIDE + col) * 2;   \
                    LDSM_X4(b[p][2 * np][0], b[p][2 * np][1],                      \
                            b[p][2 * np + 1][0], b[p][2 * np + 1][1], addr);       \
                }                                                                  \
            /* main: A1*B1 fp32-accum */                                           \
            _Pragma("unroll")                                                      \
            for (int mt = 0; mt < 2; ++mt)                                         \
                _Pragma("unroll")                                                  \
                for (int nt = 0; nt < 4; ++nt)                                     \
                    MMA16816(acc[mt][nt], a[0][mt], b[0][nt]);                     \
            /* corrections: A1*B2 then A2*B1, both fp16-accum into ac1 */          \
            _Pragma("unroll")                                                      \
            for (int mt = 0; mt < 2; ++mt)                                         \
                _Pragma("unroll")                                                  \
                for (int nt = 0; nt < 4; ++nt)                                     \
                    MMA16816H(ac1[mt][nt], a[0][mt], b[1][nt]);                    \
            _Pragma("unroll")                                                      \
            for (int mt = 0; mt < 2; ++mt)                                         \
                _Pragma("unroll")                                                  \
                for (int nt = 0; nt < 4; ++nt)                                     \
                    MMA16816H(ac1[mt][nt], a[1][mt], b[0][nt]);                    \
        }                                                                          \
    } while (0)

__global__ __launch_bounds__(256, 3)
void gemm_mma() {
    extern __shared__ __align__(16) char smem[];
    const uint32_t sbase = smem_to_u32(smem);
    const int tid = threadIdx.x;
    const int lane = tid & 31, wid = tid >> 5;
    const int warp_m = wid >> 1, warp_n = wid & 1;
    const int zi = blockIdx.z;             // batch*KSPLIT + split
    const int bz = zi >> 2, sp = zi & 3;
    const int bm = blockIdx.y * 128, bn = blockIdx.x * 64;
    const int kbase8 = sp * (KCHUNK / 8);
    float* __restrict__ P = gPart[zi];

    const uint4* __restrict__ Ah = reinterpret_cast<const uint4*>(gAh[bz]);
    const uint4* __restrict__ Al = reinterpret_cast<const uint4*>(gAl[bz]);
    const uint4* __restrict__ Bh = reinterpret_cast<const uint4*>(gBh);
    const uint4* __restrict__ Bl = reinterpret_cast<const uint4*>(gBl);

    float acc[2][4][4] = {};
    uint32_t ac1[2][4][2] = {};

    const int la_row0 = tid >> 2;
    const int la_c4 = tid & 3;

#define LOAD_STAGE(it_)                                                            \
    do {                                                                           \
        const int s_ = (it_) % GM_STAGES;                                          \
        const int kc8_ = kbase8 + (it_) * 4;                                       \
        const uint32_t sb_ = sbase + s_ * STAGE_BYTES;                             \
        _Pragma("unroll")                                                          \
        for (int u = 0; u < 2; ++u) {                                              \
            const int row = la_row0 + u * 64;                                      \
            const uint32_t doff = (uint32_t)(row * SA_STRIDE + la_c4 * 8) * 2;     \
            const size_t gi = (size_t)(bm + row) * (DD / 8) + kc8_ + la_c4;        \
            CP_ASYNC16(sb_ + STG_A1 + doff, Ah + gi);                              \
            CP_ASYNC16(sb_ + STG_A2 + doff, Al + gi);                              \
        }                                                                          \
        {                                                                          \
            const uint32_t doff = (uint32_t)(la_row0 * SA_STRIDE + la_c4 * 8) * 2; \
            const size_t gi = (size_t)(bn + la_row0) * (DD / 8) + kc8_ + la_c4;    \
            CP_ASYNC16(sb_ + STG_B1 + doff, Bh + gi);                              \
            CP_ASYNC16(sb_ + STG_B2 + doff, Bl + gi);                              \
        }                                                                          \
        CP_COMMIT();                                                               \
    } while (0)

    LOAD_STAGE(0);

    const int NKT = KCHUNK / 32;           // 64
#pragma unroll 1
    for (int it = 0; it < NKT; ++it) {
        CP_WAIT0();                        // load(it) complete
        __syncthreads();                   // all warps done consuming it-1
        if (it + 1 < NKT) LOAD_STAGE(it + 1);   // into slot of it-1: safe
        const uint32_t sb = sbase + (it % GM_STAGES) * STAGE_BYTES;
        CONSUME_STAGE(sb);
    }
#undef LOAD_STAGE

    // epilogue: fold fp16 correction acc into fp32, vector stores (aligned buf)
#pragma unroll
    for (int mt = 0; mt < 2; ++mt) {
        const int r0 = bm + warp_m * 32 + mt * 16 + (lane >> 2);
#pragma unroll
        for (int nt = 0; nt < 4; ++nt) {
            const float2 c1lo = __half22float2(*reinterpret_cast<__half2*>(&ac1[mt][nt][0]));
            const float2 c1hi = __half22float2(*reinterpret_cast<__half2*>(&ac1[mt][nt][1]));
            const int gc = bn + warp_n * 32 + nt * 8 + (lane & 3) * 2;
            *reinterpret_cast<float2*>(P + (size_t)r0 * FF + gc) =
                make_float2(acc[mt][nt][0] + c1lo.x, acc[mt][nt][1] + c1lo.y);
            *reinterpret_cast<float2*>(P + (size_t)(r0 + 8) * FF + gc) =
                make_float2(acc[mt][nt][2] + c1hi.x, acc[mt][nt][3] + c1hi.y);
        }
    }
}

// ---------------------------------------------------------------------------
// Split-K reduce: feats = sum of KSPLIT partials; also emit f16 hi/lo planes.
// ---------------------------------------------------------------------------
__global__ __launch_bounds__(256)
void reduceK(float* __restrict__ o0, float* __restrict__ o1) {
    const int i2 = blockIdx.x * 256 + threadIdx.x;
    const int b = blockIdx.y;
    const int i = i2 * 2;
    float* __restrict__ o = b ? o1 : o0;
    float s0 = 0.0f, s1 = 0.0f;
#pragma unroll
    for (int s = 0; s < KSPLIT; ++s) {
        s0 += gPart[KSPLIT * b + s][i];
        s1 += gPart[KSPLIT * b + s][i + 1];
    }
    o[i] = s0; o[i + 1] = s1;
    __half2 h = __floats2half2_rn(s0, s1);
    float2 hf = __half22float2(h);
    __half2 l = __floats2half2_rn(s0 - hf.x, s1 - hf.y);
    *reinterpret_cast<__half2*>(&gFh[b][i]) = h;
    *reinterpret_cast<__half2*>(&gFl[b][i]) = l;
}

// ---------------------------------------------------------------------------
// Split-FP16 HMMA logits GEMM: logits[b] = feats[b] @ W_fc + b_fc
// ---------------------------------------------------------------------------
__global__ __launch_bounds__(256, 2)
void gemm_logits(float* __restrict__ C0, float* __restrict__ C1,
                 const float* __restrict__ bias) {
    extern __shared__ __align__(16) char smem[];
    const uint32_t sbase = smem_to_u32(smem);
    const int tid = threadIdx.x;
    const int lane = tid & 31, wid = tid >> 5;
    const int warp_m = wid >> 1, warp_n = wid & 1;
    const int bz = blockIdx.z;
    const int bm = blockIdx.y * 128, bn = blockIdx.x * 64;
    float* __restrict__ C = bz ? C1 : C0;

    const uint4* __restrict__ Ah = reinterpret_cast<const uint4*>(gFh[bz]);
    const uint4* __restrict__ Al = reinterpret_cast<const uint4*>(gFl[bz]);
    const uint4* __restrict__ Bh = reinterpret_cast<const uint4*>(gWfh);
    const uint4* __restrict__ Bl = reinterpret_cast<const uint4*>(gWfl);

    float acc[2][4][4] = {};
    uint32_t ac1[2][4][2] = {};

    const int la_row0 = tid >> 2;
    const int la_c4 = tid & 3;

#define LOAD_STAGE_L(it_)                                                          \
    do {                                                                           \
        const int s_ = (it_) % GL_STAGES;                                          \
        const int kc8_ = (it_) * 4;                                                \
        const uint32_t sb_ = sbase + s_ * STAGE_BYTES;                             \
        _Pragma("unroll")                                                          \
        for (int u = 0; u < 2; ++u) {                                              \
            const int row = la_row0 + u * 64;                                      \
            const uint32_t doff = (uint32_t)(row * SA_STRIDE + la_c4 * 8) * 2;     \
            const size_t gi = (size_t)(bm + row) * (FF / 8) + kc8_ + la_c4;        \
            CP_ASYNC16(sb_ + STG_A1 + doff, Ah + gi);                              \
            CP_ASYNC16(sb_ + STG_A2 + doff, Al + gi);                              \
        }                                                                          \
        {                                                                          \
            const uint32_t doff = (uint32_t)(la_row0 * SA_STRIDE + la_c4 * 8) * 2; \
            const size_t gi = (size_t)(bn + la_row0) * (FF / 8) + kc8_ + la_c4;    \
            CP_ASYNC16(sb_ + STG_B1 + doff, Bh + gi);                              \
            CP_ASYNC16(sb_ + STG_B2 + doff, Bl + gi);                              \
        }                                                                          \
        CP_COMMIT();                                                               \
    } while (0)

    LOAD_STAGE_L(0);
    LOAD_STAGE_L(1);

    const int NKT = FF / 32;               // 16
#pragma unroll 1
    for (int it = 0; it < NKT; ++it) {
        if (it + 1 < NKT) CP_WAIT1(); else CP_WAIT0();
        __syncthreads();
        if (it + 2 < NKT) LOAD_STAGE_L(it + 2);
        const uint32_t sb = sbase + (it % GL_STAGES) * STAGE_BYTES;
        CONSUME_STAGE(sb);
    }
#undef LOAD_STAGE_L

    // epilogue: fold correction, scalar stores into [1024 x 345], mask n >= CC
#pragma unroll
    for (int mt = 0; mt < 2; ++mt) {
        const int r0 = bm + warp_m * 32 + mt * 16 + (lane >> 2);
#pragma unroll
        for (int nt = 0; nt < 4; ++nt) {
            const float2 c1lo = __half22float2(*reinterpret_cast<__half2*>(&ac1[mt][nt][0]));
            const float2 c1hi = __half22float2(*reinterpret_cast<__half2*>(&ac1[mt][nt][1]));
            const int gc = bn + warp_n * 32 + nt * 8 + (lane & 3) * 2;
            if (gc < CC) {
                C[(size_t)r0 * CC + gc] = acc[mt][nt][0] + c1lo.x + bias[gc];
                C[(size_t)(r0 + 8) * CC + gc] = acc[mt][nt][2] + c1hi.x + bias[gc];
            }
            if (gc + 1 < CC) {
                C[(size_t)r0 * CC + gc + 1] = acc[mt][nt][1] + c1lo.y + bias[gc + 1];
                C[(size_t)(r0 + 8) * CC + gc + 1] = acc[mt][nt][3] + c1hi.y + bias[gc + 1];
            }
        }
    }
}

// ---------------------------------------------------------------------------
// fp32 tiled GEMM (prot_scores only)
// ---------------------------------------------------------------------------
__global__ __launch_bounds__(256)
void gemm64(const float* __restrict__ A0,
            const float* __restrict__ Bmat, const float* __restrict__ bias,
            float* __restrict__ C0, int M, int N, int K)
{
    const float* __restrict__ A = A0;
    float* __restrict__ C = C0;
    __shared__ float As[16][64 + 1];
    __shared__ float Bs[16][64];
    const int tid = threadIdx.x;
    const int tx = tid & 15, ty = tid >> 4;
    const int bm = blockIdx.y * 64, bn = blockIdx.x * 64;
    float acc[4][4] = {};
    for (int k0 = 0; k0 < K; k0 += 16) {
        {
            const int acol = tid & 15, arow0 = tid >> 4;
#pragma unroll
            for (int j = 0; j < 4; ++j) {
                const int arow = arow0 + j * 16, gr = bm + arow;
                As[acol][arow] = (gr < M) ? A[(size_t)gr * K + (k0 + acol)] : 0.0f;
            }
        }
        {
            const int brow = tid >> 4, bcol0 = tid & 15;
#pragma unroll
            for (int j = 0; j < 4; ++j) {
                const int bcol = bcol0 + j * 16, gc = bn + bcol;
                Bs[brow][bcol] = (gc < N) ? Bmat[(size_t)(k0 + brow) * N + gc] : 0.0f;
            }
        }
        __syncthreads();
#pragma unroll
        for (int kk = 0; kk < 16; ++kk) {
            float a[4], b[4];
#pragma unroll
            for (int i = 0; i < 4; ++i) a[i] = As[kk][ty * 4 + i];
#pragma unroll
            for (int j = 0; j < 4; ++j) b[j] = Bs[kk][tx * 4 + j];
#pragma unroll
            for (int i = 0; i < 4; ++i)
#pragma unroll
                for (int j = 0; j < 4; ++j) acc[i][j] = fmaf(a[i], b[j], acc[i][j]);
        }
        __syncthreads();
    }
#pragma unroll
    for (int i = 0; i < 4; ++i) {
        const int rr = bm + ty * 4 + i;
        if (rr >= M) continue;
#pragma unroll
        for (int j = 0; j < 4; ++j) {
            const int cidx = bn + tx * 4 + j;
            if (cidx < N) {
                float v = acc[i][j];
                if (bias) v += bias[cidx];
                C[(size_t)rr * N + cidx] = v;
            }
        }
    }
}

// ---------------------------------------------------------------------------
// Masked argmax -> labels (first index on ties)
// ---------------------------------------------------------------------------
__global__ void argmax_kernel(const float* __restrict__ logits,
                              const float* __restrict__ Y,
                              float* __restrict__ labels_f)
{
    const int row = blockIdx.x * 8 + threadIdx.y;
    const int lane = threadIdx.x;
    if (row >= BB) return;
    float best = -FLT_MAX; int bidx = 0x7fffffff;
    for (int c = lane; c < CC; c += 32) {
        if (Y[(size_t)row * CC + c] != 0.0f) {
            const float v = logits[(size_t)row * CC + c];
            if (v > best || (v == best && c < bidx)) { best = v; bidx = c; }
        }
    }
#pragma unroll
    for (int o = 16; o > 0; o >>= 1) {
        const float ov = __shfl_down_sync(0xffffffffu, best, o);
        const int   oi = __shfl_down_sync(0xffffffffu, bidx, o);
        if (ov > best || (ov == best && oi < bidx)) { best = ov; bidx = oi; }
    }
    if (lane == 0) { g_labels[row] = bidx; labels_f[row] = (float)bidx; }
}

// ---------------------------------------------------------------------------
// One-block prep: class-parallel counting scan. 1024 threads.
// ---------------------------------------------------------------------------
__global__ __launch_bounds__(1024)
void prep_kernel() {
    __shared__ int s_lab[BB];
    __shared__ int s_tot[CC];
    __shared__ int s_start[CC];
    const int tid = threadIdx.x;
    s_lab[tid] = g_labels[tid];
    __syncthreads();

    if (tid < CC) {
        int cnt = 0;
        for (int j = 0; j < BB; ++j) cnt += (s_lab[j] == tid);
        s_tot[tid] = cnt;
    }
    __syncthreads();
    if (tid == 0) {
        int acc = 0;
        for (int c = 0; c < CC; ++c) { s_start[c] = acc; acc += s_tot[c]; }
    }
    __syncthreads();

    if (tid < CC) {
        const int n = s_tot[tid];
        const int st = s_start[tid];
        int k = 0;
        for (int j = 0; j < BB; ++j) {
            if (s_lab[j] == tid) {
                g_idx[st + k] = j;
                g_coefs[st + k] = (1.0f - PROTO_W_F) * __powf(PROTO_W_F, (float)(n - 1 - k));
                ++k;
            }
        }
        g_scale[tid] = __powf(PROTO_W_F, (float)n);
        g_start[tid] = st;
        g_n[tid]     = n;
    }
}

// ---------------------------------------------------------------------------
// Prototype EMA + normalize (one block per class, 512 threads = FF)
// ---------------------------------------------------------------------------
__global__ __launch_bounds__(512)
void proto_kernel(const float* __restrict__ feats,
                  const float* __restrict__ proto,
                  float* __restrict__ new_proto)
{
    const int c = blockIdx.x;
    __shared__ float s_red[512];
    __shared__ float s_norm;
    const int tid = threadIdx.x;
    const int n = g_n[c], st = g_start[c];
    float acc = g_scale[c] * proto[(size_t)c * FF + tid];
    for (int k = 0; k < n; ++k)
        acc = fmaf(g_coefs[st + k], feats[(size_t)g_idx[st + k] * FF + tid], acc);
    s_red[tid] = acc * acc;
    __syncthreads();
#pragma unroll
    for (int s = 256; s > 0; s >>= 1) {
        if (tid < s) s_red[tid] += s_red[tid + s];
        __syncthreads();
    }
    if (tid == 0) s_norm = sqrtf(s_red[0]);
    __syncthreads();
    new_proto[(size_t)c * FF + tid] = acc / s_norm;
}

// ---------------------------------------------------------------------------
extern "C" void kernel_launch(void* const* d_in, const int* in_sizes, int n_in,
                              void* d_out, int out_size)
{
    const float* img_q     = (const float*)d_in[0];
    const float* img_q1    = (const float*)d_in[1];
    const float* partial_Y = (const float*)d_in[2];
    const float* W_enc     = (const float*)d_in[3];
    const float* W_fc      = (const float*)d_in[4];
    const float* b_fc      = (const float*)d_in[5];
    const float* proto     = (const float*)d_in[6];

    float* out = (float*)d_out;
    float* o_logits_q  = out + OFF_LOGITS_Q;
    float* o_logits_q1 = out + OFF_LOGITS_Q1;
    float* o_new_proto = out + OFF_NEW_PROTO;
    float* o_prot      = out + OFF_PROT;
    float* o_labels    = out + OFF_LABELS;
    float* o_feats_q   = out + OFF_FEATS_Q;
    float* o_feats_q1  = out + OFF_FEATS_Q1;

    cudaFuncSetAttribute(gemm_mma, cudaFuncAttributeMaxDynamicSharedMemorySize, GM_SMEM);
    cudaFuncSetAttribute(gemm_logits, cudaFuncAttributeMaxDynamicSharedMemorySize, GL_SMEM);

    // 0) split inputs into f16 hi/lo planes (W fused with transpose)
    {
        dim3 blk(32, 8);
        splitW<<<dim3(FF / 32, DD / 32), blk>>>(W_enc);
        splitWfc<<<dim3(NPAD / 32, FF / 32), blk>>>(W_fc);
    }
    {
        void* pAh; void* pAl;
        cudaGetSymbolAddress(&pAh, gAh);
        cudaGetSymbolAddress(&pAl, gAl);
        const int nF4 = BB * DD / 4;
        splitA<<<(nF4 + 255) / 256, 256>>>((const float4*)img_q,
                                           (uint2*)pAh, (uint2*)pAl, nF4);
        splitA<<<(nF4 + 255) / 256, 256>>>((const float4*)img_q1,
                                           (uint2*)((__half*)pAh + (size_t)BB * DD),
                                           (uint2*)((__half*)pAl + (size_t)BB * DD), nF4);
    }

    // 1) feats = img @ W_enc via split-fp16 HMMA, split-K=4 -> partials -> reduce
    {
        dim3 grid(FF / 64, BB / 128, 2 * KSPLIT);   // 512 CTAs
        gemm_mma<<<grid, 256, GM_SMEM>>>();
        dim3 rgrid(BB * FF / 512, 2);
        reduceK<<<rgrid, 256>>>(o_feats_q, o_feats_q1);
    }
    // 2) logits = feats @ W_fc + b via split-fp16 HMMA
    {
        dim3 grid(NPAD / 64, BB / 128, 2);
        gemm_logits<<<grid, 256, GL_SMEM>>>(o_logits_q, o_logits_q1, b_fc);
    }
    // 3) masked argmax -> labels
    {
        dim3 blk(32, 8);
        argmax_kernel<<<BB / 8, blk>>>(o_logits_q, partial_Y, o_labels);
    }
    // 4) prep + prototype EMA + normalize
    prep_kernel<<<1, 1024>>>();
    proto_kernel<<<CC, 512>>>(o_feats_q, proto, o_new_proto);

    // 5) prot_scores = new_proto @ W_fc + b (fp32, small)
    {
        dim3 grid((CC + 63) / 64, (CC + 63) / 64, 1);
        gemm64<<<grid, 256>>>(o_new_proto, W_fc, b_fc, o_prot, CC, CC, FF);
    }
}

// round 17
// speedup vs baseline: 2.9601x; 1.0172x over previous
#include <cuda_runtime.h>
#include <cuda_fp16.h>
#include <cstdint>
#include <float.h>

// Problem constants
#define BB 1024
#define DD 8192
#define CC 345
#define FF 512
#define NPAD 384                      // padded class dim for HMMA logits
#define PROTO_W_F 0.99f

// Output layout (flattened, return-tuple order, float32)
#define OFF_LOGITS_Q   0
#define OFF_LOGITS_Q1  353280
#define OFF_NEW_PROTO  706560
#define OFF_PROT       883200
#define OFF_LABELS     1002225
#define OFF_FEATS_Q    1003249
#define OFF_FEATS_Q1   1527537
// NOTE: OFF_FEATS_Q / OFF_FEATS_Q1 are ODD element offsets -> those output
// pointers are only 4-byte aligned. All accesses to them MUST be scalar.

#define KSPLIT 4
#define KCHUNK (DD / KSPLIT)               // 2048

// ---------------------------------------------------------------------------
// Device scratch (static: allocation-free per harness rules)
// ---------------------------------------------------------------------------
__device__ __half gAh[2][BB * DD];   // f16 hi planes of img_q / img_q1 [row][k]
__device__ __half gAl[2][BB * DD];   // f16 lo planes
__device__ __half gBh[FF * DD];      // f16 hi plane of W_enc^T  [n][k]
__device__ __half gBl[FF * DD];      // f16 lo plane
__device__ float gPart[2 * KSPLIT][BB * FF];  // split-K partials
__device__ __half gFh[2][BB * FF];   // f16 hi planes of feats (for logits HMMA)
__device__ __half gFl[2][BB * FF];   // f16 lo planes
__device__ __half gWfh[NPAD * FF];   // f16 hi plane of W_fc^T [n][k], zero-padded
__device__ __half gWfl[NPAD * FF];   // f16 lo plane

__device__ int   g_labels[BB];
__device__ int   g_idx[BB];
__device__ float g_coefs[BB];
__device__ float g_scale[CC];
__device__ int   g_start[CC];
__device__ int   g_n[CC];

// ---------------------------------------------------------------------------
// PTX helpers (plain sm_103-compatible: cp.async + ldmatrix + mma.sync)
// ---------------------------------------------------------------------------
__device__ __forceinline__ uint32_t smem_to_u32(const void* p) {
    uint32_t a;
    asm("{ .reg .u64 t; cvta.to.shared.u64 t, %1; cvt.u32.u64 %0, t; }" : "=r"(a) : "l"(p));
    return a;
}
#define CP_ASYNC16(dst, src) \
    asm volatile("cp.async.cg.shared.global [%0], [%1], 16;" :: "r"(dst), "l"(src) : "memory")
#define CP_COMMIT()  asm volatile("cp.async.commit_group;" ::: "memory")
#define CP_WAIT1()   asm volatile("cp.async.wait_group 1;" ::: "memory")
#define CP_WAIT0()   asm volatile("cp.async.wait_group 0;" ::: "memory")
#define LDSM_X4(r0, r1, r2, r3, addr) \
    asm volatile("ldmatrix.sync.aligned.m8n8.x4.shared.b16 {%0,%1,%2,%3}, [%4];" \
                 : "=r"(r0), "=r"(r1), "=r"(r2), "=r"(r3) : "r"(addr))
// fp32-accumulate HMMA (main product)
#define MMA16816(d, a, b) \
    asm volatile("mma.sync.aligned.m16n8k16.row.col.f32.f16.f16.f32 " \
                 "{%0,%1,%2,%3}, {%4,%5,%6,%7}, {%8,%9}, {%0,%1,%2,%3};" \
                 : "+f"((d)[0]), "+f"((d)[1]), "+f"((d)[2]), "+f"((d)[3]) \
                 : "r"((a)[0]), "r"((a)[1]), "r"((a)[2]), "r"((a)[3]), \
                   "r"((b)[0]), "r"((b)[1]))
// fp16-accumulate HMMA (both correction products share one accumulator)
#define MMA16816H(d, a, b) \
    asm volatile("mma.sync.aligned.m16n8k16.row.col.f16.f16.f16.f16 " \
                 "{%0,%1}, {%2,%3,%4,%5}, {%6,%7}, {%0,%1};" \
                 : "+r"((d)[0]), "+r"((d)[1]) \
                 : "r"((a)[0]), "r"((a)[1]), "r"((a)[2]), "r"((a)[3]), \
                   "r"((b)[0]), "r"((b)[1]))

// ---------------------------------------------------------------------------
// Fused front-end: one launch does
//   blocks [0, 8192)          : splitA batch 0 (img_q)
//   blocks [8192, 16384)      : splitA batch 1 (img_q1)
//   blocks [16384, 20480)     : splitW  (W_enc transpose+split, 32x32 tiles)
//   blocks [20480, 20672)     : splitWfc (W_fc transpose+split, padded)
// 256 threads everywhere.
// ---------------------------------------------------------------------------
#define NBLK_A (BB * DD / 4 / 256)         // 8192
#define NBLK_W ((FF / 32) * (DD / 32))     // 4096
#define NBLK_WFC ((NPAD / 32) * (FF / 32)) // 192
#define NBLK_FRONT (2 * NBLK_A + NBLK_W + NBLK_WFC)

__global__ __launch_bounds__(256)
void front_kernel(const float4* __restrict__ imgq,
                  const float4* __restrict__ imgq1,
                  const float* __restrict__ W,
                  const float* __restrict__ Wfc) {
    const int bid = blockIdx.x;
    const int tid = threadIdx.x;

    if (bid < 2 * NBLK_A) {
        // ---- splitA ----
        const int b = bid >= NBLK_A;
        const float4* __restrict__ src = b ? imgq1 : imgq;
        uint2* __restrict__ hi = reinterpret_cast<uint2*>(gAh[b]);
        uint2* __restrict__ lo = reinterpret_cast<uint2*>(gAl[b]);
        const int i = (bid - (b ? NBLK_A : 0)) * 256 + tid;
        float4 v = src[i];
        __half2 h01 = __floats2half2_rn(v.x, v.y);
        __half2 h23 = __floats2half2_rn(v.z, v.w);
        float2 f01 = __half22float2(h01);
        float2 f23 = __half22float2(h23);
        __half2 l01 = __floats2half2_rn(v.x - f01.x, v.y - f01.y);
        __half2 l23 = __floats2half2_rn(v.z - f23.x, v.w - f23.y);
        uint2 hw, lw;
        hw.x = *reinterpret_cast<uint32_t*>(&h01); hw.y = *reinterpret_cast<uint32_t*>(&h23);
        lw.x = *reinterpret_cast<uint32_t*>(&l01); lw.y = *reinterpret_cast<uint32_t*>(&l23);
        hi[i] = hw; lo[i] = lw;
        return;
    }

    __shared__ float t[32][33];
    const int tx = tid & 31, ty = tid >> 5;   // 32 x 8

    if (bid < 2 * NBLK_A + NBLK_W) {
        // ---- splitW: W_enc [DD x FF] -> gBh/gBl [FF x DD] ----
        const int w = bid - 2 * NBLK_A;
        const int n0 = (w % (FF / 32)) * 32, k0 = (w / (FF / 32)) * 32;
#pragma unroll
        for (int j = 0; j < 4; ++j)
            t[ty + 8 * j][tx] = W[(size_t)(k0 + ty + 8 * j) * FF + n0 + tx];
        __syncthreads();
#pragma unroll
        for (int j = 0; j < 4; ++j) {
            const float v = t[tx][ty + 8 * j];
            const int n = n0 + ty + 8 * j, k = k0 + tx;
            const __half h = __float2half_rn(v);
            gBh[(size_t)n * DD + k] = h;
            gBl[(size_t)n * DD + k] = __float2half_rn(v - __half2float(h));
        }
        return;
    }

    // ---- splitWfc: W_fc [FF x CC] -> gWfh/gWfl [NPAD x FF] ----
    {
        const int w = bid - 2 * NBLK_A - NBLK_W;
        const int n0 = (w % (NPAD / 32)) * 32, k0 = (w / (NPAD / 32)) * 32;
#pragma unroll
        for (int j = 0; j < 4; ++j) {
            const int nn = n0 + tx, kk = k0 + ty + 8 * j;
            t[ty + 8 * j][tx] = (nn < CC) ? Wfc[(size_t)kk * CC + nn] : 0.0f;
        }
        __syncthreads();
#pragma unroll
        for (int j = 0; j < 4; ++j) {
            const float v = t[tx][ty + 8 * j];
            const int n = n0 + ty + 8 * j, k = k0 + tx;
            const __half h = __float2half_rn(v);
            gWfh[(size_t)n * FF + k] = h;
            gWfl[(size_t)n * FF + k] = __float2half_rn(v - __half2float(h));
        }
    }
}

// ---------------------------------------------------------------------------
// Split-FP16 HMMA GEMM, split-K. BM=128, BN=64, BK=32, 256 threads.
// Main product fp32-accum; BOTH corrections into ONE fp16 accumulator.
// 2-stage pipeline, 61.4 KB smem -> 3 CTAs/SM.
// ---------------------------------------------------------------------------
#define SA_STRIDE 40
#define STG_A1 0
#define STG_A2 10240
#define STG_B1 20480
#define STG_B2 25600
#define STAGE_BYTES 30720
#define GM_STAGES 2
#define GM_SMEM (GM_STAGES * STAGE_BYTES)   // 61440
#define GL_STAGES 3
#define GL_SMEM (GL_STAGES * STAGE_BYTES)   // 92160

#define CONSUME_STAGE(sb)                                                          \
    do {                                                                           \
        _Pragma("unroll")                                                          \
        for (int ks = 0; ks < 2; ++ks) {                                           \
            uint32_t a[2][2][4];   /* [plane][mtile] */                            \
            uint32_t b[2][4][2];   /* [plane][ntile] */                            \
            _Pragma("unroll")                                                      \
            for (int p = 0; p < 2; ++p)                                            \
                _Pragma("unroll")                                                  \
                for (int mt = 0; mt < 2; ++mt) {                                   \
                    const int row = warp_m * 32 + mt * 16 + (lane & 15);           \
                    const int col = ks * 16 + (lane >> 4) * 8;                     \
                    const uint32_t addr = (sb) + (p ? STG_A2 : STG_A1) +           \
                                          (uint32_t)(row * SA_STRIDE + col) * 2;   \
                    LDSM_X4(a[p][mt][0], a[p][mt][1], a[p][mt][2], a[p][mt][3], addr); \
                }                                                                  \
            _Pragma("unroll")                                                      \
            for (int p = 0; p < 2; ++p)                                            \
                _Pragma("unroll")                                                  \
                for (int np = 0; np < 2; ++np) {                                   \
                    const int r = lane & 7, sel = lane >> 3;                       \
                    const int row = warp_n * 32 + np * 16 + (sel >> 1) * 8 + r;    \
                    const int col = ks * 16 + (sel & 1) * 8;                       \
                    const uint32_t addr = (sb) + (p ? STG_B2 : STG_B1) +           \
                                          (uint32_t)(row * SA_STRIDE + col) * 2;   \
                    LDSM_X4(b[p][2 * np][0], b[p][2 * np][1],                      \
                            b[p][2 * np + 1][0], b[p][2 * np + 1][1], addr);       \
                }                                                                  \
            _Pragma("unroll")                                                      \
            for (int mt = 0; mt < 2; ++mt)                                         \
                _Pragma("unroll")                                                  \
                for (int nt = 0; nt < 4; ++nt)                                     \
                    MMA16816(acc[mt][nt], a[0][mt], b[0][nt]);                     \
            _Pragma("unroll")                                                      \
            for (int mt = 0; mt < 2; ++mt)                                         \
                _Pragma("unroll")                                                  \
                for (int nt = 0; nt < 4; ++nt)                                     \
                    MMA16816H(ac1[mt][nt], a[0][mt], b[1][nt]);                    \
            _Pragma("unroll")                                                      \
            for (int mt = 0; mt < 2; ++mt)                                         \
                _Pragma("unroll")                                                  \
                for (int nt = 0; nt < 4; ++nt)                                     \
                    MMA16816H(ac1[mt][nt], a[1][mt], b[0][nt]);                    \
        }                                                                          \
    } while (0)

__global__ __launch_bounds__(256, 3)
void gemm_mma() {
    extern __shared__ __align__(16) char smem[];
    const uint32_t sbase = smem_to_u32(smem);
    const int tid = threadIdx.x;
    const int lane = tid & 31, wid = tid >> 5;
    const int warp_m = wid >> 1, warp_n = wid & 1;
    const int zi = blockIdx.z;
    const int bz = zi >> 2, sp = zi & 3;
    const int bm = blockIdx.y * 128, bn = blockIdx.x * 64;
    const int kbase8 = sp * (KCHUNK / 8);
    float* __restrict__ P = gPart[zi];

    const uint4* __restrict__ Ah = reinterpret_cast<const uint4*>(gAh[bz]);
    const uint4* __restrict__ Al = reinterpret_cast<const uint4*>(gAl[bz]);
    const uint4* __restrict__ Bh = reinterpret_cast<const uint4*>(gBh);
    const uint4* __restrict__ Bl = reinterpret_cast<const uint4*>(gBl);

    float acc[2][4][4] = {};
    uint32_t ac1[2][4][2] = {};

    const int la_row0 = tid >> 2;
    const int la_c4 = tid & 3;

#define LOAD_STAGE(it_)                                                            \
    do {                                                                           \
        const int s_ = (it_) % GM_STAGES;                                          \
        const int kc8_ = kbase8 + (it_) * 4;                                       \
        const uint32_t sb_ = sbase + s_ * STAGE_BYTES;                             \
        _Pragma("unroll")                                                          \
        for (int u = 0; u < 2; ++u) {                                              \
            const int row = la_row0 + u * 64;                                      \
            const uint32_t doff = (uint32_t)(row * SA_STRIDE + la_c4 * 8) * 2;     \
            const size_t gi = (size_t)(bm + row) * (DD / 8) + kc8_ + la_c4;        \
            CP_ASYNC16(sb_ + STG_A1 + doff, Ah + gi);                              \
            CP_ASYNC16(sb_ + STG_A2 + doff, Al + gi);                              \
        }                                                                          \
        {                                                                          \
            const uint32_t doff = (uint32_t)(la_row0 * SA_STRIDE + la_c4 * 8) * 2; \
            const size_t gi = (size_t)(bn + la_row0) * (DD / 8) + kc8_ + la_c4;    \
            CP_ASYNC16(sb_ + STG_B1 + doff, Bh + gi);                              \
            CP_ASYNC16(sb_ + STG_B2 + doff, Bl + gi);                              \
        }                                                                          \
        CP_COMMIT();                                                               \
    } while (0)

    LOAD_STAGE(0);

    const int NKT = KCHUNK / 32;           // 64
#pragma unroll 1
    for (int it = 0; it < NKT; ++it) {
        CP_WAIT0();
        __syncthreads();
        if (it + 1 < NKT) LOAD_STAGE(it + 1);
        const uint32_t sb = sbase + (it % GM_STAGES) * STAGE_BYTES;
        CONSUME_STAGE(sb);
    }
#undef LOAD_STAGE

#pragma unroll
    for (int mt = 0; mt < 2; ++mt) {
        const int r0 = bm + warp_m * 32 + mt * 16 + (lane >> 2);
#pragma unroll
        for (int nt = 0; nt < 4; ++nt) {
            const float2 c1lo = __half22float2(*reinterpret_cast<__half2*>(&ac1[mt][nt][0]));
            const float2 c1hi = __half22float2(*reinterpret_cast<__half2*>(&ac1[mt][nt][1]));
            const int gc = bn + warp_n * 32 + nt * 8 + (lane & 3) * 2;
            *reinterpret_cast<float2*>(P + (size_t)r0 * FF + gc) =
                make_float2(acc[mt][nt][0] + c1lo.x, acc[mt][nt][1] + c1lo.y);
            *reinterpret_cast<float2*>(P + (size_t)(r0 + 8) * FF + gc) =
                make_float2(acc[mt][nt][2] + c1hi.x, acc[mt][nt][3] + c1hi.y);
        }
    }
}

// ---------------------------------------------------------------------------
// Split-K reduce: feats = sum of KSPLIT partials; also emit f16 hi/lo planes.
// 4 elements per thread.
// ---------------------------------------------------------------------------
__global__ __launch_bounds__(256)
void reduceK(float* __restrict__ o0, float* __restrict__ o1) {
    const int i4 = blockIdx.x * 256 + threadIdx.x;
    const int b = blockIdx.y;
    const int i = i4 * 4;
    float* __restrict__ o = b ? o1 : o0;
    float s[4] = {};
#pragma unroll
    for (int p = 0; p < KSPLIT; ++p) {
        const float4 v = *reinterpret_cast<const float4*>(&gPart[KSPLIT * b + p][i]);
        s[0] += v.x; s[1] += v.y; s[2] += v.z; s[3] += v.w;
    }
    o[i] = s[0]; o[i + 1] = s[1]; o[i + 2] = s[2]; o[i + 3] = s[3];
    __half2 h0 = __floats2half2_rn(s[0], s[1]);
    __half2 h1 = __floats2half2_rn(s[2], s[3]);
    float2 hf0 = __half22float2(h0);
    float2 hf1 = __half22float2(h1);
    __half2 l0 = __floats2half2_rn(s[0] - hf0.x, s[1] - hf0.y);
    __half2 l1 = __floats2half2_rn(s[2] - hf1.x, s[3] - hf1.y);
    uint2 hv, lv;
    hv.x = *reinterpret_cast<uint32_t*>(&h0); hv.y = *reinterpret_cast<uint32_t*>(&h1);
    lv.x = *reinterpret_cast<uint32_t*>(&l0); lv.y = *reinterpret_cast<uint32_t*>(&l1);
    *reinterpret_cast<uint2*>(&gFh[b][i]) = hv;
    *reinterpret_cast<uint2*>(&gFl[b][i]) = lv;
}

// ---------------------------------------------------------------------------
// Split-FP16 HMMA logits GEMM: logits[b] = feats[b] @ W_fc + b_fc
// ---------------------------------------------------------------------------
__global__ __launch_bounds__(256, 2)
void gemm_logits(float* __restrict__ C0, float* __restrict__ C1,
                 const float* __restrict__ bias) {
    extern __shared__ __align__(16) char smem[];
    const uint32_t sbase = smem_to_u32(smem);
    const int tid = threadIdx.x;
    const int lane = tid & 31, wid = tid >> 5;
    const int warp_m = wid >> 1, warp_n = wid & 1;
    const int bz = blockIdx.z;
    const int bm = blockIdx.y * 128, bn = blockIdx.x * 64;
    float* __restrict__ C = bz ? C1 : C0;

    const uint4* __restrict__ Ah = reinterpret_cast<const uint4*>(gFh[bz]);
    const uint4* __restrict__ Al = reinterpret_cast<const uint4*>(gFl[bz]);
    const uint4* __restrict__ Bh = reinterpret_cast<const uint4*>(gWfh);
    const uint4* __restrict__ Bl = reinterpret_cast<const uint4*>(gWfl);

    float acc[2][4][4] = {};
    uint32_t ac1[2][4][2] = {};

    const int la_row0 = tid >> 2;
    const int la_c4 = tid & 3;

#define LOAD_STAGE_L(it_)                                                          \
    do {                                                                           \
        const int s_ = (it_) % GL_STAGES;                                          \
        const int kc8_ = (it_) * 4;                                                \
        const uint32_t sb_ = sbase + s_ * STAGE_BYTES;                             \
        _Pragma("unroll")                                                          \
        for (int u = 0; u < 2; ++u) {                                              \
            const int row = la_row0 + u * 64;                                      \
            const uint32_t doff = (uint32_t)(row * SA_STRIDE + la_c4 * 8) * 2;     \
            const size_t gi = (size_t)(bm + row) * (FF / 8) + kc8_ + la_c4;        \
            CP_ASYNC16(sb_ + STG_A1 + doff, Ah + gi);                              \
            CP_ASYNC16(sb_ + STG_A2 + doff, Al + gi);                              \
        }                                                                          \
        {                                                                          \
            const uint32_t doff = (uint32_t)(la_row0 * SA_STRIDE + la_c4 * 8) * 2; \
            const size_t gi = (size_t)(bn + la_row0) * (FF / 8) + kc8_ + la_c4;    \
            CP_ASYNC16(sb_ + STG_B1 + doff, Bh + gi);                              \
            CP_ASYNC16(sb_ + STG_B2 + doff, Bl + gi);                              \
        }                                                                          \
        CP_COMMIT();                                                               \
    } while (0)

    LOAD_STAGE_L(0);
    LOAD_STAGE_L(1);

    const int NKT = FF / 32;               // 16
#pragma unroll 1
    for (int it = 0; it < NKT; ++it) {
        if (it + 1 < NKT) CP_WAIT1(); else CP_WAIT0();
        __syncthreads();
        if (it + 2 < NKT) LOAD_STAGE_L(it + 2);
        const uint32_t sb = sbase + (it % GL_STAGES) * STAGE_BYTES;
        CONSUME_STAGE(sb);
    }
#undef LOAD_STAGE_L

#pragma unroll
    for (int mt = 0; mt < 2; ++mt) {
        const int r0 = bm + warp_m * 32 + mt * 16 + (lane >> 2);
#pragma unroll
        for (int nt = 0; nt < 4; ++nt) {
            const float2 c1lo = __half22float2(*reinterpret_cast<__half2*>(&ac1[mt][nt][0]));
            const float2 c1hi = __half22float2(*reinterpret_cast<__half2*>(&ac1[mt][nt][1]));
            const int gc = bn + warp_n * 32 + nt * 8 + (lane & 3) * 2;
            if (gc < CC) {
                C[(size_t)r0 * CC + gc] = acc[mt][nt][0] + c1lo.x + bias[gc];
                C[(size_t)(r0 + 8) * CC + gc] = acc[mt][nt][2] + c1hi.x + bias[gc];
            }
            if (gc + 1 < CC) {
                C[(size_t)r0 * CC + gc + 1] = acc[mt][nt][1] + c1lo.y + bias[gc + 1];
                C[(size_t)(r0 + 8) * CC + gc + 1] = acc[mt][nt][3] + c1hi.y + bias[gc + 1];
            }
        }
    }
}

// ---------------------------------------------------------------------------
// fp32 tiled GEMM (prot_scores only)
// ---------------------------------------------------------------------------
__global__ __launch_bounds__(256)
void gemm64(const float* __restrict__ A0,
            const float* __restrict__ Bmat, const float* __restrict__ bias,
            float* __restrict__ C0, int M, int N, int K)
{
    const float* __restrict__ A = A0;
    float* __restrict__ C = C0;
    __shared__ float As[16][64 + 1];
    __shared__ float Bs[16][64];
    const int tid = threadIdx.x;
    const int tx = tid & 15, ty = tid >> 4;
    const int bm = blockIdx.y * 64, bn = blockIdx.x * 64;
    float acc[4][4] = {};
    for (int k0 = 0; k0 < K; k0 += 16) {
        {
            const int acol = tid & 15, arow0 = tid >> 4;
#pragma unroll
            for (int j = 0; j < 4; ++j) {
                const int arow = arow0 + j * 16, gr = bm + arow;
                As[acol][arow] = (gr < M) ? A[(size_t)gr * K + (k0 + acol)] : 0.0f;
            }
        }
        {
            const int brow = tid >> 4, bcol0 = tid & 15;
#pragma unroll
            for (int j = 0; j < 4; ++j) {
                const int bcol = bcol0 + j * 16, gc = bn + bcol;
                Bs[brow][bcol] = (gc < N) ? Bmat[(size_t)(k0 + brow) * N + gc] : 0.0f;
            }
        }
        __syncthreads();
#pragma unroll
        for (int kk = 0; kk < 16; ++kk) {
            float a[4], b[4];
#pragma unroll
            for (int i = 0; i < 4; ++i) a[i] = As[kk][ty * 4 + i];
#pragma unroll
            for (int j = 0; j < 4; ++j) b[j] = Bs[kk][tx * 4 + j];
#pragma unroll
            for (int i = 0; i < 4; ++i)
#pragma unroll
                for (int j = 0; j < 4; ++j) acc[i][j] = fmaf(a[i], b[j], acc[i][j]);
        }
        __syncthreads();
    }
#pragma unroll
    for (int i = 0; i < 4; ++i) {
        const int rr = bm + ty * 4 + i;
        if (rr >= M) continue;
#pragma unroll
        for (int j = 0; j < 4; ++j) {
            const int cidx = bn + tx * 4 + j;
            if (cidx < N) {
                float v = acc[i][j];
                if (bias) v += bias[cidx];
                C[(size_t)rr * N + cidx] = v;
            }
        }
    }
}

// ---------------------------------------------------------------------------
// Masked argmax -> labels (first index on ties)
// ---------------------------------------------------------------------------
__global__ void argmax_kernel(const float* __restrict__ logits,
                              const float* __restrict__ Y,
                              float* __restrict__ labels_f)
{
    const int row = blockIdx.x * 8 + threadIdx.y;
    const int lane = threadIdx.x;
    if (row >= BB) return;
    float best = -FLT_MAX; int bidx = 0x7fffffff;
    for (int c = lane; c < CC; c += 32) {
        if (Y[(size_t)row * CC + c] != 0.0f) {
            const float v = logits[(size_t)row * CC + c];
            if (v > best || (v == best && c < bidx)) { best = v; bidx = c; }
        }
    }
#pragma unroll
    for (int o = 16; o > 0; o >>= 1) {
        const float ov = __shfl_down_sync(0xffffffffu, best, o);
        const int   oi = __shfl_down_sync(0xffffffffu, bidx, o);
        if (ov > best || (ov == best && oi < bidx)) { best = ov; bidx = oi; }
    }
    if (lane == 0) { g_labels[row] = bidx; labels_f[row] = (float)bidx; }
}

// ---------------------------------------------------------------------------
// One-block prep: class-parallel counting scan. 1024 threads.
// ---------------------------------------------------------------------------
__global__ __launch_bounds__(1024)
void prep_kernel() {
    __shared__ int s_lab[BB];
    __shared__ int s_tot[CC];
    __shared__ int s_start[CC];
    const int tid = threadIdx.x;
    s_lab[tid] = g_labels[tid];
    __syncthreads();

    if (tid < CC) {
        int cnt = 0;
        for (int j = 0; j < BB; ++j) cnt += (s_lab[j] == tid);
        s_tot[tid] = cnt;
    }
    __syncthreads();
    if (tid == 0) {
        int acc = 0;
        for (int c = 0; c < CC; ++c) { s_start[c] = acc; acc += s_tot[c]; }
    }
    __syncthreads();

    if (tid < CC) {
        const int n = s_tot[tid];
        const int st = s_start[tid];
        int k = 0;
        for (int j = 0; j < BB; ++j) {
            if (s_lab[j] == tid) {
                g_idx[st + k] = j;
                g_coefs[st + k] = (1.0f - PROTO_W_F) * __powf(PROTO_W_F, (float)(n - 1 - k));
                ++k;
            }
        }
        g_scale[tid] = __powf(PROTO_W_F, (float)n);
        g_start[tid] = st;
        g_n[tid]     = n;
    }
}

// ---------------------------------------------------------------------------
// Prototype EMA + normalize (one block per class, 512 threads = FF)
// ---------------------------------------------------------------------------
__global__ __launch_bounds__(512)
void proto_kernel(const float* __restrict__ feats,
                  const float* __restrict__ proto,
                  float* __restrict__ new_proto)
{
    const int c = blockIdx.x;
    __shared__ float s_red[512];
    __shared__ float s_norm;
    const int tid = threadIdx.x;
    const int n = g_n[c], st = g_start[c];
    float acc = g_scale[c] * proto[(size_t)c * FF + tid];
    for (int k = 0; k < n; ++k)
        acc = fmaf(g_coefs[st + k], feats[(size_t)g_idx[st + k] * FF + tid], acc);
    s_red[tid] = acc * acc;
    __syncthreads();
#pragma unroll
    for (int s = 256; s > 0; s >>= 1) {
        if (tid < s) s_red[tid] += s_red[tid + s];
        __syncthreads();
    }
    if (tid == 0) s_norm = sqrtf(s_red[0]);
    __syncthreads();
    new_proto[(size_t)c * FF + tid] = acc / s_norm;
}

// ---------------------------------------------------------------------------
extern "C" void kernel_launch(void* const* d_in, const int* in_sizes, int n_in,
                              void* d_out, int out_size)
{
    const float* img_q     = (const float*)d_in[0];
    const float* img_q1    = (const float*)d_in[1];
    const float* partial_Y = (const float*)d_in[2];
    const float* W_enc     = (const float*)d_in[3];
    const float* W_fc      = (const float*)d_in[4];
    const float* b_fc      = (const float*)d_in[5];
    const float* proto     = (const float*)d_in[6];

    float* out = (float*)d_out;
    float* o_logits_q  = out + OFF_LOGITS_Q;
    float* o_logits_q1 = out + OFF_LOGITS_Q1;
    float* o_new_proto = out + OFF_NEW_PROTO;
    float* o_prot      = out + OFF_PROT;
    float* o_labels    = out + OFF_LABELS;
    float* o_feats_q   = out + OFF_FEATS_Q;
    float* o_feats_q1  = out + OFF_FEATS_Q1;

    cudaFuncSetAttribute(gemm_mma, cudaFuncAttributeMaxDynamicSharedMemorySize, GM_SMEM);
    cudaFuncSetAttribute(gemm_logits, cudaFuncAttributeMaxDynamicSharedMemorySize, GL_SMEM);

    // 0) fused front-end: all splits in one launch
    front_kernel<<<NBLK_FRONT, 256>>>((const float4*)img_q, (const float4*)img_q1,
                                      W_enc, W_fc);

    // 1) feats = img @ W_enc via split-fp16 HMMA, split-K=4 -> partials -> reduce
    {
        dim3 grid(FF / 64, BB / 128, 2 * KSPLIT);   // 512 CTAs
        gemm_mma<<<grid, 256, GM_SMEM>>>();
        dim3 rgrid(BB * FF / 1024, 2);
        reduceK<<<rgrid, 256>>>(o_feats_q, o_feats_q1);
    }
    // 2) logits = feats @ W_fc + b via split-fp16 HMMA
    {
        dim3 grid(NPAD / 64, BB / 128, 2);
        gemm_logits<<<grid, 256, GL_SMEM>>>(o_logits_q, o_logits_q1, b_fc);
    }
    // 3) masked argmax -> labels
    {
        dim3 blk(32, 8);
        argmax_kernel<<<BB / 8, blk>>>(o_logits_q, partial_Y, o_labels);
    }
    // 4) prep + prototype EMA + normalize
    prep_kernel<<<1, 1024>>>();
    proto_kernel<<<CC, 512>>>(o_feats_q, proto, o_new_proto);

    // 5) prot_scores = new_proto @ W_fc + b (fp32, small)
    {
        dim3 grid((CC + 63) / 64, (CC + 63) / 64, 1);
        gemm64<<<grid, 256>>>(o_new_proto, W_fc, b_fc, o_prot, CC, CC, FF);
    }
}